// round 1
// baseline (speedup 1.0000x reference)
#include <cuda_runtime.h>
#include <cuda_bf16.h>
#include <cstdint>

#define BS   4
#define NQ   1024
#define D    256
#define NH   8
#define NP   4
#define LNUM 6
#define DFF  1024
#define H_BEV 200
#define W_BEV 150
#define NV   (H_BEV * W_BEV)
#define DH   32
#define MROWS (BS * NQ)          // 4096

// ------------------------- scratch (static device globals) -------------------------
__device__ float g_xbuf[MROWS * D];
__device__ float g_q[MROWS * D];
__device__ float g_k[MROWS * D];
__device__ float g_v[MROWS * D];
__device__ float g_sa[MROWS * D];
__device__ float g_tmp[MROWS * D];
__device__ float g_t1[MROWS * D];
__device__ float g_t2[MROWS * D];
__device__ float g_val[(size_t)BS * NV * D];     // 30.72M floats
__device__ float g_off[MROWS * NH * NP * 2];
__device__ float g_aw[MROWS * NH * NP];
__device__ float g_ca[MROWS * D];
__device__ float g_ffn[MROWS * DFF];

// ------------------------- elementwise add -------------------------
__global__ void add_kernel(const float* __restrict__ a, const float* __restrict__ b,
                           float* __restrict__ o, int n) {
    int i = blockIdx.x * blockDim.x + threadIdx.x;
    if (i < n) o[i] = a[i] + b[i];
}

// ------------------------- GEMM: C[M,N] = A[M,K] @ W[N,K]^T + bias -------------------------
// 64x64 tile, BK=16, 256 threads, 4x4 microtile
template <bool RELU>
__global__ void gemm_bias_kernel(const float* __restrict__ A, const float* __restrict__ W,
                                 const float* __restrict__ bias, float* __restrict__ C,
                                 int M, int N, int K) {
    __shared__ float As[16][65];
    __shared__ float Bs[16][65];
    const int tid = threadIdx.x;
    const int tx = tid & 15, ty = tid >> 4;
    const int m0 = blockIdx.y * 64, n0 = blockIdx.x * 64;
    const int lr = tid >> 2;            // 0..63
    const int lc = (tid & 3) * 4;       // 0,4,8,12

    float acc[4][4];
#pragma unroll
    for (int i = 0; i < 4; i++)
#pragma unroll
        for (int j = 0; j < 4; j++) acc[i][j] = 0.f;

    for (int k0 = 0; k0 < K; k0 += 16) {
        {
            int gm = m0 + lr;
            float4 v = make_float4(0.f, 0.f, 0.f, 0.f);
            if (gm < M) v = *reinterpret_cast<const float4*>(&A[(size_t)gm * K + k0 + lc]);
            As[lc + 0][lr] = v.x; As[lc + 1][lr] = v.y; As[lc + 2][lr] = v.z; As[lc + 3][lr] = v.w;
            int gn = n0 + lr;
            float4 w4 = make_float4(0.f, 0.f, 0.f, 0.f);
            if (gn < N) w4 = *reinterpret_cast<const float4*>(&W[(size_t)gn * K + k0 + lc]);
            Bs[lc + 0][lr] = w4.x; Bs[lc + 1][lr] = w4.y; Bs[lc + 2][lr] = w4.z; Bs[lc + 3][lr] = w4.w;
        }
        __syncthreads();
#pragma unroll
        for (int kk = 0; kk < 16; kk++) {
            float a[4], b[4];
#pragma unroll
            for (int i = 0; i < 4; i++) a[i] = As[kk][ty * 4 + i];
#pragma unroll
            for (int j = 0; j < 4; j++) b[j] = Bs[kk][tx * 4 + j];
#pragma unroll
            for (int i = 0; i < 4; i++)
#pragma unroll
                for (int j = 0; j < 4; j++) acc[i][j] += a[i] * b[j];
        }
        __syncthreads();
    }
#pragma unroll
    for (int i = 0; i < 4; i++) {
        int gm = m0 + ty * 4 + i;
        if (gm >= M) continue;
#pragma unroll
        for (int j = 0; j < 4; j++) {
            int gn = n0 + tx * 4 + j;
            if (gn >= N) continue;
            float v = acc[i][j] + bias[gn];
            if (RELU) v = fmaxf(v, 0.f);
            C[(size_t)gm * N + gn] = v;
        }
    }
}

// ------------------------- flash attention (DH=32, 64-row Q tiles) -------------------------
__global__ void attn_kernel(const float* __restrict__ Q, const float* __restrict__ K,
                            const float* __restrict__ V, float* __restrict__ O) {
    // grid: (NQ/64, NH, BS), block 256
    const int q0 = blockIdx.x * 64;
    const int h  = blockIdx.y;
    const int b  = blockIdx.z;
    const int tid = threadIdx.x;
    __shared__ float Qs[64][33];
    __shared__ float Ks[64][33];
    __shared__ float Vs[64][33];
    __shared__ float Ps[64][65];

    const int row  = tid >> 2;   // 0..63
    const int quad = tid & 3;    // 0..3

    for (int i = tid; i < 64 * 8; i += 256) {
        int r = i >> 3, c = (i & 7) * 4;
        float4 v = *reinterpret_cast<const float4*>(&Q[((size_t)(b * NQ + q0 + r) * D) + h * DH + c]);
        Qs[r][c] = v.x; Qs[r][c + 1] = v.y; Qs[r][c + 2] = v.z; Qs[r][c + 3] = v.w;
    }
    __syncthreads();

    float qreg[32];
#pragma unroll
    for (int k = 0; k < 32; k++) qreg[k] = Qs[row][k] * 0.17677669529663687f;  // 1/sqrt(32)

    float m_run = -1e30f, lsum = 0.f;
    float acc[8];
#pragma unroll
    for (int i = 0; i < 8; i++) acc[i] = 0.f;

    for (int t0 = 0; t0 < NQ; t0 += 64) {
        __syncthreads();
        for (int i = tid; i < 64 * 8; i += 256) {
            int r = i >> 3, c = (i & 7) * 4;
            float4 kv = *reinterpret_cast<const float4*>(&K[((size_t)(b * NQ + t0 + r) * D) + h * DH + c]);
            Ks[r][c] = kv.x; Ks[r][c + 1] = kv.y; Ks[r][c + 2] = kv.z; Ks[r][c + 3] = kv.w;
            float4 vv = *reinterpret_cast<const float4*>(&V[((size_t)(b * NQ + t0 + r) * D) + h * DH + c]);
            Vs[r][c] = vv.x; Vs[r][c + 1] = vv.y; Vs[r][c + 2] = vv.z; Vs[r][c + 3] = vv.w;
        }
        __syncthreads();

        float s[16];
        float mt = -1e30f;
#pragma unroll
        for (int jj = 0; jj < 16; jj++) {
            int j = quad * 16 + jj;
            float sa = 0.f;
#pragma unroll
            for (int k = 0; k < 32; k++) sa += qreg[k] * Ks[j][k];
            s[jj] = sa;
            mt = fmaxf(mt, sa);
        }
        mt = fmaxf(mt, __shfl_xor_sync(0xffffffffu, mt, 1));
        mt = fmaxf(mt, __shfl_xor_sync(0xffffffffu, mt, 2));
        float m_new = fmaxf(m_run, mt);
        float scale = __expf(m_run - m_new);
        float psum = 0.f;
#pragma unroll
        for (int jj = 0; jj < 16; jj++) {
            float p = __expf(s[jj] - m_new);
            Ps[row][quad * 16 + jj] = p;
            psum += p;
        }
        psum += __shfl_xor_sync(0xffffffffu, psum, 1);
        psum += __shfl_xor_sync(0xffffffffu, psum, 2);
        lsum = lsum * scale + psum;
        m_run = m_new;
#pragma unroll
        for (int i = 0; i < 8; i++) acc[i] *= scale;
        __syncthreads();
#pragma unroll 4
        for (int j = 0; j < 64; j++) {
            float p = Ps[row][j];
#pragma unroll
            for (int i = 0; i < 8; i++) acc[i] += p * Vs[j][quad * 8 + i];
        }
    }
    float inv = 1.f / lsum;
#pragma unroll
    for (int i = 0; i < 8; i++)
        O[((size_t)(b * NQ + q0 + row) * D) + h * DH + quad * 8 + i] = acc[i] * inv;
}

// ------------------------- residual + LayerNorm -------------------------
__global__ void add_ln_kernel(const float* __restrict__ x, const float* __restrict__ r,
                              const float* __restrict__ w, const float* __restrict__ b,
                              float* __restrict__ out) {
    const int row = blockIdx.x;
    const int t = threadIdx.x;  // 256
    float v = x[(size_t)row * D + t] + r[(size_t)row * D + t];

    __shared__ float red[8];
    __shared__ float sh_mean, sh_rstd;
    float s = v;
#pragma unroll
    for (int o = 16; o; o >>= 1) s += __shfl_xor_sync(0xffffffffu, s, o);
    if ((t & 31) == 0) red[t >> 5] = s;
    __syncthreads();
    if (t < 32) {
        float z = (t < 8) ? red[t] : 0.f;
#pragma unroll
        for (int o = 4; o; o >>= 1) z += __shfl_xor_sync(0xffffffffu, z, o);
        if (t == 0) sh_mean = z * (1.f / D);
    }
    __syncthreads();
    float m = sh_mean;
    float d = v - m;
    float sq = d * d;
#pragma unroll
    for (int o = 16; o; o >>= 1) sq += __shfl_xor_sync(0xffffffffu, sq, o);
    __syncthreads();   // red reuse
    if ((t & 31) == 0) red[t >> 5] = sq;
    __syncthreads();
    if (t < 32) {
        float z = (t < 8) ? red[t] : 0.f;
#pragma unroll
        for (int o = 4; o; o >>= 1) z += __shfl_xor_sync(0xffffffffu, z, o);
        if (t == 0) sh_rstd = rsqrtf(z * (1.f / D) + 1e-5f);
    }
    __syncthreads();
    out[(size_t)row * D + t] = d * sh_rstd * w[t] + b[t];
}

// ------------------------- MSDA sampling (warp per (b,q,h), lane = dh) -------------------------
__global__ void msda_kernel(const float* __restrict__ val, const float* __restrict__ off,
                            const float* __restrict__ aw, const float* __restrict__ ref,
                            const int* __restrict__ lsi, float* __restrict__ out) {
    const int warp = (blockIdx.x * blockDim.x + threadIdx.x) >> 5;
    const int lane = threadIdx.x & 31;
    if (warp >= BS * NQ * NH) return;
    const int h  = warp % NH;
    const int bq = warp / NH;       // b*NQ + q
    const int b  = bq / NQ;
    const int base = lsi[0];

    const float rx = ref[bq * 2 + 0] * (float)W_BEV - 0.5f;
    const float ry = ref[bq * 2 + 1] * (float)H_BEV - 0.5f;

    // attention-weight softmax over NP=4
    float a0 = aw[bq * (NH * NP) + h * NP + 0];
    float a1 = aw[bq * (NH * NP) + h * NP + 1];
    float a2 = aw[bq * (NH * NP) + h * NP + 2];
    float a3 = aw[bq * (NH * NP) + h * NP + 3];
    float mx = fmaxf(fmaxf(a0, a1), fmaxf(a2, a3));
    float e0 = __expf(a0 - mx), e1 = __expf(a1 - mx), e2 = __expf(a2 - mx), e3 = __expf(a3 - mx);
    float inv = 1.f / (e0 + e1 + e2 + e3);
    float ap[4] = {e0 * inv, e1 * inv, e2 * inv, e3 * inv};

    float accv = 0.f;
#pragma unroll
    for (int p = 0; p < NP; p++) {
        float ox = off[bq * (NH * NP * 2) + (h * NP + p) * 2 + 0];
        float oy = off[bq * (NH * NP * 2) + (h * NP + p) * 2 + 1];
        float x = rx + ox, y = ry + oy;
        float x0f = floorf(x), y0f = floorf(y);
        int x0 = (int)x0f, y0 = (int)y0f;
        float fx = x - x0f, fy = y - y0f;
        float wgt[4] = {(1.f - fx) * (1.f - fy), fx * (1.f - fy), (1.f - fx) * fy, fx * fy};
        int xs[4] = {x0, x0 + 1, x0, x0 + 1};
        int ys[4] = {y0, y0, y0 + 1, y0 + 1};
#pragma unroll
        for (int c = 0; c < 4; c++) {
            int xi = xs[c], yi = ys[c];
            if (xi >= 0 && xi < W_BEV && yi >= 0 && yi < H_BEV) {
                float vv = val[((size_t)(b * NV + base + yi * W_BEV + xi)) * D + h * DH + lane];
                accv += ap[p] * wgt[c] * vv;
            }
        }
    }
    out[(size_t)bq * D + h * DH + lane] = accv;
}

// ------------------------- refs tail -------------------------
__global__ void copy_refs_kernel(const float* __restrict__ ref, float* __restrict__ out) {
    int i = blockIdx.x * blockDim.x + threadIdx.x;
    const int n1 = BS * NQ * 2;
    if (i < LNUM * n1) out[i] = ref[i % n1];
}

// ------------------------- launch -------------------------
extern "C" void kernel_launch(void* const* d_in, const int* in_sizes, int n_in,
                              void* d_out, int out_size) {
    const float* query    = (const float*)d_in[0];
    const float* qpos     = (const float*)d_in[1];
    const float* ref      = (const float*)d_in[2];
    const float* src      = (const float*)d_in[3];
    // d_in[4] spatial_shapes (unused; fixed 200x150)
    const int*   lsi      = (const int*)d_in[5];
    const float* sa_in_w  = (const float*)d_in[6];
    const float* sa_in_b  = (const float*)d_in[7];
    const float* sa_out_w = (const float*)d_in[8];
    const float* sa_out_b = (const float*)d_in[9];
    const float* ca_off_w = (const float*)d_in[10];
    const float* ca_off_b = (const float*)d_in[11];
    const float* ca_aw_w  = (const float*)d_in[12];
    const float* ca_aw_b  = (const float*)d_in[13];
    const float* ca_val_w = (const float*)d_in[14];
    const float* ca_val_b = (const float*)d_in[15];
    const float* ca_out_w = (const float*)d_in[16];
    const float* ca_out_b = (const float*)d_in[17];
    const float* n1_w     = (const float*)d_in[18];
    const float* n1_b     = (const float*)d_in[19];
    const float* n2_w     = (const float*)d_in[20];
    const float* n2_b     = (const float*)d_in[21];
    const float* n3_w     = (const float*)d_in[22];
    const float* n3_b     = (const float*)d_in[23];
    const float* ff1_w    = (const float*)d_in[24];
    const float* ff1_b    = (const float*)d_in[25];
    const float* ff2_w    = (const float*)d_in[26];
    const float* ff2_b    = (const float*)d_in[27];

    float *xbuf, *qb, *kb, *vb, *sab, *tmpb, *t1b, *t2b, *valb, *offb, *awb, *cab, *ffnb;
    cudaGetSymbolAddress((void**)&xbuf, g_xbuf);
    cudaGetSymbolAddress((void**)&qb,   g_q);
    cudaGetSymbolAddress((void**)&kb,   g_k);
    cudaGetSymbolAddress((void**)&vb,   g_v);
    cudaGetSymbolAddress((void**)&sab,  g_sa);
    cudaGetSymbolAddress((void**)&tmpb, g_tmp);
    cudaGetSymbolAddress((void**)&t1b,  g_t1);
    cudaGetSymbolAddress((void**)&t2b,  g_t2);
    cudaGetSymbolAddress((void**)&valb, g_val);
    cudaGetSymbolAddress((void**)&offb, g_off);
    cudaGetSymbolAddress((void**)&awb,  g_aw);
    cudaGetSymbolAddress((void**)&cab,  g_ca);
    cudaGetSymbolAddress((void**)&ffnb, g_ffn);

    float* out_hs = (float*)d_out;
    const int NTOK = MROWS * D;  // 1,048,576

    for (int l = 0; l < LNUM; l++) {
        const float* prev = (l == 0) ? query : out_hs + (size_t)(l - 1) * NTOK;
        float* cur = out_hs + (size_t)l * NTOK;

        // --- self attention ---
        add_kernel<<<(NTOK + 255) / 256, 256>>>(prev, qpos, xbuf, NTOK);
        gemm_bias_kernel<false><<<dim3(4, 64), 256>>>(xbuf, sa_in_w + (size_t)l * 3 * D * D,
                                                      sa_in_b + (size_t)l * 3 * D, qb, MROWS, D, D);
        gemm_bias_kernel<false><<<dim3(4, 64), 256>>>(xbuf, sa_in_w + (size_t)l * 3 * D * D + (size_t)D * D,
                                                      sa_in_b + (size_t)l * 3 * D + D, kb, MROWS, D, D);
        gemm_bias_kernel<false><<<dim3(4, 64), 256>>>(prev, sa_in_w + (size_t)l * 3 * D * D + (size_t)2 * D * D,
                                                      sa_in_b + (size_t)l * 3 * D + 2 * D, vb, MROWS, D, D);
        attn_kernel<<<dim3(NQ / 64, NH, BS), 256>>>(qb, kb, vb, sab);
        gemm_bias_kernel<false><<<dim3(4, 64), 256>>>(sab, sa_out_w + (size_t)l * D * D,
                                                      sa_out_b + (size_t)l * D, tmpb, MROWS, D, D);
        add_ln_kernel<<<MROWS, 256>>>(tmpb, prev, n2_w + (size_t)l * D, n2_b + (size_t)l * D, t1b);

        // --- deformable cross attention ---
        add_kernel<<<(NTOK + 255) / 256, 256>>>(t1b, qpos, xbuf, NTOK);
        gemm_bias_kernel<false><<<dim3(4, (BS * NV + 63) / 64), 256>>>(src, ca_val_w + (size_t)l * D * D,
                                                                       ca_val_b + (size_t)l * D, valb,
                                                                       BS * NV, D, D);
        gemm_bias_kernel<false><<<dim3(1, 64), 256>>>(xbuf, ca_off_w + (size_t)l * NH * NP * 2 * D,
                                                      ca_off_b + (size_t)l * NH * NP * 2, offb,
                                                      MROWS, NH * NP * 2, D);
        gemm_bias_kernel<false><<<dim3(1, 64), 256>>>(xbuf, ca_aw_w + (size_t)l * NH * NP * D,
                                                      ca_aw_b + (size_t)l * NH * NP, awb,
                                                      MROWS, NH * NP, D);
        msda_kernel<<<(BS * NQ * NH + 7) / 8, 256>>>(valb, offb, awb, ref, lsi, cab);
        gemm_bias_kernel<false><<<dim3(4, 64), 256>>>(cab, ca_out_w + (size_t)l * D * D,
                                                      ca_out_b + (size_t)l * D, tmpb, MROWS, D, D);
        add_ln_kernel<<<MROWS, 256>>>(tmpb, t1b, n1_w + (size_t)l * D, n1_b + (size_t)l * D, t2b);

        // --- FFN ---
        gemm_bias_kernel<true><<<dim3(DFF / 64, 64), 256>>>(t2b, ff1_w + (size_t)l * DFF * D,
                                                            ff1_b + (size_t)l * DFF, ffnb, MROWS, DFF, D);
        gemm_bias_kernel<false><<<dim3(4, 64), 256>>>(ffnb, ff2_w + (size_t)l * D * DFF,
                                                      ff2_b + (size_t)l * D, tmpb, MROWS, D, DFF);
        add_ln_kernel<<<MROWS, 256>>>(tmpb, t2b, n3_w + (size_t)l * D, n3_b + (size_t)l * D, cur);
    }

    const int hs_total = LNUM * MROWS * D;
    if (out_size > hs_total) {
        copy_refs_kernel<<<(LNUM * BS * NQ * 2 + 255) / 256, 256>>>(ref, out_hs + hs_total);
    }
}

// round 2
// speedup vs baseline: 1.1873x; 1.1873x over previous
#include <cuda_runtime.h>
#include <cuda_bf16.h>
#include <cstdint>

#define BS   4
#define NQ   1024
#define D    256
#define NH   8
#define NP   4
#define LNUM 6
#define DFF  1024
#define H_BEV 200
#define W_BEV 150
#define NV   (H_BEV * W_BEV)
#define DH   32
#define MROWS (BS * NQ)          // 4096

// ------------------------- scratch (static device globals) -------------------------
__device__ float g_xbuf[MROWS * D];
__device__ float g_q[MROWS * D];
__device__ float g_k[MROWS * D];
__device__ float g_v[MROWS * D];
__device__ float g_sa[MROWS * D];
__device__ float g_tmp[MROWS * D];
__device__ float g_t1[MROWS * D];
__device__ float g_t2[MROWS * D];
__device__ float g_val[(size_t)BS * NV * D];
__device__ float g_off[MROWS * NH * NP * 2];
__device__ float g_aw[MROWS * NH * NP];
__device__ float g_ca[MROWS * D];
__device__ float g_ffn[MROWS * DFF];

// ------------------------- elementwise add -------------------------
__global__ void add_kernel(const float* __restrict__ a, const float* __restrict__ b,
                           float* __restrict__ o, int n) {
    int i = blockIdx.x * blockDim.x + threadIdx.x;
    if (i < n) o[i] = a[i] + b[i];
}

// ------------------------- big GEMM: C[M,N] = A[M,K] @ W[N,K]^T + bias -------------------------
// BN=128, BK=16, 256 threads, double-buffered smem, (BM/16)x8 microtile.
template <int BM, bool RELU>
__global__ __launch_bounds__(256)
void gemm_big_kernel(const float* __restrict__ A, const float* __restrict__ W,
                     const float* __restrict__ bias, float* __restrict__ C,
                     int M, int N, int K) {
    constexpr int BN = 128, BK = 16;
    constexpr int TM = BM / 16;          // 8 or 4
    constexpr int LDA = BM + 4;
    constexpr int LDB = BN + 4;
    constexpr int APASS = BM / 64;       // 2 or 1
    constexpr int BPASS = 2;

    __shared__ float As[2][BK * LDA];
    __shared__ float Bs[2][BK * LDB];

    const int tid = threadIdx.x;
    const int tx = tid & 15;             // 0..15 (col group, 8 cols each)
    const int ty = tid >> 4;             // 0..15 (row group, TM rows each)
    const int m0 = blockIdx.y * BM;
    const int n0 = blockIdx.x * BN;

    const int lkc = (tid & 3) * 4;       // k offset within BK: 0,4,8,12
    const int lr  = tid >> 2;            // 0..63

    float4 aref[APASS], bref[BPASS];

    auto ldg_tile = [&](int k0) {
#pragma unroll
        for (int p = 0; p < APASS; p++) {
            int gm = m0 + lr + p * 64;
            float4 v = make_float4(0.f, 0.f, 0.f, 0.f);
            if (gm < M) v = *reinterpret_cast<const float4*>(&A[(size_t)gm * K + k0 + lkc]);
            aref[p] = v;
        }
#pragma unroll
        for (int p = 0; p < BPASS; p++) {
            int gn = n0 + lr + p * 64;
            float4 v = make_float4(0.f, 0.f, 0.f, 0.f);
            if (gn < N) v = *reinterpret_cast<const float4*>(&W[(size_t)gn * K + k0 + lkc]);
            bref[p] = v;
        }
    };
    auto sts_tile = [&](int buf) {
#pragma unroll
        for (int p = 0; p < APASS; p++) {
            int row = lr + p * 64;
            As[buf][(lkc + 0) * LDA + row] = aref[p].x;
            As[buf][(lkc + 1) * LDA + row] = aref[p].y;
            As[buf][(lkc + 2) * LDA + row] = aref[p].z;
            As[buf][(lkc + 3) * LDA + row] = aref[p].w;
        }
#pragma unroll
        for (int p = 0; p < BPASS; p++) {
            int col = lr + p * 64;
            Bs[buf][(lkc + 0) * LDB + col] = bref[p].x;
            Bs[buf][(lkc + 1) * LDB + col] = bref[p].y;
            Bs[buf][(lkc + 2) * LDB + col] = bref[p].z;
            Bs[buf][(lkc + 3) * LDB + col] = bref[p].w;
        }
    };

    float acc[TM][8];
#pragma unroll
    for (int i = 0; i < TM; i++)
#pragma unroll
        for (int j = 0; j < 8; j++) acc[i][j] = 0.f;

    ldg_tile(0);
    sts_tile(0);
    __syncthreads();

    const int NT = K / BK;
    for (int t = 0; t < NT; t++) {
        const int cur = t & 1;
        if (t + 1 < NT) ldg_tile((t + 1) * BK);
#pragma unroll
        for (int kk = 0; kk < BK; kk++) {
            float a[TM], b[8];
            const float4* ap = reinterpret_cast<const float4*>(&As[cur][kk * LDA + ty * TM]);
#pragma unroll
            for (int q = 0; q < TM / 4; q++) {
                float4 t4 = ap[q];
                a[4 * q + 0] = t4.x; a[4 * q + 1] = t4.y; a[4 * q + 2] = t4.z; a[4 * q + 3] = t4.w;
            }
            const float4* bp = reinterpret_cast<const float4*>(&Bs[cur][kk * LDB + tx * 8]);
            float4 b0 = bp[0], b1 = bp[1];
            b[0] = b0.x; b[1] = b0.y; b[2] = b0.z; b[3] = b0.w;
            b[4] = b1.x; b[5] = b1.y; b[6] = b1.z; b[7] = b1.w;
#pragma unroll
            for (int i = 0; i < TM; i++)
#pragma unroll
                for (int j = 0; j < 8; j++) acc[i][j] += a[i] * b[j];
        }
        if (t + 1 < NT) {
            sts_tile(cur ^ 1);
            __syncthreads();
        }
    }

    float bv[8];
#pragma unroll
    for (int j = 0; j < 8; j++) bv[j] = bias[n0 + tx * 8 + j];

#pragma unroll
    for (int i = 0; i < TM; i++) {
        int gm = m0 + ty * TM + i;
        if (gm >= M) continue;
        float4 o0, o1;
        float r0 = acc[i][0] + bv[0], r1 = acc[i][1] + bv[1], r2 = acc[i][2] + bv[2], r3 = acc[i][3] + bv[3];
        float r4 = acc[i][4] + bv[4], r5 = acc[i][5] + bv[5], r6 = acc[i][6] + bv[6], r7 = acc[i][7] + bv[7];
        if (RELU) {
            r0 = fmaxf(r0, 0.f); r1 = fmaxf(r1, 0.f); r2 = fmaxf(r2, 0.f); r3 = fmaxf(r3, 0.f);
            r4 = fmaxf(r4, 0.f); r5 = fmaxf(r5, 0.f); r6 = fmaxf(r6, 0.f); r7 = fmaxf(r7, 0.f);
        }
        o0 = make_float4(r0, r1, r2, r3);
        o1 = make_float4(r4, r5, r6, r7);
        float* cp = &C[(size_t)gm * N + n0 + tx * 8];
        *reinterpret_cast<float4*>(cp) = o0;
        *reinterpret_cast<float4*>(cp + 4) = o1;
    }
}

// ------------------------- small-N GEMM (64x64 tile) for offsets / attn weights -------------------------
template <bool RELU>
__global__ void gemm_bias_kernel(const float* __restrict__ A, const float* __restrict__ W,
                                 const float* __restrict__ bias, float* __restrict__ C,
                                 int M, int N, int K) {
    __shared__ float As[16][65];
    __shared__ float Bs[16][65];
    const int tid = threadIdx.x;
    const int tx = tid & 15, ty = tid >> 4;
    const int m0 = blockIdx.y * 64, n0 = blockIdx.x * 64;
    const int lr = tid >> 2;
    const int lc = (tid & 3) * 4;

    float acc[4][4];
#pragma unroll
    for (int i = 0; i < 4; i++)
#pragma unroll
        for (int j = 0; j < 4; j++) acc[i][j] = 0.f;

    for (int k0 = 0; k0 < K; k0 += 16) {
        {
            int gm = m0 + lr;
            float4 v = make_float4(0.f, 0.f, 0.f, 0.f);
            if (gm < M) v = *reinterpret_cast<const float4*>(&A[(size_t)gm * K + k0 + lc]);
            As[lc + 0][lr] = v.x; As[lc + 1][lr] = v.y; As[lc + 2][lr] = v.z; As[lc + 3][lr] = v.w;
            int gn = n0 + lr;
            float4 w4 = make_float4(0.f, 0.f, 0.f, 0.f);
            if (gn < N) w4 = *reinterpret_cast<const float4*>(&W[(size_t)gn * K + k0 + lc]);
            Bs[lc + 0][lr] = w4.x; Bs[lc + 1][lr] = w4.y; Bs[lc + 2][lr] = w4.z; Bs[lc + 3][lr] = w4.w;
        }
        __syncthreads();
#pragma unroll
        for (int kk = 0; kk < 16; kk++) {
            float a[4], b[4];
#pragma unroll
            for (int i = 0; i < 4; i++) a[i] = As[kk][ty * 4 + i];
#pragma unroll
            for (int j = 0; j < 4; j++) b[j] = Bs[kk][tx * 4 + j];
#pragma unroll
            for (int i = 0; i < 4; i++)
#pragma unroll
                for (int j = 0; j < 4; j++) acc[i][j] += a[i] * b[j];
        }
        __syncthreads();
    }
#pragma unroll
    for (int i = 0; i < 4; i++) {
        int gm = m0 + ty * 4 + i;
        if (gm >= M) continue;
#pragma unroll
        for (int j = 0; j < 4; j++) {
            int gn = n0 + tx * 4 + j;
            if (gn >= N) continue;
            float v = acc[i][j] + bias[gn];
            if (RELU) v = fmaxf(v, 0.f);
            C[(size_t)gm * N + gn] = v;
        }
    }
}

// ------------------------- flash attention (DH=32, 64-row Q tiles, vectorized) -------------------------
__global__ void attn_kernel(const float* __restrict__ Q, const float* __restrict__ K,
                            const float* __restrict__ V, float* __restrict__ O) {
    // grid: (NQ/64, NH, BS), block 256
    const int q0 = blockIdx.x * 64;
    const int h  = blockIdx.y;
    const int b  = blockIdx.z;
    const int tid = threadIdx.x;
    __shared__ float Qs[64][36];
    __shared__ float Ks[64][36];
    __shared__ float Vs[64][36];
    __shared__ float Ps[64][65];

    const int row  = tid >> 2;   // 0..63
    const int quad = tid & 3;    // 0..3

    for (int i = tid; i < 64 * 8; i += 256) {
        int r = i >> 3, c = (i & 7) * 4;
        float4 v = *reinterpret_cast<const float4*>(&Q[((size_t)(b * NQ + q0 + r) * D) + h * DH + c]);
        *reinterpret_cast<float4*>(&Qs[r][c]) = v;
    }
    __syncthreads();

    float qreg[32];
#pragma unroll
    for (int k = 0; k < 32; k++) qreg[k] = Qs[row][k] * 0.17677669529663687f;  // 1/sqrt(32)

    float m_run = -1e30f, lsum = 0.f;
    float acc[8];
#pragma unroll
    for (int i = 0; i < 8; i++) acc[i] = 0.f;

    for (int t0 = 0; t0 < NQ; t0 += 64) {
        __syncthreads();
        for (int i = tid; i < 64 * 8; i += 256) {
            int r = i >> 3, c = (i & 7) * 4;
            float4 kv = *reinterpret_cast<const float4*>(&K[((size_t)(b * NQ + t0 + r) * D) + h * DH + c]);
            *reinterpret_cast<float4*>(&Ks[r][c]) = kv;
            float4 vv = *reinterpret_cast<const float4*>(&V[((size_t)(b * NQ + t0 + r) * D) + h * DH + c]);
            *reinterpret_cast<float4*>(&Vs[r][c]) = vv;
        }
        __syncthreads();

        float s[16];
        float mt = -1e30f;
#pragma unroll
        for (int jj = 0; jj < 16; jj++) {
            int j = jj * 4 + quad;   // quads read consecutive rows -> conflict-free float4 LDS
            const float4* kp = reinterpret_cast<const float4*>(&Ks[j][0]);
            float sa = 0.f;
#pragma unroll
            for (int kq = 0; kq < 8; kq++) {
                float4 kv = kp[kq];
                sa += qreg[4 * kq + 0] * kv.x + qreg[4 * kq + 1] * kv.y
                    + qreg[4 * kq + 2] * kv.z + qreg[4 * kq + 3] * kv.w;
            }
            s[jj] = sa;
            mt = fmaxf(mt, sa);
        }
        mt = fmaxf(mt, __shfl_xor_sync(0xffffffffu, mt, 1));
        mt = fmaxf(mt, __shfl_xor_sync(0xffffffffu, mt, 2));
        float m_new = fmaxf(m_run, mt);
        float scale = __expf(m_run - m_new);
        float psum = 0.f;
#pragma unroll
        for (int jj = 0; jj < 16; jj++) {
            float p = __expf(s[jj] - m_new);
            Ps[row][jj * 4 + quad] = p;
            psum += p;
        }
        psum += __shfl_xor_sync(0xffffffffu, psum, 1);
        psum += __shfl_xor_sync(0xffffffffu, psum, 2);
        lsum = lsum * scale + psum;
        m_run = m_new;
#pragma unroll
        for (int i = 0; i < 8; i++) acc[i] *= scale;
        __syncthreads();
#pragma unroll 8
        for (int j = 0; j < 64; j++) {
            float p = Ps[row][j];
            const float4* vp = reinterpret_cast<const float4*>(&Vs[j][quad * 8]);
            float4 v0 = vp[0], v1 = vp[1];
            acc[0] += p * v0.x; acc[1] += p * v0.y; acc[2] += p * v0.z; acc[3] += p * v0.w;
            acc[4] += p * v1.x; acc[5] += p * v1.y; acc[6] += p * v1.z; acc[7] += p * v1.w;
        }
    }
    float inv = 1.f / lsum;
#pragma unroll
    for (int i = 0; i < 8; i++)
        O[((size_t)(b * NQ + q0 + row) * D) + h * DH + quad * 8 + i] = acc[i] * inv;
}

// ------------------------- residual + LayerNorm -------------------------
__global__ void add_ln_kernel(const float* __restrict__ x, const float* __restrict__ r,
                              const float* __restrict__ w, const float* __restrict__ b,
                              float* __restrict__ out) {
    const int row = blockIdx.x;
    const int t = threadIdx.x;  // 256
    float v = x[(size_t)row * D + t] + r[(size_t)row * D + t];

    __shared__ float red[8];
    __shared__ float sh_mean, sh_rstd;
    float s = v;
#pragma unroll
    for (int o = 16; o; o >>= 1) s += __shfl_xor_sync(0xffffffffu, s, o);
    if ((t & 31) == 0) red[t >> 5] = s;
    __syncthreads();
    if (t < 32) {
        float z = (t < 8) ? red[t] : 0.f;
#pragma unroll
        for (int o = 4; o; o >>= 1) z += __shfl_xor_sync(0xffffffffu, z, o);
        if (t == 0) sh_mean = z * (1.f / D);
    }
    __syncthreads();
    float m = sh_mean;
    float d = v - m;
    float sq = d * d;
#pragma unroll
    for (int o = 16; o; o >>= 1) sq += __shfl_xor_sync(0xffffffffu, sq, o);
    __syncthreads();
    if ((t & 31) == 0) red[t >> 5] = sq;
    __syncthreads();
    if (t < 32) {
        float z = (t < 8) ? red[t] : 0.f;
#pragma unroll
        for (int o = 4; o; o >>= 1) z += __shfl_xor_sync(0xffffffffu, z, o);
        if (t == 0) sh_rstd = rsqrtf(z * (1.f / D) + 1e-5f);
    }
    __syncthreads();
    out[(size_t)row * D + t] = d * sh_rstd * w[t] + b[t];
}

// ------------------------- MSDA sampling (warp per (b,q,h), lane = dh) -------------------------
__global__ void msda_kernel(const float* __restrict__ val, const float* __restrict__ off,
                            const float* __restrict__ aw, const float* __restrict__ ref,
                            const int* __restrict__ lsi, float* __restrict__ out) {
    const int warp = (blockIdx.x * blockDim.x + threadIdx.x) >> 5;
    const int lane = threadIdx.x & 31;
    if (warp >= BS * NQ * NH) return;
    const int h  = warp % NH;
    const int bq = warp / NH;
    const int b  = bq / NQ;
    const int base = lsi[0];

    const float rx = ref[bq * 2 + 0] * (float)W_BEV - 0.5f;
    const float ry = ref[bq * 2 + 1] * (float)H_BEV - 0.5f;

    float a0 = aw[bq * (NH * NP) + h * NP + 0];
    float a1 = aw[bq * (NH * NP) + h * NP + 1];
    float a2 = aw[bq * (NH * NP) + h * NP + 2];
    float a3 = aw[bq * (NH * NP) + h * NP + 3];
    float mx = fmaxf(fmaxf(a0, a1), fmaxf(a2, a3));
    float e0 = __expf(a0 - mx), e1 = __expf(a1 - mx), e2 = __expf(a2 - mx), e3 = __expf(a3 - mx);
    float inv = 1.f / (e0 + e1 + e2 + e3);
    float ap[4] = {e0 * inv, e1 * inv, e2 * inv, e3 * inv};

    float accv = 0.f;
#pragma unroll
    for (int p = 0; p < NP; p++) {
        float ox = off[bq * (NH * NP * 2) + (h * NP + p) * 2 + 0];
        float oy = off[bq * (NH * NP * 2) + (h * NP + p) * 2 + 1];
        float x = rx + ox, y = ry + oy;
        float x0f = floorf(x), y0f = floorf(y);
        int x0 = (int)x0f, y0 = (int)y0f;
        float fx = x - x0f, fy = y - y0f;
        float wgt[4] = {(1.f - fx) * (1.f - fy), fx * (1.f - fy), (1.f - fx) * fy, fx * fy};
        int xs[4] = {x0, x0 + 1, x0, x0 + 1};
        int ys[4] = {y0, y0, y0 + 1, y0 + 1};
#pragma unroll
        for (int c = 0; c < 4; c++) {
            int xi = xs[c], yi = ys[c];
            if (xi >= 0 && xi < W_BEV && yi >= 0 && yi < H_BEV) {
                float vv = val[((size_t)(b * NV + base + yi * W_BEV + xi)) * D + h * DH + lane];
                accv += ap[p] * wgt[c] * vv;
            }
        }
    }
    out[(size_t)bq * D + h * DH + lane] = accv;
}

// ------------------------- refs tail -------------------------
__global__ void copy_refs_kernel(const float* __restrict__ ref, float* __restrict__ out) {
    int i = blockIdx.x * blockDim.x + threadIdx.x;
    const int n1 = BS * NQ * 2;
    if (i < LNUM * n1) out[i] = ref[i % n1];
}

// ------------------------- launch -------------------------
extern "C" void kernel_launch(void* const* d_in, const int* in_sizes, int n_in,
                              void* d_out, int out_size) {
    const float* query    = (const float*)d_in[0];
    const float* qpos     = (const float*)d_in[1];
    const float* ref      = (const float*)d_in[2];
    const float* src      = (const float*)d_in[3];
    const int*   lsi      = (const int*)d_in[5];
    const float* sa_in_w  = (const float*)d_in[6];
    const float* sa_in_b  = (const float*)d_in[7];
    const float* sa_out_w = (const float*)d_in[8];
    const float* sa_out_b = (const float*)d_in[9];
    const float* ca_off_w = (const float*)d_in[10];
    const float* ca_off_b = (const float*)d_in[11];
    const float* ca_aw_w  = (const float*)d_in[12];
    const float* ca_aw_b  = (const float*)d_in[13];
    const float* ca_val_w = (const float*)d_in[14];
    const float* ca_val_b = (const float*)d_in[15];
    const float* ca_out_w = (const float*)d_in[16];
    const float* ca_out_b = (const float*)d_in[17];
    const float* n1_w     = (const float*)d_in[18];
    const float* n1_b     = (const float*)d_in[19];
    const float* n2_w     = (const float*)d_in[20];
    const float* n2_b     = (const float*)d_in[21];
    const float* n3_w     = (const float*)d_in[22];
    const float* n3_b     = (const float*)d_in[23];
    const float* ff1_w    = (const float*)d_in[24];
    const float* ff1_b    = (const float*)d_in[25];
    const float* ff2_w    = (const float*)d_in[26];
    const float* ff2_b    = (const float*)d_in[27];

    float *xbuf, *qb, *kb, *vb, *sab, *tmpb, *t1b, *t2b, *valb, *offb, *awb, *cab, *ffnb;
    cudaGetSymbolAddress((void**)&xbuf, g_xbuf);
    cudaGetSymbolAddress((void**)&qb,   g_q);
    cudaGetSymbolAddress((void**)&kb,   g_k);
    cudaGetSymbolAddress((void**)&vb,   g_v);
    cudaGetSymbolAddress((void**)&sab,  g_sa);
    cudaGetSymbolAddress((void**)&tmpb, g_tmp);
    cudaGetSymbolAddress((void**)&t1b,  g_t1);
    cudaGetSymbolAddress((void**)&t2b,  g_t2);
    cudaGetSymbolAddress((void**)&valb, g_val);
    cudaGetSymbolAddress((void**)&offb, g_off);
    cudaGetSymbolAddress((void**)&awb,  g_aw);
    cudaGetSymbolAddress((void**)&cab,  g_ca);
    cudaGetSymbolAddress((void**)&ffnb, g_ffn);

    float* out_hs = (float*)d_out;
    const int NTOK = MROWS * D;

    for (int l = 0; l < LNUM; l++) {
        const float* prev = (l == 0) ? query : out_hs + (size_t)(l - 1) * NTOK;
        float* cur = out_hs + (size_t)l * NTOK;

        // --- self attention ---
        add_kernel<<<(NTOK + 255) / 256, 256>>>(prev, qpos, xbuf, NTOK);
        gemm_big_kernel<64, false><<<dim3(D / 128, MROWS / 64), 256>>>(
            xbuf, sa_in_w + (size_t)l * 3 * D * D, sa_in_b + (size_t)l * 3 * D, qb, MROWS, D, D);
        gemm_big_kernel<64, false><<<dim3(D / 128, MROWS / 64), 256>>>(
            xbuf, sa_in_w + (size_t)l * 3 * D * D + (size_t)D * D,
            sa_in_b + (size_t)l * 3 * D + D, kb, MROWS, D, D);
        gemm_big_kernel<64, false><<<dim3(D / 128, MROWS / 64), 256>>>(
            prev, sa_in_w + (size_t)l * 3 * D * D + (size_t)2 * D * D,
            sa_in_b + (size_t)l * 3 * D + 2 * D, vb, MROWS, D, D);
        attn_kernel<<<dim3(NQ / 64, NH, BS), 256>>>(qb, kb, vb, sab);
        gemm_big_kernel<64, false><<<dim3(D / 128, MROWS / 64), 256>>>(
            sab, sa_out_w + (size_t)l * D * D, sa_out_b + (size_t)l * D, tmpb, MROWS, D, D);
        add_ln_kernel<<<MROWS, 256>>>(tmpb, prev, n2_w + (size_t)l * D, n2_b + (size_t)l * D, t1b);

        // --- deformable cross attention ---
        add_kernel<<<(NTOK + 255) / 256, 256>>>(t1b, qpos, xbuf, NTOK);
        gemm_big_kernel<128, false><<<dim3(D / 128, (BS * NV + 127) / 128), 256>>>(
            src, ca_val_w + (size_t)l * D * D, ca_val_b + (size_t)l * D, valb, BS * NV, D, D);
        gemm_bias_kernel<false><<<dim3(1, 64), 256>>>(
            xbuf, ca_off_w + (size_t)l * NH * NP * 2 * D, ca_off_b + (size_t)l * NH * NP * 2,
            offb, MROWS, NH * NP * 2, D);
        gemm_bias_kernel<false><<<dim3(1, 64), 256>>>(
            xbuf, ca_aw_w + (size_t)l * NH * NP * D, ca_aw_b + (size_t)l * NH * NP,
            awb, MROWS, NH * NP, D);
        msda_kernel<<<(BS * NQ * NH + 7) / 8, 256>>>(valb, offb, awb, ref, lsi, cab);
        gemm_big_kernel<64, false><<<dim3(D / 128, MROWS / 64), 256>>>(
            cab, ca_out_w + (size_t)l * D * D, ca_out_b + (size_t)l * D, tmpb, MROWS, D, D);
        add_ln_kernel<<<MROWS, 256>>>(tmpb, t1b, n1_w + (size_t)l * D, n1_b + (size_t)l * D, t2b);

        // --- FFN ---
        gemm_big_kernel<128, true><<<dim3(DFF / 128, MROWS / 128), 256>>>(
            t2b, ff1_w + (size_t)l * DFF * D, ff1_b + (size_t)l * DFF, ffnb, MROWS, DFF, D);
        gemm_big_kernel<64, false><<<dim3(D / 128, MROWS / 64), 256>>>(
            ffnb, ff2_w + (size_t)l * D * DFF, ff2_b + (size_t)l * D, tmpb, MROWS, D, DFF);
        add_ln_kernel<<<MROWS, 256>>>(tmpb, t2b, n3_w + (size_t)l * D, n3_b + (size_t)l * D, cur);
    }

    const int hs_total = LNUM * MROWS * D;
    if (out_size > hs_total) {
        copy_refs_kernel<<<(LNUM * BS * NQ * 2 + 255) / 256, 256>>>(ref, out_hs + hs_total);
    }
}

// round 3
// speedup vs baseline: 1.9237x; 1.6202x over previous
#include <cuda_runtime.h>
#include <cuda_bf16.h>
#include <cstdint>

#define BS   4
#define NQ   1024
#define D    256
#define NH   8
#define NP   4
#define LNUM 6
#define DFF  1024
#define H_BEV 200
#define W_BEV 150
#define NV   (H_BEV * W_BEV)
#define DH   32
#define MROWS (BS * NQ)          // 4096

// ------------------------- scratch (static device globals) -------------------------
__device__ float g_xbuf[MROWS * D];
__device__ float g_qk[MROWS * 512];
__device__ float g_v[MROWS * D];
__device__ float g_sa[MROWS * D];
__device__ float g_tmp[MROWS * D];
__device__ float g_t1[MROWS * D];
__device__ float g_t2[MROWS * D];
__device__ float g_val[(size_t)BS * NV * D];
__device__ float g_off[MROWS * NH * NP * 2];
__device__ float g_aw[MROWS * NH * NP];
__device__ float g_ca[MROWS * D];
__device__ float g_ffn[MROWS * DFF];

// ------------------------- helpers -------------------------
__device__ __forceinline__ uint32_t f2tf(float f) {
    uint32_t r;
    asm("cvt.rna.tf32.f32 %0, %1;" : "=r"(r) : "f"(f));
    return r;
}
__device__ __forceinline__ void mma_tf32(float* c, const uint32_t* a, const uint32_t* b) {
    asm volatile("mma.sync.aligned.m16n8k8.row.col.f32.tf32.tf32.f32 "
                 "{%0,%1,%2,%3},{%4,%5,%6,%7},{%8,%9},{%0,%1,%2,%3};"
                 : "+f"(c[0]), "+f"(c[1]), "+f"(c[2]), "+f"(c[3])
                 : "r"(a[0]), "r"(a[1]), "r"(a[2]), "r"(a[3]), "r"(b[0]), "r"(b[1]));
}

// ------------------------- elementwise add -------------------------
__global__ void add_kernel(const float* __restrict__ a, const float* __restrict__ b,
                           float* __restrict__ o, int n) {
    int i = blockIdx.x * blockDim.x + threadIdx.x;
    if (i < n) o[i] = a[i] + b[i];
}

// ------------------------- tf32 tensor-core GEMM -------------------------
// C[M,N] = A[M,K] @ W[N,K]^T + bias.  CTA tile 128x128, BK=16, 8 warps (32x64 each).
template <bool RELU>
__global__ __launch_bounds__(256)
void gemm_tc(const float* __restrict__ A, const float* __restrict__ W,
             const float* __restrict__ bias, float* __restrict__ C,
             int M, int N, int K) {
    constexpr int LDK = 20;
    __shared__ uint32_t As[2][128 * LDK];
    __shared__ uint32_t Bs[2][128 * LDK];

    const int tid  = threadIdx.x;
    const int lane = tid & 31;
    const int wid  = tid >> 5;
    const int wm   = wid & 3;          // warp m index (0..3) -> 32 rows each
    const int wn   = wid >> 2;         // warp n index (0..1) -> 64 cols each
    const int g    = lane >> 2;        // 0..7
    const int t    = lane & 3;         // 0..3
    const int m0   = blockIdx.y * 128;
    const int n0   = blockIdx.x * 128;

    const int arow = tid >> 1;             // 0..127
    const int acg  = (tid & 1) * 8;        // 0 or 8

    float4 sa0, sa1, sb0, sb1;

    auto ldg = [&](int k0) {
        int gm = m0 + arow;
        if (gm < M) {
            const float* ap = &A[(size_t)gm * K + k0 + acg];
            sa0 = *reinterpret_cast<const float4*>(ap);
            sa1 = *reinterpret_cast<const float4*>(ap + 4);
        } else {
            sa0 = make_float4(0.f, 0.f, 0.f, 0.f);
            sa1 = sa0;
        }
        const float* bp = &W[(size_t)(n0 + arow) * K + k0 + acg];
        sb0 = *reinterpret_cast<const float4*>(bp);
        sb1 = *reinterpret_cast<const float4*>(bp + 4);
    };
    auto sts = [&](int buf) {
        uint4 u0 = make_uint4(f2tf(sa0.x), f2tf(sa0.y), f2tf(sa0.z), f2tf(sa0.w));
        uint4 u1 = make_uint4(f2tf(sa1.x), f2tf(sa1.y), f2tf(sa1.z), f2tf(sa1.w));
        *reinterpret_cast<uint4*>(&As[buf][arow * LDK + acg])     = u0;
        *reinterpret_cast<uint4*>(&As[buf][arow * LDK + acg + 4]) = u1;
        uint4 v0 = make_uint4(f2tf(sb0.x), f2tf(sb0.y), f2tf(sb0.z), f2tf(sb0.w));
        uint4 v1 = make_uint4(f2tf(sb1.x), f2tf(sb1.y), f2tf(sb1.z), f2tf(sb1.w));
        *reinterpret_cast<uint4*>(&Bs[buf][arow * LDK + acg])     = v0;
        *reinterpret_cast<uint4*>(&Bs[buf][arow * LDK + acg + 4]) = v1;
    };

    float acc[2][8][4];
#pragma unroll
    for (int i = 0; i < 2; i++)
#pragma unroll
        for (int j = 0; j < 8; j++)
#pragma unroll
            for (int c = 0; c < 4; c++) acc[i][j][c] = 0.f;

    ldg(0);
    sts(0);
    __syncthreads();

    const int KT = K / 16;
    for (int kt = 0; kt < KT; kt++) {
        const int cur = kt & 1;
        if (kt + 1 < KT) ldg((kt + 1) * 16);
#pragma unroll
        for (int ks = 0; ks < 2; ks++) {
            uint32_t af[2][4];
#pragma unroll
            for (int mt = 0; mt < 2; mt++) {
                const uint32_t* base = &As[cur][(wm * 32 + mt * 16) * LDK + ks * 8];
                af[mt][0] = base[g * LDK + t];
                af[mt][1] = base[(g + 8) * LDK + t];
                af[mt][2] = base[g * LDK + t + 4];
                af[mt][3] = base[(g + 8) * LDK + t + 4];
            }
            uint32_t bf[8][2];
#pragma unroll
            for (int nt = 0; nt < 8; nt++) {
                const uint32_t* base = &Bs[cur][(wn * 64 + nt * 8) * LDK + ks * 8];
                bf[nt][0] = base[g * LDK + t];
                bf[nt][1] = base[g * LDK + t + 4];
            }
#pragma unroll
            for (int mt = 0; mt < 2; mt++)
#pragma unroll
                for (int nt = 0; nt < 8; nt++)
                    mma_tf32(acc[mt][nt], af[mt], bf[nt]);
        }
        if (kt + 1 < KT) {
            sts(cur ^ 1);
            __syncthreads();
        }
    }

#pragma unroll
    for (int nt = 0; nt < 8; nt++) {
        const int cb = n0 + wn * 64 + nt * 8 + t * 2;
        const float bv0 = bias[cb], bv1 = bias[cb + 1];
#pragma unroll
        for (int mt = 0; mt < 2; mt++) {
            int r0 = m0 + wm * 32 + mt * 16 + g;
            float o0 = acc[mt][nt][0] + bv0, o1 = acc[mt][nt][1] + bv1;
            float o2 = acc[mt][nt][2] + bv0, o3 = acc[mt][nt][3] + bv1;
            if (RELU) {
                o0 = fmaxf(o0, 0.f); o1 = fmaxf(o1, 0.f);
                o2 = fmaxf(o2, 0.f); o3 = fmaxf(o3, 0.f);
            }
            if (r0 < M)
                *reinterpret_cast<float2*>(&C[(size_t)r0 * N + cb]) = make_float2(o0, o1);
            if (r0 + 8 < M)
                *reinterpret_cast<float2*>(&C[(size_t)(r0 + 8) * N + cb]) = make_float2(o2, o3);
        }
    }
}

// ------------------------- small-N GEMM (64x64 tile) for offsets / attn weights -------------------------
template <bool RELU>
__global__ void gemm_bias_kernel(const float* __restrict__ A, const float* __restrict__ W,
                                 const float* __restrict__ bias, float* __restrict__ C,
                                 int M, int N, int K) {
    __shared__ float As[16][65];
    __shared__ float Bs[16][65];
    const int tid = threadIdx.x;
    const int tx = tid & 15, ty = tid >> 4;
    const int m0 = blockIdx.y * 64, n0 = blockIdx.x * 64;
    const int lr = tid >> 2;
    const int lc = (tid & 3) * 4;

    float acc[4][4];
#pragma unroll
    for (int i = 0; i < 4; i++)
#pragma unroll
        for (int j = 0; j < 4; j++) acc[i][j] = 0.f;

    for (int k0 = 0; k0 < K; k0 += 16) {
        {
            int gm = m0 + lr;
            float4 v = make_float4(0.f, 0.f, 0.f, 0.f);
            if (gm < M) v = *reinterpret_cast<const float4*>(&A[(size_t)gm * K + k0 + lc]);
            As[lc + 0][lr] = v.x; As[lc + 1][lr] = v.y; As[lc + 2][lr] = v.z; As[lc + 3][lr] = v.w;
            int gn = n0 + lr;
            float4 w4 = make_float4(0.f, 0.f, 0.f, 0.f);
            if (gn < N) w4 = *reinterpret_cast<const float4*>(&W[(size_t)gn * K + k0 + lc]);
            Bs[lc + 0][lr] = w4.x; Bs[lc + 1][lr] = w4.y; Bs[lc + 2][lr] = w4.z; Bs[lc + 3][lr] = w4.w;
        }
        __syncthreads();
#pragma unroll
        for (int kk = 0; kk < 16; kk++) {
            float a[4], b[4];
#pragma unroll
            for (int i = 0; i < 4; i++) a[i] = As[kk][ty * 4 + i];
#pragma unroll
            for (int j = 0; j < 4; j++) b[j] = Bs[kk][tx * 4 + j];
#pragma unroll
            for (int i = 0; i < 4; i++)
#pragma unroll
                for (int j = 0; j < 4; j++) acc[i][j] += a[i] * b[j];
        }
        __syncthreads();
    }
#pragma unroll
    for (int i = 0; i < 4; i++) {
        int gm = m0 + ty * 4 + i;
        if (gm >= M) continue;
#pragma unroll
        for (int j = 0; j < 4; j++) {
            int gn = n0 + tx * 4 + j;
            if (gn >= N) continue;
            float v = acc[i][j] + bias[gn];
            if (RELU) v = fmaxf(v, 0.f);
            C[(size_t)gm * N + gn] = v;
        }
    }
}

// ------------------------- flash attention (DH=32, 64-row Q tiles) -------------------------
// Q from qk[..,h*32], K from qk[..,256+h*32] (row stride 512), V stride 256.
__global__ void attn_kernel(const float* __restrict__ QK, const float* __restrict__ V,
                            float* __restrict__ O) {
    const int q0 = blockIdx.x * 64;
    const int h  = blockIdx.y;
    const int b  = blockIdx.z;
    const int tid = threadIdx.x;
    __shared__ float Qs[64][36];
    __shared__ float Ks[64][36];
    __shared__ float Vs[64][36];
    __shared__ float Ps[64][65];

    const int row  = tid >> 2;
    const int quad = tid & 3;

    for (int i = tid; i < 64 * 8; i += 256) {
        int r = i >> 3, c = (i & 7) * 4;
        float4 v = *reinterpret_cast<const float4*>(&QK[((size_t)(b * NQ + q0 + r) * 512) + h * DH + c]);
        *reinterpret_cast<float4*>(&Qs[r][c]) = v;
    }
    __syncthreads();

    float qreg[32];
#pragma unroll
    for (int k = 0; k < 32; k++) qreg[k] = Qs[row][k] * 0.17677669529663687f;

    float m_run = -1e30f, lsum = 0.f;
    float acc[8];
#pragma unroll
    for (int i = 0; i < 8; i++) acc[i] = 0.f;

    for (int t0 = 0; t0 < NQ; t0 += 64) {
        __syncthreads();
        for (int i = tid; i < 64 * 8; i += 256) {
            int r = i >> 3, c = (i & 7) * 4;
            float4 kv = *reinterpret_cast<const float4*>(&QK[((size_t)(b * NQ + t0 + r) * 512) + 256 + h * DH + c]);
            *reinterpret_cast<float4*>(&Ks[r][c]) = kv;
            float4 vv = *reinterpret_cast<const float4*>(&V[((size_t)(b * NQ + t0 + r) * D) + h * DH + c]);
            *reinterpret_cast<float4*>(&Vs[r][c]) = vv;
        }
        __syncthreads();

        float s[16];
        float mt = -1e30f;
#pragma unroll
        for (int jj = 0; jj < 16; jj++) {
            int j = jj * 4 + quad;
            const float4* kp = reinterpret_cast<const float4*>(&Ks[j][0]);
            float sa = 0.f;
#pragma unroll
            for (int kq = 0; kq < 8; kq++) {
                float4 kv = kp[kq];
                sa += qreg[4 * kq + 0] * kv.x + qreg[4 * kq + 1] * kv.y
                    + qreg[4 * kq + 2] * kv.z + qreg[4 * kq + 3] * kv.w;
            }
            s[jj] = sa;
            mt = fmaxf(mt, sa);
        }
        mt = fmaxf(mt, __shfl_xor_sync(0xffffffffu, mt, 1));
        mt = fmaxf(mt, __shfl_xor_sync(0xffffffffu, mt, 2));
        float m_new = fmaxf(m_run, mt);
        float scale = __expf(m_run - m_new);
        float psum = 0.f;
#pragma unroll
        for (int jj = 0; jj < 16; jj++) {
            float p = __expf(s[jj] - m_new);
            Ps[row][jj * 4 + quad] = p;
            psum += p;
        }
        psum += __shfl_xor_sync(0xffffffffu, psum, 1);
        psum += __shfl_xor_sync(0xffffffffu, psum, 2);
        lsum = lsum * scale + psum;
        m_run = m_new;
#pragma unroll
        for (int i = 0; i < 8; i++) acc[i] *= scale;
        __syncthreads();
#pragma unroll 8
        for (int j = 0; j < 64; j++) {
            float p = Ps[row][j];
            const float4* vp = reinterpret_cast<const float4*>(&Vs[j][quad * 8]);
            float4 v0 = vp[0], v1 = vp[1];
            acc[0] += p * v0.x; acc[1] += p * v0.y; acc[2] += p * v0.z; acc[3] += p * v0.w;
            acc[4] += p * v1.x; acc[5] += p * v1.y; acc[6] += p * v1.z; acc[7] += p * v1.w;
        }
    }
    float inv = 1.f / lsum;
#pragma unroll
    for (int i = 0; i < 8; i++)
        O[((size_t)(b * NQ + q0 + row) * D) + h * DH + quad * 8 + i] = acc[i] * inv;
}

// ------------------------- residual + LayerNorm -------------------------
__global__ void add_ln_kernel(const float* __restrict__ x, const float* __restrict__ r,
                              const float* __restrict__ w, const float* __restrict__ b,
                              float* __restrict__ out) {
    const int row = blockIdx.x;
    const int t = threadIdx.x;
    float v = x[(size_t)row * D + t] + r[(size_t)row * D + t];

    __shared__ float red[8];
    __shared__ float sh_mean, sh_rstd;
    float s = v;
#pragma unroll
    for (int o = 16; o; o >>= 1) s += __shfl_xor_sync(0xffffffffu, s, o);
    if ((t & 31) == 0) red[t >> 5] = s;
    __syncthreads();
    if (t < 32) {
        float z = (t < 8) ? red[t] : 0.f;
#pragma unroll
        for (int o = 4; o; o >>= 1) z += __shfl_xor_sync(0xffffffffu, z, o);
        if (t == 0) sh_mean = z * (1.f / D);
    }
    __syncthreads();
    float m = sh_mean;
    float d = v - m;
    float sq = d * d;
#pragma unroll
    for (int o = 16; o; o >>= 1) sq += __shfl_xor_sync(0xffffffffu, sq, o);
    __syncthreads();
    if ((t & 31) == 0) red[t >> 5] = sq;
    __syncthreads();
    if (t < 32) {
        float z = (t < 8) ? red[t] : 0.f;
#pragma unroll
        for (int o = 4; o; o >>= 1) z += __shfl_xor_sync(0xffffffffu, z, o);
        if (t == 0) sh_rstd = rsqrtf(z * (1.f / D) + 1e-5f);
    }
    __syncthreads();
    out[(size_t)row * D + t] = d * sh_rstd * w[t] + b[t];
}

// ------------------------- MSDA sampling (warp per (b,q,h), lane = dh) -------------------------
__global__ void msda_kernel(const float* __restrict__ val, const float* __restrict__ off,
                            const float* __restrict__ aw, const float* __restrict__ ref,
                            const int* __restrict__ lsi, float* __restrict__ out) {
    const int warp = (blockIdx.x * blockDim.x + threadIdx.x) >> 5;
    const int lane = threadIdx.x & 31;
    if (warp >= BS * NQ * NH) return;
    const int h  = warp % NH;
    const int bq = warp / NH;
    const int b  = bq / NQ;
    const int base = lsi[0];

    const float rx = ref[bq * 2 + 0] * (float)W_BEV - 0.5f;
    const float ry = ref[bq * 2 + 1] * (float)H_BEV - 0.5f;

    float a0 = aw[bq * (NH * NP) + h * NP + 0];
    float a1 = aw[bq * (NH * NP) + h * NP + 1];
    float a2 = aw[bq * (NH * NP) + h * NP + 2];
    float a3 = aw[bq * (NH * NP) + h * NP + 3];
    float mx = fmaxf(fmaxf(a0, a1), fmaxf(a2, a3));
    float e0 = __expf(a0 - mx), e1 = __expf(a1 - mx), e2 = __expf(a2 - mx), e3 = __expf(a3 - mx);
    float inv = 1.f / (e0 + e1 + e2 + e3);
    float ap[4] = {e0 * inv, e1 * inv, e2 * inv, e3 * inv};

    float accv = 0.f;
#pragma unroll
    for (int p = 0; p < NP; p++) {
        float ox = off[bq * (NH * NP * 2) + (h * NP + p) * 2 + 0];
        float oy = off[bq * (NH * NP * 2) + (h * NP + p) * 2 + 1];
        float x = rx + ox, y = ry + oy;
        float x0f = floorf(x), y0f = floorf(y);
        int x0 = (int)x0f, y0 = (int)y0f;
        float fx = x - x0f, fy = y - y0f;
        float wgt[4] = {(1.f - fx) * (1.f - fy), fx * (1.f - fy), (1.f - fx) * fy, fx * fy};
        int xs[4] = {x0, x0 + 1, x0, x0 + 1};
        int ys[4] = {y0, y0, y0 + 1, y0 + 1};
#pragma unroll
        for (int c = 0; c < 4; c++) {
            int xi = xs[c], yi = ys[c];
            if (xi >= 0 && xi < W_BEV && yi >= 0 && yi < H_BEV) {
                float vv = val[((size_t)(b * NV + base + yi * W_BEV + xi)) * D + h * DH + lane];
                accv += ap[p] * wgt[c] * vv;
            }
        }
    }
    out[(size_t)bq * D + h * DH + lane] = accv;
}

// ------------------------- refs tail -------------------------
__global__ void copy_refs_kernel(const float* __restrict__ ref, float* __restrict__ out) {
    int i = blockIdx.x * blockDim.x + threadIdx.x;
    const int n1 = BS * NQ * 2;
    if (i < LNUM * n1) out[i] = ref[i % n1];
}

// ------------------------- launch -------------------------
extern "C" void kernel_launch(void* const* d_in, const int* in_sizes, int n_in,
                              void* d_out, int out_size) {
    const float* query    = (const float*)d_in[0];
    const float* qpos     = (const float*)d_in[1];
    const float* ref      = (const float*)d_in[2];
    const float* src      = (const float*)d_in[3];
    const int*   lsi      = (const int*)d_in[5];
    const float* sa_in_w  = (const float*)d_in[6];
    const float* sa_in_b  = (const float*)d_in[7];
    const float* sa_out_w = (const float*)d_in[8];
    const float* sa_out_b = (const float*)d_in[9];
    const float* ca_off_w = (const float*)d_in[10];
    const float* ca_off_b = (const float*)d_in[11];
    const float* ca_aw_w  = (const float*)d_in[12];
    const float* ca_aw_b  = (const float*)d_in[13];
    const float* ca_val_w = (const float*)d_in[14];
    const float* ca_val_b = (const float*)d_in[15];
    const float* ca_out_w = (const float*)d_in[16];
    const float* ca_out_b = (const float*)d_in[17];
    const float* n1_w     = (const float*)d_in[18];
    const float* n1_b     = (const float*)d_in[19];
    const float* n2_w     = (const float*)d_in[20];
    const float* n2_b     = (const float*)d_in[21];
    const float* n3_w     = (const float*)d_in[22];
    const float* n3_b     = (const float*)d_in[23];
    const float* ff1_w    = (const float*)d_in[24];
    const float* ff1_b    = (const float*)d_in[25];
    const float* ff2_w    = (const float*)d_in[26];
    const float* ff2_b    = (const float*)d_in[27];

    float *xbuf, *qkb, *vb, *sab, *tmpb, *t1b, *t2b, *valb, *offb, *awb, *cab, *ffnb;
    cudaGetSymbolAddress((void**)&xbuf, g_xbuf);
    cudaGetSymbolAddress((void**)&qkb,  g_qk);
    cudaGetSymbolAddress((void**)&vb,   g_v);
    cudaGetSymbolAddress((void**)&sab,  g_sa);
    cudaGetSymbolAddress((void**)&tmpb, g_tmp);
    cudaGetSymbolAddress((void**)&t1b,  g_t1);
    cudaGetSymbolAddress((void**)&t2b,  g_t2);
    cudaGetSymbolAddress((void**)&valb, g_val);
    cudaGetSymbolAddress((void**)&offb, g_off);
    cudaGetSymbolAddress((void**)&awb,  g_aw);
    cudaGetSymbolAddress((void**)&cab,  g_ca);
    cudaGetSymbolAddress((void**)&ffnb, g_ffn);

    float* out_hs = (float*)d_out;
    const int NTOK = MROWS * D;

    for (int l = 0; l < LNUM; l++) {
        const float* prev = (l == 0) ? query : out_hs + (size_t)(l - 1) * NTOK;
        float* cur = out_hs + (size_t)l * NTOK;

        // --- self attention ---
        add_kernel<<<(NTOK + 255) / 256, 256>>>(prev, qpos, xbuf, NTOK);
        gemm_tc<false><<<dim3(512 / 128, MROWS / 128), 256>>>(
            xbuf, sa_in_w + (size_t)l * 3 * D * D, sa_in_b + (size_t)l * 3 * D,
            qkb, MROWS, 512, D);
        gemm_tc<false><<<dim3(D / 128, MROWS / 128), 256>>>(
            prev, sa_in_w + (size_t)l * 3 * D * D + (size_t)2 * D * D,
            sa_in_b + (size_t)l * 3 * D + 2 * D, vb, MROWS, D, D);
        attn_kernel<<<dim3(NQ / 64, NH, BS), 256>>>(qkb, vb, sab);
        gemm_tc<false><<<dim3(D / 128, MROWS / 128), 256>>>(
            sab, sa_out_w + (size_t)l * D * D, sa_out_b + (size_t)l * D, tmpb, MROWS, D, D);
        add_ln_kernel<<<MROWS, 256>>>(tmpb, prev, n2_w + (size_t)l * D, n2_b + (size_t)l * D, t1b);

        // --- deformable cross attention ---
        add_kernel<<<(NTOK + 255) / 256, 256>>>(t1b, qpos, xbuf, NTOK);
        gemm_tc<false><<<dim3(D / 128, (BS * NV + 127) / 128), 256>>>(
            src, ca_val_w + (size_t)l * D * D, ca_val_b + (size_t)l * D, valb, BS * NV, D, D);
        gemm_bias_kernel<false><<<dim3(1, 64), 256>>>(
            xbuf, ca_off_w + (size_t)l * NH * NP * 2 * D, ca_off_b + (size_t)l * NH * NP * 2,
            offb, MROWS, NH * NP * 2, D);
        gemm_bias_kernel<false><<<dim3(1, 64), 256>>>(
            xbuf, ca_aw_w + (size_t)l * NH * NP * D, ca_aw_b + (size_t)l * NH * NP,
            awb, MROWS, NH * NP, D);
        msda_kernel<<<(BS * NQ * NH + 7) / 8, 256>>>(valb, offb, awb, ref, lsi, cab);
        gemm_tc<false><<<dim3(D / 128, MROWS / 128), 256>>>(
            cab, ca_out_w + (size_t)l * D * D, ca_out_b + (size_t)l * D, tmpb, MROWS, D, D);
        add_ln_kernel<<<MROWS, 256>>>(tmpb, t1b, n1_w + (size_t)l * D, n1_b + (size_t)l * D, t2b);

        // --- FFN ---
        gemm_tc<true><<<dim3(DFF / 128, MROWS / 128), 256>>>(
            t2b, ff1_w + (size_t)l * DFF * D, ff1_b + (size_t)l * DFF, ffnb, MROWS, DFF, D);
        gemm_tc<false><<<dim3(D / 128, MROWS / 128), 256>>>(
            ffnb, ff2_w + (size_t)l * D * DFF, ff2_b + (size_t)l * D, tmpb, MROWS, D, DFF);
        add_ln_kernel<<<MROWS, 256>>>(tmpb, t2b, n3_w + (size_t)l * D, n3_b + (size_t)l * D, cur);
    }

    const int hs_total = LNUM * MROWS * D;
    if (out_size > hs_total) {
        copy_refs_kernel<<<(LNUM * BS * NQ * 2 + 255) / 256, 256>>>(ref, out_hs + hs_total);
    }
}

// round 4
// speedup vs baseline: 3.0145x; 1.5671x over previous
#include <cuda_runtime.h>
#include <cuda_bf16.h>
#include <cstdint>

#define BS   4
#define NQ   1024
#define D    256
#define NH   8
#define NP   4
#define LNUM 6
#define DFF  1024
#define H_BEV 200
#define W_BEV 150
#define NV   (H_BEV * W_BEV)
#define DH   32
#define MROWS (BS * NQ)          // 4096

// ------------------------- scratch (static device globals) -------------------------
__device__ float g_xbuf[MROWS * D];
__device__ float g_qk[MROWS * 512];
__device__ float g_v[MROWS * D];
__device__ float g_sa[MROWS * D];
__device__ float g_tmp[MROWS * D];
__device__ float g_t1[MROWS * D];
__device__ float g_t2[MROWS * D];
__device__ float g_val[(size_t)BS * NV * D];
__device__ float g_off[MROWS * NH * NP * 2];
__device__ float g_aw[MROWS * NH * NP];
__device__ float g_ca[MROWS * D];
__device__ float g_ffn[MROWS * DFF];

// ------------------------- helpers -------------------------
__device__ __forceinline__ uint32_t f2tf(float f) {
    uint32_t r;
    asm("cvt.rna.tf32.f32 %0, %1;" : "=r"(r) : "f"(f));
    return r;
}
__device__ __forceinline__ void mma_tf32(float* c, const uint32_t* a, const uint32_t* b) {
    asm volatile("mma.sync.aligned.m16n8k8.row.col.f32.tf32.tf32.f32 "
                 "{%0,%1,%2,%3},{%4,%5,%6,%7},{%8,%9},{%0,%1,%2,%3};"
                 : "+f"(c[0]), "+f"(c[1]), "+f"(c[2]), "+f"(c[3])
                 : "r"(a[0]), "r"(a[1]), "r"(a[2]), "r"(a[3]), "r"(b[0]), "r"(b[1]));
}

// ------------------------- elementwise add -------------------------
__global__ void add_kernel(const float* __restrict__ a, const float* __restrict__ b,
                           float* __restrict__ o, int n) {
    int i = blockIdx.x * blockDim.x + threadIdx.x;
    if (i < n) o[i] = a[i] + b[i];
}

// ------------------------- tf32 tensor-core GEMM -------------------------
template <bool RELU>
__global__ __launch_bounds__(256)
void gemm_tc(const float* __restrict__ A, const float* __restrict__ W,
             const float* __restrict__ bias, float* __restrict__ C,
             int M, int N, int K) {
    constexpr int LDK = 20;
    __shared__ uint32_t As[2][128 * LDK];
    __shared__ uint32_t Bs[2][128 * LDK];

    const int tid  = threadIdx.x;
    const int lane = tid & 31;
    const int wid  = tid >> 5;
    const int wm   = wid & 3;
    const int wn   = wid >> 2;
    const int g    = lane >> 2;
    const int t    = lane & 3;
    const int m0   = blockIdx.y * 128;
    const int n0   = blockIdx.x * 128;

    const int arow = tid >> 1;
    const int acg  = (tid & 1) * 8;

    float4 sa0, sa1, sb0, sb1;

    auto ldg = [&](int k0) {
        int gm = m0 + arow;
        if (gm < M) {
            const float* ap = &A[(size_t)gm * K + k0 + acg];
            sa0 = *reinterpret_cast<const float4*>(ap);
            sa1 = *reinterpret_cast<const float4*>(ap + 4);
        } else {
            sa0 = make_float4(0.f, 0.f, 0.f, 0.f);
            sa1 = sa0;
        }
        const float* bp = &W[(size_t)(n0 + arow) * K + k0 + acg];
        sb0 = *reinterpret_cast<const float4*>(bp);
        sb1 = *reinterpret_cast<const float4*>(bp + 4);
    };
    auto sts = [&](int buf) {
        uint4 u0 = make_uint4(f2tf(sa0.x), f2tf(sa0.y), f2tf(sa0.z), f2tf(sa0.w));
        uint4 u1 = make_uint4(f2tf(sa1.x), f2tf(sa1.y), f2tf(sa1.z), f2tf(sa1.w));
        *reinterpret_cast<uint4*>(&As[buf][arow * LDK + acg])     = u0;
        *reinterpret_cast<uint4*>(&As[buf][arow * LDK + acg + 4]) = u1;
        uint4 v0 = make_uint4(f2tf(sb0.x), f2tf(sb0.y), f2tf(sb0.z), f2tf(sb0.w));
        uint4 v1 = make_uint4(f2tf(sb1.x), f2tf(sb1.y), f2tf(sb1.z), f2tf(sb1.w));
        *reinterpret_cast<uint4*>(&Bs[buf][arow * LDK + acg])     = v0;
        *reinterpret_cast<uint4*>(&Bs[buf][arow * LDK + acg + 4]) = v1;
    };

    float acc[2][8][4];
#pragma unroll
    for (int i = 0; i < 2; i++)
#pragma unroll
        for (int j = 0; j < 8; j++)
#pragma unroll
            for (int c = 0; c < 4; c++) acc[i][j][c] = 0.f;

    ldg(0);
    sts(0);
    __syncthreads();

    const int KT = K / 16;
    for (int kt = 0; kt < KT; kt++) {
        const int cur = kt & 1;
        if (kt + 1 < KT) ldg((kt + 1) * 16);
#pragma unroll
        for (int ks = 0; ks < 2; ks++) {
            uint32_t af[2][4];
#pragma unroll
            for (int mt = 0; mt < 2; mt++) {
                const uint32_t* base = &As[cur][(wm * 32 + mt * 16) * LDK + ks * 8];
                af[mt][0] = base[g * LDK + t];
                af[mt][1] = base[(g + 8) * LDK + t];
                af[mt][2] = base[g * LDK + t + 4];
                af[mt][3] = base[(g + 8) * LDK + t + 4];
            }
            uint32_t bf[8][2];
#pragma unroll
            for (int nt = 0; nt < 8; nt++) {
                const uint32_t* base = &Bs[cur][(wn * 64 + nt * 8) * LDK + ks * 8];
                bf[nt][0] = base[g * LDK + t];
                bf[nt][1] = base[g * LDK + t + 4];
            }
#pragma unroll
            for (int mt = 0; mt < 2; mt++)
#pragma unroll
                for (int nt = 0; nt < 8; nt++)
                    mma_tf32(acc[mt][nt], af[mt], bf[nt]);
        }
        if (kt + 1 < KT) {
            sts(cur ^ 1);
            __syncthreads();
        }
    }

#pragma unroll
    for (int nt = 0; nt < 8; nt++) {
        const int cb = n0 + wn * 64 + nt * 8 + t * 2;
        const float bv0 = bias[cb], bv1 = bias[cb + 1];
#pragma unroll
        for (int mt = 0; mt < 2; mt++) {
            int r0 = m0 + wm * 32 + mt * 16 + g;
            float o0 = acc[mt][nt][0] + bv0, o1 = acc[mt][nt][1] + bv1;
            float o2 = acc[mt][nt][2] + bv0, o3 = acc[mt][nt][3] + bv1;
            if (RELU) {
                o0 = fmaxf(o0, 0.f); o1 = fmaxf(o1, 0.f);
                o2 = fmaxf(o2, 0.f); o3 = fmaxf(o3, 0.f);
            }
            if (r0 < M)
                *reinterpret_cast<float2*>(&C[(size_t)r0 * N + cb]) = make_float2(o0, o1);
            if (r0 + 8 < M)
                *reinterpret_cast<float2*>(&C[(size_t)(r0 + 8) * N + cb]) = make_float2(o2, o3);
        }
    }
}

// ------------------------- small-N GEMM (64x64 tile) -------------------------
template <bool RELU>
__global__ void gemm_bias_kernel(const float* __restrict__ A, const float* __restrict__ W,
                                 const float* __restrict__ bias, float* __restrict__ C,
                                 int M, int N, int K) {
    __shared__ float As[16][65];
    __shared__ float Bs[16][65];
    const int tid = threadIdx.x;
    const int tx = tid & 15, ty = tid >> 4;
    const int m0 = blockIdx.y * 64, n0 = blockIdx.x * 64;
    const int lr = tid >> 2;
    const int lc = (tid & 3) * 4;

    float acc[4][4];
#pragma unroll
    for (int i = 0; i < 4; i++)
#pragma unroll
        for (int j = 0; j < 4; j++) acc[i][j] = 0.f;

    for (int k0 = 0; k0 < K; k0 += 16) {
        {
            int gm = m0 + lr;
            float4 v = make_float4(0.f, 0.f, 0.f, 0.f);
            if (gm < M) v = *reinterpret_cast<const float4*>(&A[(size_t)gm * K + k0 + lc]);
            As[lc + 0][lr] = v.x; As[lc + 1][lr] = v.y; As[lc + 2][lr] = v.z; As[lc + 3][lr] = v.w;
            int gn = n0 + lr;
            float4 w4 = make_float4(0.f, 0.f, 0.f, 0.f);
            if (gn < N) w4 = *reinterpret_cast<const float4*>(&W[(size_t)gn * K + k0 + lc]);
            Bs[lc + 0][lr] = w4.x; Bs[lc + 1][lr] = w4.y; Bs[lc + 2][lr] = w4.z; Bs[lc + 3][lr] = w4.w;
        }
        __syncthreads();
#pragma unroll
        for (int kk = 0; kk < 16; kk++) {
            float a[4], b[4];
#pragma unroll
            for (int i = 0; i < 4; i++) a[i] = As[kk][ty * 4 + i];
#pragma unroll
            for (int j = 0; j < 4; j++) b[j] = Bs[kk][tx * 4 + j];
#pragma unroll
            for (int i = 0; i < 4; i++)
#pragma unroll
                for (int j = 0; j < 4; j++) acc[i][j] += a[i] * b[j];
        }
        __syncthreads();
    }
#pragma unroll
    for (int i = 0; i < 4; i++) {
        int gm = m0 + ty * 4 + i;
        if (gm >= M) continue;
#pragma unroll
        for (int j = 0; j < 4; j++) {
            int gn = n0 + tx * 4 + j;
            if (gn >= N) continue;
            float v = acc[i][j] + bias[gn];
            if (RELU) v = fmaxf(v, 0.f);
            C[(size_t)gm * N + gn] = v;
        }
    }
}

// ------------------------- tensor-core flash attention -------------------------
// grid (NQ/128, NH, BS), 256 threads (8 warps x 16 q-rows).
// Q at QK[row*512 + h*32], K at QK[row*512 + 256 + h*32], V stride 256.
#define LKP 36
#define LVP 40
__global__ __launch_bounds__(256)
void attn_tc_kernel(const float* __restrict__ QK, const float* __restrict__ V,
                    float* __restrict__ O) {
    __shared__ uint32_t Ks[64 * LKP];
    __shared__ uint32_t Vs[64 * LVP];

    const int q0   = blockIdx.x * 128;
    const int h    = blockIdx.y;
    const int b    = blockIdx.z;
    const int tid  = threadIdx.x;
    const int lane = tid & 31;
    const int w    = tid >> 5;
    const int g    = lane >> 2;
    const int t    = lane & 3;

    // ---- Q fragments (register resident, scaled) ----
    uint32_t af[4][4];
    {
        const int r0 = b * NQ + q0 + w * 16 + g;
        const int r1 = r0 + 8;
        const float sc = 0.17677669529663687f;  // 1/sqrt(32)
        const float* Q0 = &QK[(size_t)r0 * 512 + h * 32];
        const float* Q1 = &QK[(size_t)r1 * 512 + h * 32];
#pragma unroll
        for (int ks = 0; ks < 4; ks++) {
            af[ks][0] = f2tf(Q0[ks * 8 + t] * sc);
            af[ks][1] = f2tf(Q1[ks * 8 + t] * sc);
            af[ks][2] = f2tf(Q0[ks * 8 + t + 4] * sc);
            af[ks][3] = f2tf(Q1[ks * 8 + t + 4] * sc);
        }
    }

    float oc[4][4];
#pragma unroll
    for (int i = 0; i < 4; i++)
#pragma unroll
        for (int j = 0; j < 4; j++) oc[i][j] = 0.f;
    float m0r = -1e30f, m1r = -1e30f, l0 = 0.f, l1 = 0.f;

    const int lrow = tid >> 2;          // 0..63
    const int lcg  = (tid & 3) * 8;     // 0,8,16,24
    const unsigned F = 0xffffffffu;

    for (int t0 = 0; t0 < NQ; t0 += 64) {
        __syncthreads();
        // ---- cooperative K/V tile load + tf32 convert ----
        {
            const float* kp = &QK[(size_t)(b * NQ + t0 + lrow) * 512 + 256 + h * 32 + lcg];
            float4 k0 = *reinterpret_cast<const float4*>(kp);
            float4 k1 = *reinterpret_cast<const float4*>(kp + 4);
            *reinterpret_cast<uint4*>(&Ks[lrow * LKP + lcg]) =
                make_uint4(f2tf(k0.x), f2tf(k0.y), f2tf(k0.z), f2tf(k0.w));
            *reinterpret_cast<uint4*>(&Ks[lrow * LKP + lcg + 4]) =
                make_uint4(f2tf(k1.x), f2tf(k1.y), f2tf(k1.z), f2tf(k1.w));
            const float* vp = &V[(size_t)(b * NQ + t0 + lrow) * 256 + h * 32 + lcg];
            float4 v0 = *reinterpret_cast<const float4*>(vp);
            float4 v1 = *reinterpret_cast<const float4*>(vp + 4);
            *reinterpret_cast<uint4*>(&Vs[lrow * LVP + lcg]) =
                make_uint4(f2tf(v0.x), f2tf(v0.y), f2tf(v0.z), f2tf(v0.w));
            *reinterpret_cast<uint4*>(&Vs[lrow * LVP + lcg + 4]) =
                make_uint4(f2tf(v1.x), f2tf(v1.y), f2tf(v1.z), f2tf(v1.w));
        }
        __syncthreads();

        // ---- S = Q @ K^T  (16 x 64 per warp) ----
        float sc[8][4];
#pragma unroll
        for (int nt = 0; nt < 8; nt++) {
            sc[nt][0] = sc[nt][1] = sc[nt][2] = sc[nt][3] = 0.f;
            uint32_t bf[4][2];
#pragma unroll
            for (int ks = 0; ks < 4; ks++) {
                const uint32_t* base = &Ks[(nt * 8 + g) * LKP + ks * 8];
                bf[ks][0] = base[t];
                bf[ks][1] = base[t + 4];
            }
#pragma unroll
            for (int ks = 0; ks < 4; ks++) mma_tf32(sc[nt], af[ks], bf[ks]);
        }

        // ---- online softmax ----
        float mt0 = -1e30f, mt1 = -1e30f;
#pragma unroll
        for (int nt = 0; nt < 8; nt++) {
            mt0 = fmaxf(mt0, fmaxf(sc[nt][0], sc[nt][1]));
            mt1 = fmaxf(mt1, fmaxf(sc[nt][2], sc[nt][3]));
        }
        mt0 = fmaxf(mt0, __shfl_xor_sync(F, mt0, 1));
        mt0 = fmaxf(mt0, __shfl_xor_sync(F, mt0, 2));
        mt1 = fmaxf(mt1, __shfl_xor_sync(F, mt1, 1));
        mt1 = fmaxf(mt1, __shfl_xor_sync(F, mt1, 2));
        const float mn0 = fmaxf(m0r, mt0), mn1 = fmaxf(m1r, mt1);
        const float sc0 = __expf(m0r - mn0), sc1 = __expf(m1r - mn1);

        uint32_t pf[8][4];
        float s0 = 0.f, s1 = 0.f;
#pragma unroll
        for (int nt = 0; nt < 8; nt++) {
            float p0 = __expf(sc[nt][0] - mn0);
            float p1 = __expf(sc[nt][1] - mn0);
            float p2 = __expf(sc[nt][2] - mn1);
            float p3 = __expf(sc[nt][3] - mn1);
            s0 += p0 + p1; s1 += p2 + p3;
            pf[nt][0] = f2tf(p0); pf[nt][1] = f2tf(p1);
            pf[nt][2] = f2tf(p2); pf[nt][3] = f2tf(p3);
        }
        s0 += __shfl_xor_sync(F, s0, 1); s0 += __shfl_xor_sync(F, s0, 2);
        s1 += __shfl_xor_sync(F, s1, 1); s1 += __shfl_xor_sync(F, s1, 2);
        l0 = l0 * sc0 + s0;
        l1 = l1 * sc1 + s1;
        m0r = mn0; m1r = mn1;
#pragma unroll
        for (int nt = 0; nt < 4; nt++) {
            oc[nt][0] *= sc0; oc[nt][1] *= sc0;
            oc[nt][2] *= sc1; oc[nt][3] *= sc1;
        }

        // ---- O += P @ V  (C-layout -> A-layout via shfl) ----
        const int src0 = (lane & ~3) | (t >> 1);
        const int src1 = src0 + 2;
        const bool odd = (t & 1);
#pragma unroll
        for (int kt = 0; kt < 8; kt++) {
            uint32_t a[4];
            uint32_t x0 = __shfl_sync(F, pf[kt][0], src0);
            uint32_t x1 = __shfl_sync(F, pf[kt][1], src0);
            a[0] = odd ? x1 : x0;
            uint32_t x2 = __shfl_sync(F, pf[kt][2], src0);
            uint32_t x3 = __shfl_sync(F, pf[kt][3], src0);
            a[1] = odd ? x3 : x2;
            x0 = __shfl_sync(F, pf[kt][0], src1);
            x1 = __shfl_sync(F, pf[kt][1], src1);
            a[2] = odd ? x1 : x0;
            x2 = __shfl_sync(F, pf[kt][2], src1);
            x3 = __shfl_sync(F, pf[kt][3], src1);
            a[3] = odd ? x3 : x2;
#pragma unroll
            for (int nt = 0; nt < 4; nt++) {
                uint32_t bf[2];
                bf[0] = Vs[(kt * 8 + t) * LVP + nt * 8 + g];
                bf[1] = Vs[(kt * 8 + t + 4) * LVP + nt * 8 + g];
                mma_tf32(oc[nt], a, bf);
            }
        }
    }

    // ---- epilogue ----
    const float inv0 = 1.f / l0, inv1 = 1.f / l1;
    const int r0 = b * NQ + q0 + w * 16 + g;
#pragma unroll
    for (int nt = 0; nt < 4; nt++) {
        const int col = h * 32 + nt * 8 + t * 2;
        *reinterpret_cast<float2*>(&O[(size_t)r0 * 256 + col]) =
            make_float2(oc[nt][0] * inv0, oc[nt][1] * inv0);
        *reinterpret_cast<float2*>(&O[(size_t)(r0 + 8) * 256 + col]) =
            make_float2(oc[nt][2] * inv1, oc[nt][3] * inv1);
    }
}

// ------------------------- residual + LayerNorm -------------------------
__global__ void add_ln_kernel(const float* __restrict__ x, const float* __restrict__ r,
                              const float* __restrict__ w, const float* __restrict__ b,
                              float* __restrict__ out) {
    const int row = blockIdx.x;
    const int t = threadIdx.x;
    float v = x[(size_t)row * D + t] + r[(size_t)row * D + t];

    __shared__ float red[8];
    __shared__ float sh_mean, sh_rstd;
    float s = v;
#pragma unroll
    for (int o = 16; o; o >>= 1) s += __shfl_xor_sync(0xffffffffu, s, o);
    if ((t & 31) == 0) red[t >> 5] = s;
    __syncthreads();
    if (t < 32) {
        float z = (t < 8) ? red[t] : 0.f;
#pragma unroll
        for (int o = 4; o; o >>= 1) z += __shfl_xor_sync(0xffffffffu, z, o);
        if (t == 0) sh_mean = z * (1.f / D);
    }
    __syncthreads();
    float m = sh_mean;
    float d = v - m;
    float sq = d * d;
#pragma unroll
    for (int o = 16; o; o >>= 1) sq += __shfl_xor_sync(0xffffffffu, sq, o);
    __syncthreads();
    if ((t & 31) == 0) red[t >> 5] = sq;
    __syncthreads();
    if (t < 32) {
        float z = (t < 8) ? red[t] : 0.f;
#pragma unroll
        for (int o = 4; o; o >>= 1) z += __shfl_xor_sync(0xffffffffu, z, o);
        if (t == 0) sh_rstd = rsqrtf(z * (1.f / D) + 1e-5f);
    }
    __syncthreads();
    out[(size_t)row * D + t] = d * sh_rstd * w[t] + b[t];
}

// ------------------------- MSDA sampling -------------------------
__global__ void msda_kernel(const float* __restrict__ val, const float* __restrict__ off,
                            const float* __restrict__ aw, const float* __restrict__ ref,
                            const int* __restrict__ lsi, float* __restrict__ out) {
    const int warp = (blockIdx.x * blockDim.x + threadIdx.x) >> 5;
    const int lane = threadIdx.x & 31;
    if (warp >= BS * NQ * NH) return;
    const int h  = warp % NH;
    const int bq = warp / NH;
    const int b  = bq / NQ;
    const int base = lsi[0];

    const float rx = ref[bq * 2 + 0] * (float)W_BEV - 0.5f;
    const float ry = ref[bq * 2 + 1] * (float)H_BEV - 0.5f;

    float a0 = aw[bq * (NH * NP) + h * NP + 0];
    float a1 = aw[bq * (NH * NP) + h * NP + 1];
    float a2 = aw[bq * (NH * NP) + h * NP + 2];
    float a3 = aw[bq * (NH * NP) + h * NP + 3];
    float mx = fmaxf(fmaxf(a0, a1), fmaxf(a2, a3));
    float e0 = __expf(a0 - mx), e1 = __expf(a1 - mx), e2 = __expf(a2 - mx), e3 = __expf(a3 - mx);
    float inv = 1.f / (e0 + e1 + e2 + e3);
    float ap[4] = {e0 * inv, e1 * inv, e2 * inv, e3 * inv};

    float accv = 0.f;
#pragma unroll
    for (int p = 0; p < NP; p++) {
        float ox = off[bq * (NH * NP * 2) + (h * NP + p) * 2 + 0];
        float oy = off[bq * (NH * NP * 2) + (h * NP + p) * 2 + 1];
        float x = rx + ox, y = ry + oy;
        float x0f = floorf(x), y0f = floorf(y);
        int x0 = (int)x0f, y0 = (int)y0f;
        float fx = x - x0f, fy = y - y0f;
        float wgt[4] = {(1.f - fx) * (1.f - fy), fx * (1.f - fy), (1.f - fx) * fy, fx * fy};
        int xs[4] = {x0, x0 + 1, x0, x0 + 1};
        int ys[4] = {y0, y0, y0 + 1, y0 + 1};
#pragma unroll
        for (int c = 0; c < 4; c++) {
            int xi = xs[c], yi = ys[c];
            if (xi >= 0 && xi < W_BEV && yi >= 0 && yi < H_BEV) {
                float vv = val[((size_t)(b * NV + base + yi * W_BEV + xi)) * D + h * DH + lane];
                accv += ap[p] * wgt[c] * vv;
            }
        }
    }
    out[(size_t)bq * D + h * DH + lane] = accv;
}

// ------------------------- refs tail -------------------------
__global__ void copy_refs_kernel(const float* __restrict__ ref, float* __restrict__ out) {
    int i = blockIdx.x * blockDim.x + threadIdx.x;
    const int n1 = BS * NQ * 2;
    if (i < LNUM * n1) out[i] = ref[i % n1];
}

// ------------------------- launch -------------------------
extern "C" void kernel_launch(void* const* d_in, const int* in_sizes, int n_in,
                              void* d_out, int out_size) {
    const float* query    = (const float*)d_in[0];
    const float* qpos     = (const float*)d_in[1];
    const float* ref      = (const float*)d_in[2];
    const float* src      = (const float*)d_in[3];
    const int*   lsi      = (const int*)d_in[5];
    const float* sa_in_w  = (const float*)d_in[6];
    const float* sa_in_b  = (const float*)d_in[7];
    const float* sa_out_w = (const float*)d_in[8];
    const float* sa_out_b = (const float*)d_in[9];
    const float* ca_off_w = (const float*)d_in[10];
    const float* ca_off_b = (const float*)d_in[11];
    const float* ca_aw_w  = (const float*)d_in[12];
    const float* ca_aw_b  = (const float*)d_in[13];
    const float* ca_val_w = (const float*)d_in[14];
    const float* ca_val_b = (const float*)d_in[15];
    const float* ca_out_w = (const float*)d_in[16];
    const float* ca_out_b = (const float*)d_in[17];
    const float* n1_w     = (const float*)d_in[18];
    const float* n1_b     = (const float*)d_in[19];
    const float* n2_w     = (const float*)d_in[20];
    const float* n2_b     = (const float*)d_in[21];
    const float* n3_w     = (const float*)d_in[22];
    const float* n3_b     = (const float*)d_in[23];
    const float* ff1_w    = (const float*)d_in[24];
    const float* ff1_b    = (const float*)d_in[25];
    const float* ff2_w    = (const float*)d_in[26];
    const float* ff2_b    = (const float*)d_in[27];

    float *xbuf, *qkb, *vb, *sab, *tmpb, *t1b, *t2b, *valb, *offb, *awb, *cab, *ffnb;
    cudaGetSymbolAddress((void**)&xbuf, g_xbuf);
    cudaGetSymbolAddress((void**)&qkb,  g_qk);
    cudaGetSymbolAddress((void**)&vb,   g_v);
    cudaGetSymbolAddress((void**)&sab,  g_sa);
    cudaGetSymbolAddress((void**)&tmpb, g_tmp);
    cudaGetSymbolAddress((void**)&t1b,  g_t1);
    cudaGetSymbolAddress((void**)&t2b,  g_t2);
    cudaGetSymbolAddress((void**)&valb, g_val);
    cudaGetSymbolAddress((void**)&offb, g_off);
    cudaGetSymbolAddress((void**)&awb,  g_aw);
    cudaGetSymbolAddress((void**)&cab,  g_ca);
    cudaGetSymbolAddress((void**)&ffnb, g_ffn);

    float* out_hs = (float*)d_out;
    const int NTOK = MROWS * D;

    for (int l = 0; l < LNUM; l++) {
        const float* prev = (l == 0) ? query : out_hs + (size_t)(l - 1) * NTOK;
        float* cur = out_hs + (size_t)l * NTOK;

        // --- self attention ---
        add_kernel<<<(NTOK + 255) / 256, 256>>>(prev, qpos, xbuf, NTOK);
        gemm_tc<false><<<dim3(512 / 128, MROWS / 128), 256>>>(
            xbuf, sa_in_w + (size_t)l * 3 * D * D, sa_in_b + (size_t)l * 3 * D,
            qkb, MROWS, 512, D);
        gemm_tc<false><<<dim3(D / 128, MROWS / 128), 256>>>(
            prev, sa_in_w + (size_t)l * 3 * D * D + (size_t)2 * D * D,
            sa_in_b + (size_t)l * 3 * D + 2 * D, vb, MROWS, D, D);
        attn_tc_kernel<<<dim3(NQ / 128, NH, BS), 256>>>(qkb, vb, sab);
        gemm_tc<false><<<dim3(D / 128, MROWS / 128), 256>>>(
            sab, sa_out_w + (size_t)l * D * D, sa_out_b + (size_t)l * D, tmpb, MROWS, D, D);
        add_ln_kernel<<<MROWS, 256>>>(tmpb, prev, n2_w + (size_t)l * D, n2_b + (size_t)l * D, t1b);

        // --- deformable cross attention ---
        add_kernel<<<(NTOK + 255) / 256, 256>>>(t1b, qpos, xbuf, NTOK);
        gemm_tc<false><<<dim3(D / 128, (BS * NV + 127) / 128), 256>>>(
            src, ca_val_w + (size_t)l * D * D, ca_val_b + (size_t)l * D, valb, BS * NV, D, D);
        gemm_bias_kernel<false><<<dim3(1, 64), 256>>>(
            xbuf, ca_off_w + (size_t)l * NH * NP * 2 * D, ca_off_b + (size_t)l * NH * NP * 2,
            offb, MROWS, NH * NP * 2, D);
        gemm_bias_kernel<false><<<dim3(1, 64), 256>>>(
            xbuf, ca_aw_w + (size_t)l * NH * NP * D, ca_aw_b + (size_t)l * NH * NP,
            awb, MROWS, NH * NP, D);
        msda_kernel<<<(BS * NQ * NH + 7) / 8, 256>>>(valb, offb, awb, ref, lsi, cab);
        gemm_tc<false><<<dim3(D / 128, MROWS / 128), 256>>>(
            cab, ca_out_w + (size_t)l * D * D, ca_out_b + (size_t)l * D, tmpb, MROWS, D, D);
        add_ln_kernel<<<MROWS, 256>>>(tmpb, t1b, n1_w + (size_t)l * D, n1_b + (size_t)l * D, t2b);

        // --- FFN ---
        gemm_tc<true><<<dim3(DFF / 128, MROWS / 128), 256>>>(
            t2b, ff1_w + (size_t)l * DFF * D, ff1_b + (size_t)l * DFF, ffnb, MROWS, DFF, D);
        gemm_tc<false><<<dim3(D / 128, MROWS / 128), 256>>>(
            ffnb, ff2_w + (size_t)l * D * DFF, ff2_b + (size_t)l * D, tmpb, MROWS, D, DFF);
        add_ln_kernel<<<MROWS, 256>>>(tmpb, t2b, n3_w + (size_t)l * D, n3_b + (size_t)l * D, cur);
    }

    const int hs_total = LNUM * MROWS * D;
    if (out_size > hs_total) {
        copy_refs_kernel<<<(LNUM * BS * NQ * 2 + 255) / 256, 256>>>(ref, out_hs + hs_total);
    }
}

// round 5
// speedup vs baseline: 3.4887x; 1.1573x over previous
#include <cuda_runtime.h>
#include <cuda_bf16.h>
#include <cstdint>

#define BS   4
#define NQ   1024
#define D    256
#define NH   8
#define NP   4
#define LNUM 6
#define DFF  1024
#define H_BEV 200
#define W_BEV 150
#define NV   (H_BEV * W_BEV)
#define DH   32
#define MROWS (BS * NQ)          // 4096

// ------------------------- scratch (static device globals) -------------------------
__device__ float g_xbuf[MROWS * D];
__device__ float g_qk[MROWS * 512];
__device__ float g_v[MROWS * D];
__device__ float g_sa[MROWS * D];
__device__ float g_tmp[MROWS * D];
__device__ float g_t1[MROWS * D];
__device__ float g_t2[MROWS * D];
__device__ float g_val[(size_t)BS * NV * D];
__device__ float g_off[MROWS * NH * NP * 2];
__device__ float g_aw[MROWS * NH * NP];
__device__ float g_ca[MROWS * D];
__device__ float g_ffn[MROWS * DFF];

// ------------------------- helpers -------------------------
__device__ __forceinline__ uint32_t f2tf(float f) {
    uint32_t r;
    asm("cvt.rna.tf32.f32 %0, %1;" : "=r"(r) : "f"(f));
    return r;
}
__device__ __forceinline__ void mma_tf32(float* c, const uint32_t* a, const uint32_t* b) {
    asm volatile("mma.sync.aligned.m16n8k8.row.col.f32.tf32.tf32.f32 "
                 "{%0,%1,%2,%3},{%4,%5,%6,%7},{%8,%9},{%0,%1,%2,%3};"
                 : "+f"(c[0]), "+f"(c[1]), "+f"(c[2]), "+f"(c[3])
                 : "r"(a[0]), "r"(a[1]), "r"(a[2]), "r"(a[3]), "r"(b[0]), "r"(b[1]));
}
__device__ __forceinline__ void cp16(uint32_t smem_addr, const void* gptr, int src_bytes) {
    asm volatile("cp.async.ca.shared.global [%0], [%1], 16, %2;\n"
                 :: "r"(smem_addr), "l"(gptr), "r"(src_bytes));
}
__device__ __forceinline__ void cp_commit() { asm volatile("cp.async.commit_group;\n"); }
template <int N>
__device__ __forceinline__ void cp_wait() { asm volatile("cp.async.wait_group %0;\n" :: "n"(N)); }

// ------------------------- elementwise add -------------------------
__global__ void add_kernel(const float* __restrict__ a, const float* __restrict__ b,
                           float* __restrict__ o, int n) {
    int i = blockIdx.x * blockDim.x + threadIdx.x;
    if (i < n) o[i] = a[i] + b[i];
}

// ------------------------- tf32 tensor-core GEMM v2 (cp.async, LDS.128 frags) ----------
// C[M,N] = A[M,K] @ W[N,K]^T + bias.  CTA 128x128, BK=16, 3-stage cp.async pipeline.
// Fragments use the "virtual-k" pairing: LDS.128 at [row][4t] feeds two k8 MMA steps.
template <bool RELU>
__global__ __launch_bounds__(256)
void gemm_tc(const float* __restrict__ A, const float* __restrict__ W,
             const float* __restrict__ bias, float* __restrict__ C,
             int M, int N, int K) {
    constexpr int ST = 3;
    __shared__ uint32_t As[ST][128 * 16];
    __shared__ uint32_t Bs[ST][128 * 16];

    const int tid  = threadIdx.x;
    const int lane = tid & 31;
    const int wid  = tid >> 5;
    const int wm   = wid & 3;          // 32-row warp block
    const int wn   = wid >> 2;         // 64-col warp block
    const int g    = lane >> 2;
    const int t    = lane & 3;
    const int m0   = blockIdx.y * 128;
    const int n0   = blockIdx.x * 128;

    // cp.async mapping: chunk c (0..511): row=c>>2, colgroup=(c&3)*4
    const int c0 = tid, c1 = tid + 256;
    const int r0c = c0 >> 2, cg0 = (c0 & 3) * 4;
    const int r1c = c1 >> 2, cg1 = (c1 & 3) * 4;

    auto load_stage = [&](int s, int kt) {
        const int k0 = kt * 16;
        uint32_t sa = (uint32_t)__cvta_generic_to_shared(&As[s][0]);
        uint32_t sb = (uint32_t)__cvta_generic_to_shared(&Bs[s][0]);
        int gm0 = m0 + r0c, gm1 = m0 + r1c;
        cp16(sa + (r0c * 16 + cg0) * 4, &A[(size_t)gm0 * K + k0 + cg0], gm0 < M ? 16 : 0);
        cp16(sa + (r1c * 16 + cg1) * 4, &A[(size_t)gm1 * K + k0 + cg1], gm1 < M ? 16 : 0);
        cp16(sb + (r0c * 16 + cg0) * 4, &W[(size_t)(n0 + r0c) * K + k0 + cg0], 16);
        cp16(sb + (r1c * 16 + cg1) * 4, &W[(size_t)(n0 + r1c) * K + k0 + cg1], 16);
        cp_commit();
    };

    float acc[2][8][4];
#pragma unroll
    for (int i = 0; i < 2; i++)
#pragma unroll
        for (int j = 0; j < 8; j++)
#pragma unroll
            for (int c = 0; c < 4; c++) acc[i][j][c] = 0.f;

    const int KT = K / 16;
    load_stage(0, 0);
    if (KT > 1) load_stage(1, 1);

    for (int kt = 0; kt < KT; kt++) {
        cp_wait<1>();
        __syncthreads();
        const int s = kt % ST;

        uint32_t afA[2][4], afB[2][4];
#pragma unroll
        for (int mt = 0; mt < 2; mt++) {
            const int row = wm * 32 + mt * 16 + g;
            uint4 ar0 = *reinterpret_cast<const uint4*>(&As[s][row * 16 + t * 4]);
            uint4 ar1 = *reinterpret_cast<const uint4*>(&As[s][(row + 8) * 16 + t * 4]);
            afA[mt][0] = ar0.x; afA[mt][1] = ar1.x; afA[mt][2] = ar0.y; afA[mt][3] = ar1.y;
            afB[mt][0] = ar0.z; afB[mt][1] = ar1.z; afB[mt][2] = ar0.w; afB[mt][3] = ar1.w;
        }
#pragma unroll
        for (int nt = 0; nt < 8; nt++) {
            uint4 br = *reinterpret_cast<const uint4*>(&Bs[s][(wn * 64 + nt * 8 + g) * 16 + t * 4]);
            uint32_t bA[2] = {br.x, br.y};
            uint32_t bB[2] = {br.z, br.w};
#pragma unroll
            for (int mt = 0; mt < 2; mt++) {
                mma_tf32(acc[mt][nt], afA[mt], bA);
                mma_tf32(acc[mt][nt], afB[mt], bB);
            }
        }
        __syncthreads();
        if (kt + 2 < KT) load_stage((kt + 2) % ST, kt + 2);
    }

    float bv[8];
#pragma unroll
    for (int j = 0; j < 8; j++) {
        int idx = (j & 1) ? 1 : 0;
        bv[j] = bias[n0 + wn * 64 + (j >> 1) * 8 + t * 2 + idx];
    }
#pragma unroll
    for (int nt = 0; nt < 8; nt++) {
        const int cb = n0 + wn * 64 + nt * 8 + t * 2;
        const float bv0 = bias[cb], bv1 = bias[cb + 1];
#pragma unroll
        for (int mt = 0; mt < 2; mt++) {
            int r0 = m0 + wm * 32 + mt * 16 + g;
            float o0 = acc[mt][nt][0] + bv0, o1 = acc[mt][nt][1] + bv1;
            float o2 = acc[mt][nt][2] + bv0, o3 = acc[mt][nt][3] + bv1;
            if (RELU) {
                o0 = fmaxf(o0, 0.f); o1 = fmaxf(o1, 0.f);
                o2 = fmaxf(o2, 0.f); o3 = fmaxf(o3, 0.f);
            }
            if (r0 < M)
                *reinterpret_cast<float2*>(&C[(size_t)r0 * N + cb]) = make_float2(o0, o1);
            if (r0 + 8 < M)
                *reinterpret_cast<float2*>(&C[(size_t)(r0 + 8) * N + cb]) = make_float2(o2, o3);
        }
    }
}

// ------------------------- small-N GEMM (64x64 tile) -------------------------
template <bool RELU>
__global__ void gemm_bias_kernel(const float* __restrict__ A, const float* __restrict__ W,
                                 const float* __restrict__ bias, float* __restrict__ C,
                                 int M, int N, int K) {
    __shared__ float As[16][65];
    __shared__ float Bs[16][65];
    const int tid = threadIdx.x;
    const int tx = tid & 15, ty = tid >> 4;
    const int m0 = blockIdx.y * 64, n0 = blockIdx.x * 64;
    const int lr = tid >> 2;
    const int lc = (tid & 3) * 4;

    float acc[4][4];
#pragma unroll
    for (int i = 0; i < 4; i++)
#pragma unroll
        for (int j = 0; j < 4; j++) acc[i][j] = 0.f;

    for (int k0 = 0; k0 < K; k0 += 16) {
        {
            int gm = m0 + lr;
            float4 v = make_float4(0.f, 0.f, 0.f, 0.f);
            if (gm < M) v = *reinterpret_cast<const float4*>(&A[(size_t)gm * K + k0 + lc]);
            As[lc + 0][lr] = v.x; As[lc + 1][lr] = v.y; As[lc + 2][lr] = v.z; As[lc + 3][lr] = v.w;
            int gn = n0 + lr;
            float4 w4 = make_float4(0.f, 0.f, 0.f, 0.f);
            if (gn < N) w4 = *reinterpret_cast<const float4*>(&W[(size_t)gn * K + k0 + lc]);
            Bs[lc + 0][lr] = w4.x; Bs[lc + 1][lr] = w4.y; Bs[lc + 2][lr] = w4.z; Bs[lc + 3][lr] = w4.w;
        }
        __syncthreads();
#pragma unroll
        for (int kk = 0; kk < 16; kk++) {
            float a[4], b[4];
#pragma unroll
            for (int i = 0; i < 4; i++) a[i] = As[kk][ty * 4 + i];
#pragma unroll
            for (int j = 0; j < 4; j++) b[j] = Bs[kk][tx * 4 + j];
#pragma unroll
            for (int i = 0; i < 4; i++)
#pragma unroll
                for (int j = 0; j < 4; j++) acc[i][j] += a[i] * b[j];
        }
        __syncthreads();
    }
#pragma unroll
    for (int i = 0; i < 4; i++) {
        int gm = m0 + ty * 4 + i;
        if (gm >= M) continue;
#pragma unroll
        for (int j = 0; j < 4; j++) {
            int gn = n0 + tx * 4 + j;
            if (gn >= N) continue;
            float v = acc[i][j] + bias[gn];
            if (RELU) v = fmaxf(v, 0.f);
            C[(size_t)gm * N + gn] = v;
        }
    }
}

// ------------------------- tensor-core flash attention -------------------------
#define LKP 36
#define LVP 40
__global__ __launch_bounds__(256)
void attn_tc_kernel(const float* __restrict__ QK, const float* __restrict__ V,
                    float* __restrict__ O) {
    __shared__ uint32_t Ks[64 * LKP];
    __shared__ uint32_t Vs[64 * LVP];

    const int q0   = blockIdx.x * 128;
    const int h    = blockIdx.y;
    const int b    = blockIdx.z;
    const int tid  = threadIdx.x;
    const int lane = tid & 31;
    const int w    = tid >> 5;
    const int g    = lane >> 2;
    const int t    = lane & 3;

    uint32_t af[4][4];
    {
        const int r0 = b * NQ + q0 + w * 16 + g;
        const int r1 = r0 + 8;
        const float sc = 0.17677669529663687f;
        const float* Q0 = &QK[(size_t)r0 * 512 + h * 32];
        const float* Q1 = &QK[(size_t)r1 * 512 + h * 32];
#pragma unroll
        for (int ks = 0; ks < 4; ks++) {
            af[ks][0] = f2tf(Q0[ks * 8 + t] * sc);
            af[ks][1] = f2tf(Q1[ks * 8 + t] * sc);
            af[ks][2] = f2tf(Q0[ks * 8 + t + 4] * sc);
            af[ks][3] = f2tf(Q1[ks * 8 + t + 4] * sc);
        }
    }

    float oc[4][4];
#pragma unroll
    for (int i = 0; i < 4; i++)
#pragma unroll
        for (int j = 0; j < 4; j++) oc[i][j] = 0.f;
    float m0r = -1e30f, m1r = -1e30f, l0 = 0.f, l1 = 0.f;

    const int lrow = tid >> 2;
    const int lcg  = (tid & 3) * 8;
    const unsigned F = 0xffffffffu;

    for (int t0 = 0; t0 < NQ; t0 += 64) {
        __syncthreads();
        {
            const float* kp = &QK[(size_t)(b * NQ + t0 + lrow) * 512 + 256 + h * 32 + lcg];
            float4 k0 = *reinterpret_cast<const float4*>(kp);
            float4 k1 = *reinterpret_cast<const float4*>(kp + 4);
            *reinterpret_cast<uint4*>(&Ks[lrow * LKP + lcg]) =
                make_uint4(f2tf(k0.x), f2tf(k0.y), f2tf(k0.z), f2tf(k0.w));
            *reinterpret_cast<uint4*>(&Ks[lrow * LKP + lcg + 4]) =
                make_uint4(f2tf(k1.x), f2tf(k1.y), f2tf(k1.z), f2tf(k1.w));
            const float* vp = &V[(size_t)(b * NQ + t0 + lrow) * 256 + h * 32 + lcg];
            float4 v0 = *reinterpret_cast<const float4*>(vp);
            float4 v1 = *reinterpret_cast<const float4*>(vp + 4);
            *reinterpret_cast<uint4*>(&Vs[lrow * LVP + lcg]) =
                make_uint4(f2tf(v0.x), f2tf(v0.y), f2tf(v0.z), f2tf(v0.w));
            *reinterpret_cast<uint4*>(&Vs[lrow * LVP + lcg + 4]) =
                make_uint4(f2tf(v1.x), f2tf(v1.y), f2tf(v1.z), f2tf(v1.w));
        }
        __syncthreads();

        float sc[8][4];
#pragma unroll
        for (int nt = 0; nt < 8; nt++) {
            sc[nt][0] = sc[nt][1] = sc[nt][2] = sc[nt][3] = 0.f;
            uint32_t bf[4][2];
#pragma unroll
            for (int ks = 0; ks < 4; ks++) {
                const uint32_t* base = &Ks[(nt * 8 + g) * LKP + ks * 8];
                bf[ks][0] = base[t];
                bf[ks][1] = base[t + 4];
            }
#pragma unroll
            for (int ks = 0; ks < 4; ks++) mma_tf32(sc[nt], af[ks], bf[ks]);
        }

        float mt0 = -1e30f, mt1 = -1e30f;
#pragma unroll
        for (int nt = 0; nt < 8; nt++) {
            mt0 = fmaxf(mt0, fmaxf(sc[nt][0], sc[nt][1]));
            mt1 = fmaxf(mt1, fmaxf(sc[nt][2], sc[nt][3]));
        }
        mt0 = fmaxf(mt0, __shfl_xor_sync(F, mt0, 1));
        mt0 = fmaxf(mt0, __shfl_xor_sync(F, mt0, 2));
        mt1 = fmaxf(mt1, __shfl_xor_sync(F, mt1, 1));
        mt1 = fmaxf(mt1, __shfl_xor_sync(F, mt1, 2));
        const float mn0 = fmaxf(m0r, mt0), mn1 = fmaxf(m1r, mt1);
        const float sc0 = __expf(m0r - mn0), sc1 = __expf(m1r - mn1);

        uint32_t pf[8][4];
        float s0 = 0.f, s1 = 0.f;
#pragma unroll
        for (int nt = 0; nt < 8; nt++) {
            float p0 = __expf(sc[nt][0] - mn0);
            float p1 = __expf(sc[nt][1] - mn0);
            float p2 = __expf(sc[nt][2] - mn1);
            float p3 = __expf(sc[nt][3] - mn1);
            s0 += p0 + p1; s1 += p2 + p3;
            pf[nt][0] = f2tf(p0); pf[nt][1] = f2tf(p1);
            pf[nt][2] = f2tf(p2); pf[nt][3] = f2tf(p3);
        }
        s0 += __shfl_xor_sync(F, s0, 1); s0 += __shfl_xor_sync(F, s0, 2);
        s1 += __shfl_xor_sync(F, s1, 1); s1 += __shfl_xor_sync(F, s1, 2);
        l0 = l0 * sc0 + s0;
        l1 = l1 * sc1 + s1;
        m0r = mn0; m1r = mn1;
#pragma unroll
        for (int nt = 0; nt < 4; nt++) {
            oc[nt][0] *= sc0; oc[nt][1] *= sc0;
            oc[nt][2] *= sc1; oc[nt][3] *= sc1;
        }

        const int src0 = (lane & ~3) | (t >> 1);
        const int src1 = src0 + 2;
        const bool odd = (t & 1);
#pragma unroll
        for (int kt = 0; kt < 8; kt++) {
            uint32_t a[4];
            uint32_t x0 = __shfl_sync(F, pf[kt][0], src0);
            uint32_t x1 = __shfl_sync(F, pf[kt][1], src0);
            a[0] = odd ? x1 : x0;
            uint32_t x2 = __shfl_sync(F, pf[kt][2], src0);
            uint32_t x3 = __shfl_sync(F, pf[kt][3], src0);
            a[1] = odd ? x3 : x2;
            x0 = __shfl_sync(F, pf[kt][0], src1);
            x1 = __shfl_sync(F, pf[kt][1], src1);
            a[2] = odd ? x1 : x0;
            x2 = __shfl_sync(F, pf[kt][2], src1);
            x3 = __shfl_sync(F, pf[kt][3], src1);
            a[3] = odd ? x3 : x2;
#pragma unroll
            for (int nt = 0; nt < 4; nt++) {
                uint32_t bf[2];
                bf[0] = Vs[(kt * 8 + t) * LVP + nt * 8 + g];
                bf[1] = Vs[(kt * 8 + t + 4) * LVP + nt * 8 + g];
                mma_tf32(oc[nt], a, bf);
            }
        }
    }

    const float inv0 = 1.f / l0, inv1 = 1.f / l1;
    const int r0 = b * NQ + q0 + w * 16 + g;
#pragma unroll
    for (int nt = 0; nt < 4; nt++) {
        const int col = h * 32 + nt * 8 + t * 2;
        *reinterpret_cast<float2*>(&O[(size_t)r0 * 256 + col]) =
            make_float2(oc[nt][0] * inv0, oc[nt][1] * inv0);
        *reinterpret_cast<float2*>(&O[(size_t)(r0 + 8) * 256 + col]) =
            make_float2(oc[nt][2] * inv1, oc[nt][3] * inv1);
    }
}

// ------------------------- residual + LayerNorm -------------------------
__global__ void add_ln_kernel(const float* __restrict__ x, const float* __restrict__ r,
                              const float* __restrict__ w, const float* __restrict__ b,
                              float* __restrict__ out) {
    const int row = blockIdx.x;
    const int t = threadIdx.x;
    float v = x[(size_t)row * D + t] + r[(size_t)row * D + t];

    __shared__ float red[8];
    __shared__ float sh_mean, sh_rstd;
    float s = v;
#pragma unroll
    for (int o = 16; o; o >>= 1) s += __shfl_xor_sync(0xffffffffu, s, o);
    if ((t & 31) == 0) red[t >> 5] = s;
    __syncthreads();
    if (t < 32) {
        float z = (t < 8) ? red[t] : 0.f;
#pragma unroll
        for (int o = 4; o; o >>= 1) z += __shfl_xor_sync(0xffffffffu, z, o);
        if (t == 0) sh_mean = z * (1.f / D);
    }
    __syncthreads();
    float m = sh_mean;
    float d = v - m;
    float sq = d * d;
#pragma unroll
    for (int o = 16; o; o >>= 1) sq += __shfl_xor_sync(0xffffffffu, sq, o);
    __syncthreads();
    if ((t & 31) == 0) red[t >> 5] = sq;
    __syncthreads();
    if (t < 32) {
        float z = (t < 8) ? red[t] : 0.f;
#pragma unroll
        for (int o = 4; o; o >>= 1) z += __shfl_xor_sync(0xffffffffu, z, o);
        if (t == 0) sh_rstd = rsqrtf(z * (1.f / D) + 1e-5f);
    }
    __syncthreads();
    out[(size_t)row * D + t] = d * sh_rstd * w[t] + b[t];
}

// ------------------------- MSDA sampling -------------------------
__global__ void msda_kernel(const float* __restrict__ val, const float* __restrict__ off,
                            const float* __restrict__ aw, const float* __restrict__ ref,
                            const int* __restrict__ lsi, float* __restrict__ out) {
    const int warp = (blockIdx.x * blockDim.x + threadIdx.x) >> 5;
    const int lane = threadIdx.x & 31;
    if (warp >= BS * NQ * NH) return;
    const int h  = warp % NH;
    const int bq = warp / NH;
    const int b  = bq / NQ;
    const int base = lsi[0];

    const float rx = ref[bq * 2 + 0] * (float)W_BEV - 0.5f;
    const float ry = ref[bq * 2 + 1] * (float)H_BEV - 0.5f;

    float a0 = aw[bq * (NH * NP) + h * NP + 0];
    float a1 = aw[bq * (NH * NP) + h * NP + 1];
    float a2 = aw[bq * (NH * NP) + h * NP + 2];
    float a3 = aw[bq * (NH * NP) + h * NP + 3];
    float mx = fmaxf(fmaxf(a0, a1), fmaxf(a2, a3));
    float e0 = __expf(a0 - mx), e1 = __expf(a1 - mx), e2 = __expf(a2 - mx), e3 = __expf(a3 - mx);
    float inv = 1.f / (e0 + e1 + e2 + e3);
    float ap[4] = {e0 * inv, e1 * inv, e2 * inv, e3 * inv};

    float accv = 0.f;
#pragma unroll
    for (int p = 0; p < NP; p++) {
        float ox = off[bq * (NH * NP * 2) + (h * NP + p) * 2 + 0];
        float oy = off[bq * (NH * NP * 2) + (h * NP + p) * 2 + 1];
        float x = rx + ox, y = ry + oy;
        float x0f = floorf(x), y0f = floorf(y);
        int x0 = (int)x0f, y0 = (int)y0f;
        float fx = x - x0f, fy = y - y0f;
        float wgt[4] = {(1.f - fx) * (1.f - fy), fx * (1.f - fy), (1.f - fx) * fy, fx * fy};
        int xs[4] = {x0, x0 + 1, x0, x0 + 1};
        int ys[4] = {y0, y0, y0 + 1, y0 + 1};
#pragma unroll
        for (int c = 0; c < 4; c++) {
            int xi = xs[c], yi = ys[c];
            if (xi >= 0 && xi < W_BEV && yi >= 0 && yi < H_BEV) {
                float vv = val[((size_t)(b * NV + base + yi * W_BEV + xi)) * D + h * DH + lane];
                accv += ap[p] * wgt[c] * vv;
            }
        }
    }
    out[(size_t)bq * D + h * DH + lane] = accv;
}

// ------------------------- refs tail -------------------------
__global__ void copy_refs_kernel(const float* __restrict__ ref, float* __restrict__ out) {
    int i = blockIdx.x * blockDim.x + threadIdx.x;
    const int n1 = BS * NQ * 2;
    if (i < LNUM * n1) out[i] = ref[i % n1];
}

// ------------------------- launch -------------------------
extern "C" void kernel_launch(void* const* d_in, const int* in_sizes, int n_in,
                              void* d_out, int out_size) {
    const float* query    = (const float*)d_in[0];
    const float* qpos     = (const float*)d_in[1];
    const float* ref      = (const float*)d_in[2];
    const float* src      = (const float*)d_in[3];
    const int*   lsi      = (const int*)d_in[5];
    const float* sa_in_w  = (const float*)d_in[6];
    const float* sa_in_b  = (const float*)d_in[7];
    const float* sa_out_w = (const float*)d_in[8];
    const float* sa_out_b = (const float*)d_in[9];
    const float* ca_off_w = (const float*)d_in[10];
    const float* ca_off_b = (const float*)d_in[11];
    const float* ca_aw_w  = (const float*)d_in[12];
    const float* ca_aw_b  = (const float*)d_in[13];
    const float* ca_val_w = (const float*)d_in[14];
    const float* ca_val_b = (const float*)d_in[15];
    const float* ca_out_w = (const float*)d_in[16];
    const float* ca_out_b = (const float*)d_in[17];
    const float* n1_w     = (const float*)d_in[18];
    const float* n1_b     = (const float*)d_in[19];
    const float* n2_w     = (const float*)d_in[20];
    const float* n2_b     = (const float*)d_in[21];
    const float* n3_w     = (const float*)d_in[22];
    const float* n3_b     = (const float*)d_in[23];
    const float* ff1_w    = (const float*)d_in[24];
    const float* ff1_b    = (const float*)d_in[25];
    const float* ff2_w    = (const float*)d_in[26];
    const float* ff2_b    = (const float*)d_in[27];

    float *xbuf, *qkb, *vb, *sab, *tmpb, *t1b, *t2b, *valb, *offb, *awb, *cab, *ffnb;
    cudaGetSymbolAddress((void**)&xbuf, g_xbuf);
    cudaGetSymbolAddress((void**)&qkb,  g_qk);
    cudaGetSymbolAddress((void**)&vb,   g_v);
    cudaGetSymbolAddress((void**)&sab,  g_sa);
    cudaGetSymbolAddress((void**)&tmpb, g_tmp);
    cudaGetSymbolAddress((void**)&t1b,  g_t1);
    cudaGetSymbolAddress((void**)&t2b,  g_t2);
    cudaGetSymbolAddress((void**)&valb, g_val);
    cudaGetSymbolAddress((void**)&offb, g_off);
    cudaGetSymbolAddress((void**)&awb,  g_aw);
    cudaGetSymbolAddress((void**)&cab,  g_ca);
    cudaGetSymbolAddress((void**)&ffnb, g_ffn);

    float* out_hs = (float*)d_out;
    const int NTOK = MROWS * D;

    for (int l = 0; l < LNUM; l++) {
        const float* prev = (l == 0) ? query : out_hs + (size_t)(l - 1) * NTOK;
        float* cur = out_hs + (size_t)l * NTOK;

        // --- self attention ---
        add_kernel<<<(NTOK + 255) / 256, 256>>>(prev, qpos, xbuf, NTOK);
        gemm_tc<false><<<dim3(512 / 128, MROWS / 128), 256>>>(
            xbuf, sa_in_w + (size_t)l * 3 * D * D, sa_in_b + (size_t)l * 3 * D,
            qkb, MROWS, 512, D);
        gemm_tc<false><<<dim3(D / 128, MROWS / 128), 256>>>(
            prev, sa_in_w + (size_t)l * 3 * D * D + (size_t)2 * D * D,
            sa_in_b + (size_t)l * 3 * D + 2 * D, vb, MROWS, D, D);
        attn_tc_kernel<<<dim3(NQ / 128, NH, BS), 256>>>(qkb, vb, sab);
        gemm_tc<false><<<dim3(D / 128, MROWS / 128), 256>>>(
            sab, sa_out_w + (size_t)l * D * D, sa_out_b + (size_t)l * D, tmpb, MROWS, D, D);
        add_ln_kernel<<<MROWS, 256>>>(tmpb, prev, n2_w + (size_t)l * D, n2_b + (size_t)l * D, t1b);

        // --- deformable cross attention ---
        add_kernel<<<(NTOK + 255) / 256, 256>>>(t1b, qpos, xbuf, NTOK);
        gemm_tc<false><<<dim3(D / 128, (BS * NV + 127) / 128), 256>>>(
            src, ca_val_w + (size_t)l * D * D, ca_val_b + (size_t)l * D, valb, BS * NV, D, D);
        gemm_bias_kernel<false><<<dim3(1, 64), 256>>>(
            xbuf, ca_off_w + (size_t)l * NH * NP * 2 * D, ca_off_b + (size_t)l * NH * NP * 2,
            offb, MROWS, NH * NP * 2, D);
        gemm_bias_kernel<false><<<dim3(1, 64), 256>>>(
            xbuf, ca_aw_w + (size_t)l * NH * NP * D, ca_aw_b + (size_t)l * NH * NP,
            awb, MROWS, NH * NP, D);
        msda_kernel<<<(BS * NQ * NH + 7) / 8, 256>>>(valb, offb, awb, ref, lsi, cab);
        gemm_tc<false><<<dim3(D / 128, MROWS / 128), 256>>>(
            cab, ca_out_w + (size_t)l * D * D, ca_out_b + (size_t)l * D, tmpb, MROWS, D, D);
        add_ln_kernel<<<MROWS, 256>>>(tmpb, t1b, n1_w + (size_t)l * D, n1_b + (size_t)l * D, t2b);

        // --- FFN ---
        gemm_tc<true><<<dim3(DFF / 128, MROWS / 128), 256>>>(
            t2b, ff1_w + (size_t)l * DFF * D, ff1_b + (size_t)l * DFF, ffnb, MROWS, DFF, D);
        gemm_tc<false><<<dim3(D / 128, MROWS / 128), 256>>>(
            ffnb, ff2_w + (size_t)l * D * DFF, ff2_b + (size_t)l * D, tmpb, MROWS, D, DFF);
        add_ln_kernel<<<MROWS, 256>>>(tmpb, t2b, n3_w + (size_t)l * D, n3_b + (size_t)l * D, cur);
    }

    const int hs_total = LNUM * MROWS * D;
    if (out_size > hs_total) {
        copy_refs_kernel<<<(LNUM * BS * NQ * 2 + 255) / 256, 256>>>(ref, out_hs + hs_total);
    }
}

// round 6
// speedup vs baseline: 3.9065x; 1.1197x over previous
#include <cuda_runtime.h>
#include <cuda_bf16.h>
#include <cstdint>

#define BS   4
#define NQ   1024
#define D    256
#define NH   8
#define NP   4
#define LNUM 6
#define DFF  1024
#define H_BEV 200
#define W_BEV 150
#define NV   (H_BEV * W_BEV)
#define DH   32
#define MROWS (BS * NQ)          // 4096

// ------------------------- scratch (static device globals) -------------------------
__device__ float g_xbuf[MROWS * D];
__device__ float g_qk[MROWS * 512];
__device__ float g_v[MROWS * D];
__device__ float g_sa[MROWS * D];
__device__ float g_tmp[MROWS * D];
__device__ float g_t1[MROWS * D];
__device__ float g_t2[MROWS * D];
__device__ float g_val[(size_t)LNUM * BS * NV * D];   // all 6 layers' value projections
__device__ float g_off[MROWS * NH * NP * 2];
__device__ float g_aw[MROWS * NH * NP];
__device__ float g_ca[MROWS * D];
__device__ float g_ffn[MROWS * DFF];

// ------------------------- stream/event aux (created at program init) -------------------------
struct Aux {
    cudaStream_t sB = 0;
    cudaEvent_t fork = 0;
    cudaEvent_t val_ev[LNUM] = {};
    bool ok = false;
    Aux() {
        if (cudaStreamCreateWithFlags(&sB, cudaStreamNonBlocking) != cudaSuccess) return;
        if (cudaEventCreateWithFlags(&fork, cudaEventDisableTiming) != cudaSuccess) return;
        for (int i = 0; i < LNUM; i++)
            if (cudaEventCreateWithFlags(&val_ev[i], cudaEventDisableTiming) != cudaSuccess) return;
        ok = true;
    }
};
static Aux g_aux;

// ------------------------- helpers -------------------------
__device__ __forceinline__ uint32_t f2tf(float f) {
    uint32_t r;
    asm("cvt.rna.tf32.f32 %0, %1;" : "=r"(r) : "f"(f));
    return r;
}
__device__ __forceinline__ void mma_tf32(float* c, const uint32_t* a, const uint32_t* b) {
    asm volatile("mma.sync.aligned.m16n8k8.row.col.f32.tf32.tf32.f32 "
                 "{%0,%1,%2,%3},{%4,%5,%6,%7},{%8,%9},{%0,%1,%2,%3};"
                 : "+f"(c[0]), "+f"(c[1]), "+f"(c[2]), "+f"(c[3])
                 : "r"(a[0]), "r"(a[1]), "r"(a[2]), "r"(a[3]), "r"(b[0]), "r"(b[1]));
}
__device__ __forceinline__ void cp16(uint32_t smem_addr, const void* gptr, int src_bytes) {
    asm volatile("cp.async.ca.shared.global [%0], [%1], 16, %2;\n"
                 :: "r"(smem_addr), "l"(gptr), "r"(src_bytes));
}
__device__ __forceinline__ void cp_commit() { asm volatile("cp.async.commit_group;\n"); }
template <int N>
__device__ __forceinline__ void cp_wait() { asm volatile("cp.async.wait_group %0;\n" :: "n"(N)); }

// ------------------------- elementwise add -------------------------
__global__ void add_kernel(const float* __restrict__ a, const float* __restrict__ b,
                           float* __restrict__ o, int n) {
    int i = blockIdx.x * blockDim.x + threadIdx.x;
    if (i < n) o[i] = a[i] + b[i];
}

// ------------------------- tf32 tensor-core GEMM (templated tile) -------------------------
// C[M,N] = A[M,K] @ W[N,K]^T + bias.  BK=16, 3-stage cp.async pipeline, 8 warps.
template <int BM, int BN, bool RELU>
__global__ __launch_bounds__(256)
void gemm_tc(const float* __restrict__ A, const float* __restrict__ W,
             const float* __restrict__ bias, float* __restrict__ C,
             int M, int N, int K) {
    constexpr int ST  = 3;
    constexpr int WMC = BM / 32;          // warps along M
    constexpr int WNC = 8 / WMC;          // warps along N
    constexpr int WCOLS = BN / WNC;       // cols per warp
    constexpr int NT  = WCOLS / 8;        // n8 tiles per warp

    __shared__ uint32_t As[ST][BM * 16];
    __shared__ uint32_t Bs[ST][BN * 16];

    const int tid  = threadIdx.x;
    const int lane = tid & 31;
    const int wid  = tid >> 5;
    const int wm   = wid % WMC;
    const int wn   = wid / WMC;
    const int g    = lane >> 2;
    const int t    = lane & 3;
    const int m0   = blockIdx.y * BM;
    const int n0   = blockIdx.x * BN;

    auto load_stage = [&](int s, int kt) {
        const int k0 = kt * 16;
        uint32_t sa = (uint32_t)__cvta_generic_to_shared(&As[s][0]);
        uint32_t sb = (uint32_t)__cvta_generic_to_shared(&Bs[s][0]);
#pragma unroll
        for (int c = tid; c < (BM + BN) * 4; c += 256) {
            int row = c >> 2, cg = (c & 3) * 4;
            if (c < BM * 4) {
                int gm = m0 + row;
                cp16(sa + (row * 16 + cg) * 4, &A[(size_t)gm * K + k0 + cg], gm < M ? 16 : 0);
            } else {
                int r = row - BM;
                cp16(sb + (r * 16 + cg) * 4, &W[(size_t)(n0 + r) * K + k0 + cg], 16);
            }
        }
        cp_commit();
    };

    float acc[2][NT][4];
#pragma unroll
    for (int i = 0; i < 2; i++)
#pragma unroll
        for (int j = 0; j < NT; j++)
#pragma unroll
            for (int c = 0; c < 4; c++) acc[i][j][c] = 0.f;

    const int KT = K / 16;
    load_stage(0, 0);
    if (KT > 1) load_stage(1 % ST, 1);

    for (int kt = 0; kt < KT; kt++) {
        cp_wait<1>();
        __syncthreads();
        if (kt + 2 < KT) load_stage((kt + 2) % ST, kt + 2);
        const int s = kt % ST;

        uint32_t afA[2][4], afB[2][4];
#pragma unroll
        for (int mt = 0; mt < 2; mt++) {
            const int row = wm * 32 + mt * 16 + g;
            uint4 ar0 = *reinterpret_cast<const uint4*>(&As[s][row * 16 + t * 4]);
            uint4 ar1 = *reinterpret_cast<const uint4*>(&As[s][(row + 8) * 16 + t * 4]);
            afA[mt][0] = ar0.x; afA[mt][1] = ar1.x; afA[mt][2] = ar0.y; afA[mt][3] = ar1.y;
            afB[mt][0] = ar0.z; afB[mt][1] = ar1.z; afB[mt][2] = ar0.w; afB[mt][3] = ar1.w;
        }
#pragma unroll
        for (int nt = 0; nt < NT; nt++) {
            uint4 br = *reinterpret_cast<const uint4*>(&Bs[s][(wn * WCOLS + nt * 8 + g) * 16 + t * 4]);
            uint32_t bA[2] = {br.x, br.y};
            uint32_t bB[2] = {br.z, br.w};
#pragma unroll
            for (int mt = 0; mt < 2; mt++) {
                mma_tf32(acc[mt][nt], afA[mt], bA);
                mma_tf32(acc[mt][nt], afB[mt], bB);
            }
        }
    }

#pragma unroll
    for (int nt = 0; nt < NT; nt++) {
        const int cb = n0 + wn * WCOLS + nt * 8 + t * 2;
        const float bv0 = bias[cb], bv1 = bias[cb + 1];
#pragma unroll
        for (int mt = 0; mt < 2; mt++) {
            int r0 = m0 + wm * 32 + mt * 16 + g;
            float o0 = acc[mt][nt][0] + bv0, o1 = acc[mt][nt][1] + bv1;
            float o2 = acc[mt][nt][2] + bv0, o3 = acc[mt][nt][3] + bv1;
            if (RELU) {
                o0 = fmaxf(o0, 0.f); o1 = fmaxf(o1, 0.f);
                o2 = fmaxf(o2, 0.f); o3 = fmaxf(o3, 0.f);
            }
            if (r0 < M)
                *reinterpret_cast<float2*>(&C[(size_t)r0 * N + cb]) = make_float2(o0, o1);
            if (r0 + 8 < M)
                *reinterpret_cast<float2*>(&C[(size_t)(r0 + 8) * N + cb]) = make_float2(o2, o3);
        }
    }
}

// ------------------------- small-N GEMM (64x64 tile) -------------------------
template <bool RELU>
__global__ void gemm_bias_kernel(const float* __restrict__ A, const float* __restrict__ W,
                                 const float* __restrict__ bias, float* __restrict__ C,
                                 int M, int N, int K) {
    __shared__ float As[16][65];
    __shared__ float Bs[16][65];
    const int tid = threadIdx.x;
    const int tx = tid & 15, ty = tid >> 4;
    const int m0 = blockIdx.y * 64, n0 = blockIdx.x * 64;
    const int lr = tid >> 2;
    const int lc = (tid & 3) * 4;

    float acc[4][4];
#pragma unroll
    for (int i = 0; i < 4; i++)
#pragma unroll
        for (int j = 0; j < 4; j++) acc[i][j] = 0.f;

    for (int k0 = 0; k0 < K; k0 += 16) {
        {
            int gm = m0 + lr;
            float4 v = make_float4(0.f, 0.f, 0.f, 0.f);
            if (gm < M) v = *reinterpret_cast<const float4*>(&A[(size_t)gm * K + k0 + lc]);
            As[lc + 0][lr] = v.x; As[lc + 1][lr] = v.y; As[lc + 2][lr] = v.z; As[lc + 3][lr] = v.w;
            int gn = n0 + lr;
            float4 w4 = make_float4(0.f, 0.f, 0.f, 0.f);
            if (gn < N) w4 = *reinterpret_cast<const float4*>(&W[(size_t)gn * K + k0 + lc]);
            Bs[lc + 0][lr] = w4.x; Bs[lc + 1][lr] = w4.y; Bs[lc + 2][lr] = w4.z; Bs[lc + 3][lr] = w4.w;
        }
        __syncthreads();
#pragma unroll
        for (int kk = 0; kk < 16; kk++) {
            float a[4], b[4];
#pragma unroll
            for (int i = 0; i < 4; i++) a[i] = As[kk][ty * 4 + i];
#pragma unroll
            for (int j = 0; j < 4; j++) b[j] = Bs[kk][tx * 4 + j];
#pragma unroll
            for (int i = 0; i < 4; i++)
#pragma unroll
                for (int j = 0; j < 4; j++) acc[i][j] += a[i] * b[j];
        }
        __syncthreads();
    }
#pragma unroll
    for (int i = 0; i < 4; i++) {
        int gm = m0 + ty * 4 + i;
        if (gm >= M) continue;
#pragma unroll
        for (int j = 0; j < 4; j++) {
            int gn = n0 + tx * 4 + j;
            if (gn >= N) continue;
            float v = acc[i][j] + bias[gn];
            if (RELU) v = fmaxf(v, 0.f);
            C[(size_t)gm * N + gn] = v;
        }
    }
}

// ------------------------- tensor-core flash attention -------------------------
#define LKP 36
#define LVP 40
__global__ __launch_bounds__(256)
void attn_tc_kernel(const float* __restrict__ QK, const float* __restrict__ V,
                    float* __restrict__ O) {
    __shared__ uint32_t Ks[64 * LKP];
    __shared__ uint32_t Vs[64 * LVP];

    const int q0   = blockIdx.x * 128;
    const int h    = blockIdx.y;
    const int b    = blockIdx.z;
    const int tid  = threadIdx.x;
    const int lane = tid & 31;
    const int w    = tid >> 5;
    const int g    = lane >> 2;
    const int t    = lane & 3;

    uint32_t af[4][4];
    {
        const int r0 = b * NQ + q0 + w * 16 + g;
        const int r1 = r0 + 8;
        const float sc = 0.17677669529663687f;
        const float* Q0 = &QK[(size_t)r0 * 512 + h * 32];
        const float* Q1 = &QK[(size_t)r1 * 512 + h * 32];
#pragma unroll
        for (int ks = 0; ks < 4; ks++) {
            af[ks][0] = f2tf(Q0[ks * 8 + t] * sc);
            af[ks][1] = f2tf(Q1[ks * 8 + t] * sc);
            af[ks][2] = f2tf(Q0[ks * 8 + t + 4] * sc);
            af[ks][3] = f2tf(Q1[ks * 8 + t + 4] * sc);
        }
    }

    float oc[4][4];
#pragma unroll
    for (int i = 0; i < 4; i++)
#pragma unroll
        for (int j = 0; j < 4; j++) oc[i][j] = 0.f;
    float m0r = -1e30f, m1r = -1e30f, l0 = 0.f, l1 = 0.f;

    const int lrow = tid >> 2;
    const int lcg  = (tid & 3) * 8;
    const unsigned F = 0xffffffffu;

    for (int t0 = 0; t0 < NQ; t0 += 64) {
        __syncthreads();
        {
            const float* kp = &QK[(size_t)(b * NQ + t0 + lrow) * 512 + 256 + h * 32 + lcg];
            float4 k0 = *reinterpret_cast<const float4*>(kp);
            float4 k1 = *reinterpret_cast<const float4*>(kp + 4);
            *reinterpret_cast<uint4*>(&Ks[lrow * LKP + lcg]) =
                make_uint4(f2tf(k0.x), f2tf(k0.y), f2tf(k0.z), f2tf(k0.w));
            *reinterpret_cast<uint4*>(&Ks[lrow * LKP + lcg + 4]) =
                make_uint4(f2tf(k1.x), f2tf(k1.y), f2tf(k1.z), f2tf(k1.w));
            const float* vp = &V[(size_t)(b * NQ + t0 + lrow) * 256 + h * 32 + lcg];
            float4 v0 = *reinterpret_cast<const float4*>(vp);
            float4 v1 = *reinterpret_cast<const float4*>(vp + 4);
            *reinterpret_cast<uint4*>(&Vs[lrow * LVP + lcg]) =
                make_uint4(f2tf(v0.x), f2tf(v0.y), f2tf(v0.z), f2tf(v0.w));
            *reinterpret_cast<uint4*>(&Vs[lrow * LVP + lcg + 4]) =
                make_uint4(f2tf(v1.x), f2tf(v1.y), f2tf(v1.z), f2tf(v1.w));
        }
        __syncthreads();

        float sc[8][4];
#pragma unroll
        for (int nt = 0; nt < 8; nt++) {
            sc[nt][0] = sc[nt][1] = sc[nt][2] = sc[nt][3] = 0.f;
            uint32_t bf[4][2];
#pragma unroll
            for (int ks = 0; ks < 4; ks++) {
                const uint32_t* base = &Ks[(nt * 8 + g) * LKP + ks * 8];
                bf[ks][0] = base[t];
                bf[ks][1] = base[t + 4];
            }
#pragma unroll
            for (int ks = 0; ks < 4; ks++) mma_tf32(sc[nt], af[ks], bf[ks]);
        }

        float mt0 = -1e30f, mt1 = -1e30f;
#pragma unroll
        for (int nt = 0; nt < 8; nt++) {
            mt0 = fmaxf(mt0, fmaxf(sc[nt][0], sc[nt][1]));
            mt1 = fmaxf(mt1, fmaxf(sc[nt][2], sc[nt][3]));
        }
        mt0 = fmaxf(mt0, __shfl_xor_sync(F, mt0, 1));
        mt0 = fmaxf(mt0, __shfl_xor_sync(F, mt0, 2));
        mt1 = fmaxf(mt1, __shfl_xor_sync(F, mt1, 1));
        mt1 = fmaxf(mt1, __shfl_xor_sync(F, mt1, 2));
        const float mn0 = fmaxf(m0r, mt0), mn1 = fmaxf(m1r, mt1);
        const float sc0 = __expf(m0r - mn0), sc1 = __expf(m1r - mn1);

        uint32_t pf[8][4];
        float s0 = 0.f, s1 = 0.f;
#pragma unroll
        for (int nt = 0; nt < 8; nt++) {
            float p0 = __expf(sc[nt][0] - mn0);
            float p1 = __expf(sc[nt][1] - mn0);
            float p2 = __expf(sc[nt][2] - mn1);
            float p3 = __expf(sc[nt][3] - mn1);
            s0 += p0 + p1; s1 += p2 + p3;
            pf[nt][0] = f2tf(p0); pf[nt][1] = f2tf(p1);
            pf[nt][2] = f2tf(p2); pf[nt][3] = f2tf(p3);
        }
        s0 += __shfl_xor_sync(F, s0, 1); s0 += __shfl_xor_sync(F, s0, 2);
        s1 += __shfl_xor_sync(F, s1, 1); s1 += __shfl_xor_sync(F, s1, 2);
        l0 = l0 * sc0 + s0;
        l1 = l1 * sc1 + s1;
        m0r = mn0; m1r = mn1;
#pragma unroll
        for (int nt = 0; nt < 4; nt++) {
            oc[nt][0] *= sc0; oc[nt][1] *= sc0;
            oc[nt][2] *= sc1; oc[nt][3] *= sc1;
        }

        const int src0 = (lane & ~3) | (t >> 1);
        const int src1 = src0 + 2;
        const bool odd = (t & 1);
#pragma unroll
        for (int kt = 0; kt < 8; kt++) {
            uint32_t a[4];
            uint32_t x0 = __shfl_sync(F, pf[kt][0], src0);
            uint32_t x1 = __shfl_sync(F, pf[kt][1], src0);
            a[0] = odd ? x1 : x0;
            uint32_t x2 = __shfl_sync(F, pf[kt][2], src0);
            uint32_t x3 = __shfl_sync(F, pf[kt][3], src0);
            a[1] = odd ? x3 : x2;
            x0 = __shfl_sync(F, pf[kt][0], src1);
            x1 = __shfl_sync(F, pf[kt][1], src1);
            a[2] = odd ? x1 : x0;
            x2 = __shfl_sync(F, pf[kt][2], src1);
            x3 = __shfl_sync(F, pf[kt][3], src1);
            a[3] = odd ? x3 : x2;
#pragma unroll
            for (int nt = 0; nt < 4; nt++) {
                uint32_t bf[2];
                bf[0] = Vs[(kt * 8 + t) * LVP + nt * 8 + g];
                bf[1] = Vs[(kt * 8 + t + 4) * LVP + nt * 8 + g];
                mma_tf32(oc[nt], a, bf);
            }
        }
    }

    const float inv0 = 1.f / l0, inv1 = 1.f / l1;
    const int r0 = b * NQ + q0 + w * 16 + g;
#pragma unroll
    for (int nt = 0; nt < 4; nt++) {
        const int col = h * 32 + nt * 8 + t * 2;
        *reinterpret_cast<float2*>(&O[(size_t)r0 * 256 + col]) =
            make_float2(oc[nt][0] * inv0, oc[nt][1] * inv0);
        *reinterpret_cast<float2*>(&O[(size_t)(r0 + 8) * 256 + col]) =
            make_float2(oc[nt][2] * inv1, oc[nt][3] * inv1);
    }
}

// ------------------------- residual + LayerNorm -------------------------
__global__ void add_ln_kernel(const float* __restrict__ x, const float* __restrict__ r,
                              const float* __restrict__ w, const float* __restrict__ b,
                              float* __restrict__ out) {
    const int row = blockIdx.x;
    const int t = threadIdx.x;
    float v = x[(size_t)row * D + t] + r[(size_t)row * D + t];

    __shared__ float red[8];
    __shared__ float sh_mean, sh_rstd;
    float s = v;
#pragma unroll
    for (int o = 16; o; o >>= 1) s += __shfl_xor_sync(0xffffffffu, s, o);
    if ((t & 31) == 0) red[t >> 5] = s;
    __syncthreads();
    if (t < 32) {
        float z = (t < 8) ? red[t] : 0.f;
#pragma unroll
        for (int o = 4; o; o >>= 1) z += __shfl_xor_sync(0xffffffffu, z, o);
        if (t == 0) sh_mean = z * (1.f / D);
    }
    __syncthreads();
    float m = sh_mean;
    float d = v - m;
    float sq = d * d;
#pragma unroll
    for (int o = 16; o; o >>= 1) sq += __shfl_xor_sync(0xffffffffu, sq, o);
    __syncthreads();
    if ((t & 31) == 0) red[t >> 5] = sq;
    __syncthreads();
    if (t < 32) {
        float z = (t < 8) ? red[t] : 0.f;
#pragma unroll
        for (int o = 4; o; o >>= 1) z += __shfl_xor_sync(0xffffffffu, z, o);
        if (t == 0) sh_rstd = rsqrtf(z * (1.f / D) + 1e-5f);
    }
    __syncthreads();
    out[(size_t)row * D + t] = d * sh_rstd * w[t] + b[t];
}

// ------------------------- MSDA sampling -------------------------
__global__ void msda_kernel(const float* __restrict__ val, const float* __restrict__ off,
                            const float* __restrict__ aw, const float* __restrict__ ref,
                            const int* __restrict__ lsi, float* __restrict__ out) {
    const int warp = (blockIdx.x * blockDim.x + threadIdx.x) >> 5;
    const int lane = threadIdx.x & 31;
    if (warp >= BS * NQ * NH) return;
    const int h  = warp % NH;
    const int bq = warp / NH;
    const int b  = bq / NQ;
    const int base = lsi[0];

    const float rx = ref[bq * 2 + 0] * (float)W_BEV - 0.5f;
    const float ry = ref[bq * 2 + 1] * (float)H_BEV - 0.5f;

    float a0 = aw[bq * (NH * NP) + h * NP + 0];
    float a1 = aw[bq * (NH * NP) + h * NP + 1];
    float a2 = aw[bq * (NH * NP) + h * NP + 2];
    float a3 = aw[bq * (NH * NP) + h * NP + 3];
    float mx = fmaxf(fmaxf(a0, a1), fmaxf(a2, a3));
    float e0 = __expf(a0 - mx), e1 = __expf(a1 - mx), e2 = __expf(a2 - mx), e3 = __expf(a3 - mx);
    float inv = 1.f / (e0 + e1 + e2 + e3);
    float ap[4] = {e0 * inv, e1 * inv, e2 * inv, e3 * inv};

    float accv = 0.f;
#pragma unroll
    for (int p = 0; p < NP; p++) {
        float ox = off[bq * (NH * NP * 2) + (h * NP + p) * 2 + 0];
        float oy = off[bq * (NH * NP * 2) + (h * NP + p) * 2 + 1];
        float x = rx + ox, y = ry + oy;
        float x0f = floorf(x), y0f = floorf(y);
        int x0 = (int)x0f, y0 = (int)y0f;
        float fx = x - x0f, fy = y - y0f;
        float wgt[4] = {(1.f - fx) * (1.f - fy), fx * (1.f - fy), (1.f - fx) * fy, fx * fy};
        int xs[4] = {x0, x0 + 1, x0, x0 + 1};
        int ys[4] = {y0, y0, y0 + 1, y0 + 1};
#pragma unroll
        for (int c = 0; c < 4; c++) {
            int xi = xs[c], yi = ys[c];
            if (xi >= 0 && xi < W_BEV && yi >= 0 && yi < H_BEV) {
                float vv = val[((size_t)(b * NV + base + yi * W_BEV + xi)) * D + h * DH + lane];
                accv += ap[p] * wgt[c] * vv;
            }
        }
    }
    out[(size_t)bq * D + h * DH + lane] = accv;
}

// ------------------------- refs tail -------------------------
__global__ void copy_refs_kernel(const float* __restrict__ ref, float* __restrict__ out) {
    int i = blockIdx.x * blockDim.x + threadIdx.x;
    const int n1 = BS * NQ * 2;
    if (i < LNUM * n1) out[i] = ref[i % n1];
}

// ------------------------- launch -------------------------
extern "C" void kernel_launch(void* const* d_in, const int* in_sizes, int n_in,
                              void* d_out, int out_size) {
    const float* query    = (const float*)d_in[0];
    const float* qpos     = (const float*)d_in[1];
    const float* ref      = (const float*)d_in[2];
    const float* src      = (const float*)d_in[3];
    const int*   lsi      = (const int*)d_in[5];
    const float* sa_in_w  = (const float*)d_in[6];
    const float* sa_in_b  = (const float*)d_in[7];
    const float* sa_out_w = (const float*)d_in[8];
    const float* sa_out_b = (const float*)d_in[9];
    const float* ca_off_w = (const float*)d_in[10];
    const float* ca_off_b = (const float*)d_in[11];
    const float* ca_aw_w  = (const float*)d_in[12];
    const float* ca_aw_b  = (const float*)d_in[13];
    const float* ca_val_w = (const float*)d_in[14];
    const float* ca_val_b = (const float*)d_in[15];
    const float* ca_out_w = (const float*)d_in[16];
    const float* ca_out_b = (const float*)d_in[17];
    const float* n1_w     = (const float*)d_in[18];
    const float* n1_b     = (const float*)d_in[19];
    const float* n2_w     = (const float*)d_in[20];
    const float* n2_b     = (const float*)d_in[21];
    const float* n3_w     = (const float*)d_in[22];
    const float* n3_b     = (const float*)d_in[23];
    const float* ff1_w    = (const float*)d_in[24];
    const float* ff1_b    = (const float*)d_in[25];
    const float* ff2_w    = (const float*)d_in[26];
    const float* ff2_b    = (const float*)d_in[27];

    float *xbuf, *qkb, *vb, *sab, *tmpb, *t1b, *t2b, *valb, *offb, *awb, *cab, *ffnb;
    cudaGetSymbolAddress((void**)&xbuf, g_xbuf);
    cudaGetSymbolAddress((void**)&qkb,  g_qk);
    cudaGetSymbolAddress((void**)&vb,   g_v);
    cudaGetSymbolAddress((void**)&sab,  g_sa);
    cudaGetSymbolAddress((void**)&tmpb, g_tmp);
    cudaGetSymbolAddress((void**)&t1b,  g_t1);
    cudaGetSymbolAddress((void**)&t2b,  g_t2);
    cudaGetSymbolAddress((void**)&valb, g_val);
    cudaGetSymbolAddress((void**)&offb, g_off);
    cudaGetSymbolAddress((void**)&awb,  g_aw);
    cudaGetSymbolAddress((void**)&cab,  g_ca);
    cudaGetSymbolAddress((void**)&ffnb, g_ffn);

    float* out_hs = (float*)d_out;
    const int NTOK = MROWS * D;
    const size_t VAL_STRIDE = (size_t)BS * NV * D;

    const bool use_sB = g_aux.ok;
    cudaStream_t sB = use_sB ? g_aux.sB : 0;

    // ---- fork: all 6 value projections on side stream ----
    if (use_sB) {
        cudaEventRecord(g_aux.fork, 0);
        cudaStreamWaitEvent(sB, g_aux.fork, 0);
    }
    for (int l = 0; l < LNUM; l++) {
        gemm_tc<128, 128, false><<<dim3(D / 128, (BS * NV + 127) / 128), 256, 0, sB>>>(
            src, ca_val_w + (size_t)l * D * D, ca_val_b + (size_t)l * D,
            valb + (size_t)l * VAL_STRIDE, BS * NV, D, D);
        if (use_sB) cudaEventRecord(g_aux.val_ev[l], sB);
    }

    for (int l = 0; l < LNUM; l++) {
        const float* prev = (l == 0) ? query : out_hs + (size_t)(l - 1) * NTOK;
        float* cur = out_hs + (size_t)l * NTOK;

        // --- self attention ---
        add_kernel<<<(NTOK + 255) / 256, 256>>>(prev, qpos, xbuf, NTOK);
        gemm_tc<64, 128, false><<<dim3(512 / 128, MROWS / 64), 256>>>(
            xbuf, sa_in_w + (size_t)l * 3 * D * D, sa_in_b + (size_t)l * 3 * D,
            qkb, MROWS, 512, D);
        gemm_tc<64, 128, false><<<dim3(D / 128, MROWS / 64), 256>>>(
            prev, sa_in_w + (size_t)l * 3 * D * D + (size_t)2 * D * D,
            sa_in_b + (size_t)l * 3 * D + 2 * D, vb, MROWS, D, D);
        attn_tc_kernel<<<dim3(NQ / 128, NH, BS), 256>>>(qkb, vb, sab);
        gemm_tc<64, 128, false><<<dim3(D / 128, MROWS / 64), 256>>>(
            sab, sa_out_w + (size_t)l * D * D, sa_out_b + (size_t)l * D, tmpb, MROWS, D, D);
        add_ln_kernel<<<MROWS, 256>>>(tmpb, prev, n2_w + (size_t)l * D, n2_b + (size_t)l * D, t1b);

        // --- deformable cross attention ---
        add_kernel<<<(NTOK + 255) / 256, 256>>>(t1b, qpos, xbuf, NTOK);
        gemm_bias_kernel<false><<<dim3(1, 64), 256>>>(
            xbuf, ca_off_w + (size_t)l * NH * NP * 2 * D, ca_off_b + (size_t)l * NH * NP * 2,
            offb, MROWS, NH * NP * 2, D);
        gemm_bias_kernel<false><<<dim3(1, 64), 256>>>(
            xbuf, ca_aw_w + (size_t)l * NH * NP * D, ca_aw_b + (size_t)l * NH * NP,
            awb, MROWS, NH * NP, D);
        if (use_sB) cudaStreamWaitEvent(0, g_aux.val_ev[l], 0);
        msda_kernel<<<(BS * NQ * NH + 7) / 8, 256>>>(
            valb + (size_t)l * VAL_STRIDE, offb, awb, ref, lsi, cab);
        gemm_tc<64, 128, false><<<dim3(D / 128, MROWS / 64), 256>>>(
            cab, ca_out_w + (size_t)l * D * D, ca_out_b + (size_t)l * D, tmpb, MROWS, D, D);
        add_ln_kernel<<<MROWS, 256>>>(tmpb, t1b, n1_w + (size_t)l * D, n1_b + (size_t)l * D, t2b);

        // --- FFN ---
        gemm_tc<128, 128, true><<<dim3(DFF / 128, MROWS / 128), 256>>>(
            t2b, ff1_w + (size_t)l * DFF * D, ff1_b + (size_t)l * DFF, ffnb, MROWS, DFF, D);
        gemm_tc<64, 128, false><<<dim3(D / 128, MROWS / 64), 256>>>(
            ffnb, ff2_w + (size_t)l * D * DFF, ff2_b + (size_t)l * D, tmpb, MROWS, D, DFF);
        add_ln_kernel<<<MROWS, 256>>>(tmpb, t2b, n3_w + (size_t)l * D, n3_b + (size_t)l * D, cur);
    }

    const int hs_total = LNUM * MROWS * D;
    if (out_size > hs_total) {
        copy_refs_kernel<<<(LNUM * BS * NQ * 2 + 255) / 256, 256>>>(ref, out_hs + hs_total);
    }
}

// round 7
// speedup vs baseline: 4.3156x; 1.1047x over previous
#include <cuda_runtime.h>
#include <cuda_bf16.h>
#include <cstdint>

#define BS   4
#define NQ   1024
#define D    256
#define NH   8
#define NP   4
#define LNUM 6
#define DFF  1024
#define H_BEV 200
#define W_BEV 150
#define NV   (H_BEV * W_BEV)
#define DH   32
#define MROWS (BS * NQ)          // 4096

// ------------------------- scratch (static device globals) -------------------------
__device__ float g_xbuf[MROWS * D];
__device__ float g_qk[MROWS * 512];
__device__ float g_v[MROWS * D];
__device__ float g_sa[MROWS * D];
__device__ float g_t1[MROWS * D];
__device__ float g_t2[MROWS * D];
__device__ float g_val[(size_t)LNUM * BS * NV * D];
__device__ float g_off[MROWS * NH * NP * 2];
__device__ float g_aw[MROWS * NH * NP];
__device__ float g_ca[MROWS * D];
__device__ float g_ffn[MROWS * DFF];

// ------------------------- stream/event aux -------------------------
struct Aux {
    cudaStream_t sB = 0;
    cudaEvent_t fork = 0;
    cudaEvent_t val_ev[LNUM] = {};
    bool ok = false;
    Aux() {
        if (cudaStreamCreateWithFlags(&sB, cudaStreamNonBlocking) != cudaSuccess) return;
        if (cudaEventCreateWithFlags(&fork, cudaEventDisableTiming) != cudaSuccess) return;
        for (int i = 0; i < LNUM; i++)
            if (cudaEventCreateWithFlags(&val_ev[i], cudaEventDisableTiming) != cudaSuccess) return;
        ok = true;
    }
};
static Aux g_aux;

// ------------------------- helpers -------------------------
__device__ __forceinline__ uint32_t f2tf(float f) {
    uint32_t r;
    asm("cvt.rna.tf32.f32 %0, %1;" : "=r"(r) : "f"(f));
    return r;
}
__device__ __forceinline__ void mma_tf32(float* c, const uint32_t* a, const uint32_t* b) {
    asm volatile("mma.sync.aligned.m16n8k8.row.col.f32.tf32.tf32.f32 "
                 "{%0,%1,%2,%3},{%4,%5,%6,%7},{%8,%9},{%0,%1,%2,%3};"
                 : "+f"(c[0]), "+f"(c[1]), "+f"(c[2]), "+f"(c[3])
                 : "r"(a[0]), "r"(a[1]), "r"(a[2]), "r"(a[3]), "r"(b[0]), "r"(b[1]));
}
__device__ __forceinline__ void cp16(uint32_t smem_addr, const void* gptr, int src_bytes) {
    asm volatile("cp.async.ca.shared.global [%0], [%1], 16, %2;\n"
                 :: "r"(smem_addr), "l"(gptr), "r"(src_bytes));
}
__device__ __forceinline__ void cp_commit() { asm volatile("cp.async.commit_group;\n"); }
template <int N>
__device__ __forceinline__ void cp_wait() { asm volatile("cp.async.wait_group %0;\n" :: "n"(N)); }

// ------------------------- elementwise add -------------------------
__global__ void add_kernel(const float* __restrict__ a, const float* __restrict__ b,
                           float* __restrict__ o, int n) {
    int i = blockIdx.x * blockDim.x + threadIdx.x;
    if (i < n) o[i] = a[i] + b[i];
}

// ------------------------- tf32 tensor-core GEMM (templated tile) -------------------------
template <int BM, int BN, bool RELU>
__global__ __launch_bounds__(256)
void gemm_tc(const float* __restrict__ A, const float* __restrict__ W,
             const float* __restrict__ bias, float* __restrict__ C,
             int M, int N, int K) {
    constexpr int ST  = 3;
    constexpr int WMC = BM / 32;
    constexpr int WNC = 8 / WMC;
    constexpr int WCOLS = BN / WNC;
    constexpr int NT  = WCOLS / 8;

    __shared__ uint32_t As[ST][BM * 16];
    __shared__ uint32_t Bs[ST][BN * 16];

    const int tid  = threadIdx.x;
    const int lane = tid & 31;
    const int wid  = tid >> 5;
    const int wm   = wid % WMC;
    const int wn   = wid / WMC;
    const int g    = lane >> 2;
    const int t    = lane & 3;
    const int m0   = blockIdx.y * BM;
    const int n0   = blockIdx.x * BN;

    auto load_stage = [&](int s, int kt) {
        const int k0 = kt * 16;
        uint32_t sa = (uint32_t)__cvta_generic_to_shared(&As[s][0]);
        uint32_t sb = (uint32_t)__cvta_generic_to_shared(&Bs[s][0]);
#pragma unroll
        for (int c = tid; c < (BM + BN) * 4; c += 256) {
            int row = c >> 2, cg = (c & 3) * 4;
            if (c < BM * 4) {
                int gm = m0 + row;
                cp16(sa + (row * 16 + cg) * 4, &A[(size_t)gm * K + k0 + cg], gm < M ? 16 : 0);
            } else {
                int r = row - BM;
                cp16(sb + (r * 16 + cg) * 4, &W[(size_t)(n0 + r) * K + k0 + cg], 16);
            }
        }
        cp_commit();
    };

    float acc[2][NT][4];
#pragma unroll
    for (int i = 0; i < 2; i++)
#pragma unroll
        for (int j = 0; j < NT; j++)
#pragma unroll
            for (int c = 0; c < 4; c++) acc[i][j][c] = 0.f;

    const int KT = K / 16;
    load_stage(0, 0);
    if (KT > 1) load_stage(1 % ST, 1);

    for (int kt = 0; kt < KT; kt++) {
        cp_wait<1>();
        __syncthreads();
        if (kt + 2 < KT) load_stage((kt + 2) % ST, kt + 2);
        const int s = kt % ST;

        uint32_t afA[2][4], afB[2][4];
#pragma unroll
        for (int mt = 0; mt < 2; mt++) {
            const int row = wm * 32 + mt * 16 + g;
            uint4 ar0 = *reinterpret_cast<const uint4*>(&As[s][row * 16 + t * 4]);
            uint4 ar1 = *reinterpret_cast<const uint4*>(&As[s][(row + 8) * 16 + t * 4]);
            afA[mt][0] = ar0.x; afA[mt][1] = ar1.x; afA[mt][2] = ar0.y; afA[mt][3] = ar1.y;
            afB[mt][0] = ar0.z; afB[mt][1] = ar1.z; afB[mt][2] = ar0.w; afB[mt][3] = ar1.w;
        }
#pragma unroll
        for (int nt = 0; nt < NT; nt++) {
            uint4 br = *reinterpret_cast<const uint4*>(&Bs[s][(wn * WCOLS + nt * 8 + g) * 16 + t * 4]);
            uint32_t bA[2] = {br.x, br.y};
            uint32_t bB[2] = {br.z, br.w};
#pragma unroll
            for (int mt = 0; mt < 2; mt++) {
                mma_tf32(acc[mt][nt], afA[mt], bA);
                mma_tf32(acc[mt][nt], afB[mt], bB);
            }
        }
    }

#pragma unroll
    for (int nt = 0; nt < NT; nt++) {
        const int cb = n0 + wn * WCOLS + nt * 8 + t * 2;
        const float bv0 = bias[cb], bv1 = bias[cb + 1];
#pragma unroll
        for (int mt = 0; mt < 2; mt++) {
            int r0 = m0 + wm * 32 + mt * 16 + g;
            float o0 = acc[mt][nt][0] + bv0, o1 = acc[mt][nt][1] + bv1;
            float o2 = acc[mt][nt][2] + bv0, o3 = acc[mt][nt][3] + bv1;
            if (RELU) {
                o0 = fmaxf(o0, 0.f); o1 = fmaxf(o1, 0.f);
                o2 = fmaxf(o2, 0.f); o3 = fmaxf(o3, 0.f);
            }
            if (r0 < M)
                *reinterpret_cast<float2*>(&C[(size_t)r0 * N + cb]) = make_float2(o0, o1);
            if (r0 + 8 < M)
                *reinterpret_cast<float2*>(&C[(size_t)(r0 + 8) * N + cb]) = make_float2(o2, o3);
        }
    }
}

// ------------------------- fused GEMM + bias + residual + LayerNorm -------------------------
// C[M,256] = LN(A[M,K] @ W[256,K]^T + bias + resid) * lnw + lnb.  BM=32, BN=256 (full row).
// Optionally writes C2 = result + qpos.
__global__ __launch_bounds__(256)
void gemm_ln(const float* __restrict__ A, const float* __restrict__ W,
             const float* __restrict__ bias, const float* __restrict__ resid,
             const float* __restrict__ lnw, const float* __restrict__ lnb,
             float* __restrict__ C, const float* __restrict__ qpos,
             float* __restrict__ C2, int M, int K) {
    constexpr int ST = 3, BM = 32, BN = 256, NT = 4, WCOLS = 32;
    __shared__ uint32_t As[ST][BM * 16];
    __shared__ uint32_t Bs[ST][BN * 16];
    __shared__ float s_sum[BM][8];
    __shared__ float s_sq[BM][8];

    const int tid  = threadIdx.x;
    const int lane = tid & 31;
    const int wn   = tid >> 5;           // warp = column block (WMC=1)
    const int g    = lane >> 2;
    const int t    = lane & 3;
    const int m0   = blockIdx.y * BM;

    auto load_stage = [&](int s, int kt) {
        const int k0 = kt * 16;
        uint32_t sa = (uint32_t)__cvta_generic_to_shared(&As[s][0]);
        uint32_t sb = (uint32_t)__cvta_generic_to_shared(&Bs[s][0]);
#pragma unroll
        for (int c = tid; c < (BM + BN) * 4; c += 256) {
            int row = c >> 2, cg = (c & 3) * 4;
            if (c < BM * 4) {
                cp16(sa + (row * 16 + cg) * 4, &A[(size_t)(m0 + row) * K + k0 + cg], 16);
            } else {
                int r = row - BM;
                cp16(sb + (r * 16 + cg) * 4, &W[(size_t)r * K + k0 + cg], 16);
            }
        }
        cp_commit();
    };

    float acc[2][NT][4];
#pragma unroll
    for (int i = 0; i < 2; i++)
#pragma unroll
        for (int j = 0; j < NT; j++)
#pragma unroll
            for (int c = 0; c < 4; c++) acc[i][j][c] = 0.f;

    const int KT = K / 16;
    load_stage(0, 0);
    if (KT > 1) load_stage(1 % ST, 1);

    for (int kt = 0; kt < KT; kt++) {
        cp_wait<1>();
        __syncthreads();
        if (kt + 2 < KT) load_stage((kt + 2) % ST, kt + 2);
        const int s = kt % ST;

        uint32_t afA[2][4], afB[2][4];
#pragma unroll
        for (int mt = 0; mt < 2; mt++) {
            const int row = mt * 16 + g;
            uint4 ar0 = *reinterpret_cast<const uint4*>(&As[s][row * 16 + t * 4]);
            uint4 ar1 = *reinterpret_cast<const uint4*>(&As[s][(row + 8) * 16 + t * 4]);
            afA[mt][0] = ar0.x; afA[mt][1] = ar1.x; afA[mt][2] = ar0.y; afA[mt][3] = ar1.y;
            afB[mt][0] = ar0.z; afB[mt][1] = ar1.z; afB[mt][2] = ar0.w; afB[mt][3] = ar1.w;
        }
#pragma unroll
        for (int nt = 0; nt < NT; nt++) {
            uint4 br = *reinterpret_cast<const uint4*>(&Bs[s][(wn * WCOLS + nt * 8 + g) * 16 + t * 4]);
            uint32_t bA[2] = {br.x, br.y};
            uint32_t bB[2] = {br.z, br.w};
#pragma unroll
            for (int mt = 0; mt < 2; mt++) {
                mma_tf32(acc[mt][nt], afA[mt], bA);
                mma_tf32(acc[mt][nt], afB[mt], bB);
            }
        }
    }

    // ---- epilogue: bias + residual, row statistics, LN ----
    float vals[2][NT][4];
    float rsum[4] = {0.f, 0.f, 0.f, 0.f};
    float rsq[4]  = {0.f, 0.f, 0.f, 0.f};
#pragma unroll
    for (int mt = 0; mt < 2; mt++) {
        const int r0 = m0 + mt * 16 + g, r1 = r0 + 8;
#pragma unroll
        for (int nt = 0; nt < NT; nt++) {
            const int cb = wn * WCOLS + nt * 8 + t * 2;
            const float b0 = bias[cb], b1 = bias[cb + 1];
            float2 rr0 = *reinterpret_cast<const float2*>(&resid[(size_t)r0 * 256 + cb]);
            float2 rr1 = *reinterpret_cast<const float2*>(&resid[(size_t)r1 * 256 + cb]);
            float v0 = acc[mt][nt][0] + b0 + rr0.x;
            float v1 = acc[mt][nt][1] + b1 + rr0.y;
            float v2 = acc[mt][nt][2] + b0 + rr1.x;
            float v3 = acc[mt][nt][3] + b1 + rr1.y;
            vals[mt][nt][0] = v0; vals[mt][nt][1] = v1;
            vals[mt][nt][2] = v2; vals[mt][nt][3] = v3;
            rsum[mt * 2]     += v0 + v1;  rsq[mt * 2]     += v0 * v0 + v1 * v1;
            rsum[mt * 2 + 1] += v2 + v3;  rsq[mt * 2 + 1] += v2 * v2 + v3 * v3;
        }
    }
    const unsigned F = 0xffffffffu;
#pragma unroll
    for (int sl = 0; sl < 4; sl++) {
        rsum[sl] += __shfl_xor_sync(F, rsum[sl], 1);
        rsum[sl] += __shfl_xor_sync(F, rsum[sl], 2);
        rsq[sl]  += __shfl_xor_sync(F, rsq[sl], 1);
        rsq[sl]  += __shfl_xor_sync(F, rsq[sl], 2);
    }
    if (t == 0) {
#pragma unroll
        for (int sl = 0; sl < 4; sl++) {
            int rowl = (sl >> 1) * 16 + g + (sl & 1) * 8;
            s_sum[rowl][wn] = rsum[sl];
            s_sq[rowl][wn]  = rsq[sl];
        }
    }
    __syncthreads();

    float mean_[4], rstd_[4];
#pragma unroll
    for (int sl = 0; sl < 4; sl++) {
        int rowl = (sl >> 1) * 16 + g + (sl & 1) * 8;
        float s = 0.f, q = 0.f;
#pragma unroll
        for (int w8 = 0; w8 < 8; w8++) { s += s_sum[rowl][w8]; q += s_sq[rowl][w8]; }
        float mean = s * (1.f / 256.f);
        float var  = q * (1.f / 256.f) - mean * mean;
        mean_[sl] = mean;
        rstd_[sl] = rsqrtf(var + 1e-5f);
    }

#pragma unroll
    for (int mt = 0; mt < 2; mt++) {
        const int r0 = m0 + mt * 16 + g, r1 = r0 + 8;
        const float mA = mean_[mt * 2],     rA = rstd_[mt * 2];
        const float mB = mean_[mt * 2 + 1], rB = rstd_[mt * 2 + 1];
#pragma unroll
        for (int nt = 0; nt < NT; nt++) {
            const int cb = wn * WCOLS + nt * 8 + t * 2;
            const float w0 = lnw[cb], w1 = lnw[cb + 1];
            const float lb0 = lnb[cb], lb1 = lnb[cb + 1];
            float o0 = (vals[mt][nt][0] - mA) * rA * w0 + lb0;
            float o1 = (vals[mt][nt][1] - mA) * rA * w1 + lb1;
            float o2 = (vals[mt][nt][2] - mB) * rB * w0 + lb0;
            float o3 = (vals[mt][nt][3] - mB) * rB * w1 + lb1;
            *reinterpret_cast<float2*>(&C[(size_t)r0 * 256 + cb]) = make_float2(o0, o1);
            *reinterpret_cast<float2*>(&C[(size_t)r1 * 256 + cb]) = make_float2(o2, o3);
            if (C2) {
                float2 q0 = *reinterpret_cast<const float2*>(&qpos[(size_t)r0 * 256 + cb]);
                float2 q1 = *reinterpret_cast<const float2*>(&qpos[(size_t)r1 * 256 + cb]);
                *reinterpret_cast<float2*>(&C2[(size_t)r0 * 256 + cb]) =
                    make_float2(o0 + q0.x, o1 + q0.y);
                *reinterpret_cast<float2*>(&C2[(size_t)r1 * 256 + cb]) =
                    make_float2(o2 + q1.x, o3 + q1.y);
            }
        }
    }
}

// ------------------------- tensor-core flash attention -------------------------
#define LKP 36
#define LVP 40
__global__ __launch_bounds__(256)
void attn_tc_kernel(const float* __restrict__ QK, const float* __restrict__ V,
                    float* __restrict__ O) {
    __shared__ uint32_t Ks[64 * LKP];
    __shared__ uint32_t Vs[64 * LVP];

    const int q0   = blockIdx.x * 128;
    const int h    = blockIdx.y;
    const int b    = blockIdx.z;
    const int tid  = threadIdx.x;
    const int lane = tid & 31;
    const int w    = tid >> 5;
    const int g    = lane >> 2;
    const int t    = lane & 3;

    uint32_t af[4][4];
    {
        const int r0 = b * NQ + q0 + w * 16 + g;
        const int r1 = r0 + 8;
        const float sc = 0.17677669529663687f;
        const float* Q0 = &QK[(size_t)r0 * 512 + h * 32];
        const float* Q1 = &QK[(size_t)r1 * 512 + h * 32];
#pragma unroll
        for (int ks = 0; ks < 4; ks++) {
            af[ks][0] = f2tf(Q0[ks * 8 + t] * sc);
            af[ks][1] = f2tf(Q1[ks * 8 + t] * sc);
            af[ks][2] = f2tf(Q0[ks * 8 + t + 4] * sc);
            af[ks][3] = f2tf(Q1[ks * 8 + t + 4] * sc);
        }
    }

    float oc[4][4];
#pragma unroll
    for (int i = 0; i < 4; i++)
#pragma unroll
        for (int j = 0; j < 4; j++) oc[i][j] = 0.f;
    float m0r = -1e30f, m1r = -1e30f, l0 = 0.f, l1 = 0.f;

    const int lrow = tid >> 2;
    const int lcg  = (tid & 3) * 8;
    const unsigned F = 0xffffffffu;

    for (int t0 = 0; t0 < NQ; t0 += 64) {
        __syncthreads();
        {
            const float* kp = &QK[(size_t)(b * NQ + t0 + lrow) * 512 + 256 + h * 32 + lcg];
            float4 k0 = *reinterpret_cast<const float4*>(kp);
            float4 k1 = *reinterpret_cast<const float4*>(kp + 4);
            *reinterpret_cast<uint4*>(&Ks[lrow * LKP + lcg]) =
                make_uint4(f2tf(k0.x), f2tf(k0.y), f2tf(k0.z), f2tf(k0.w));
            *reinterpret_cast<uint4*>(&Ks[lrow * LKP + lcg + 4]) =
                make_uint4(f2tf(k1.x), f2tf(k1.y), f2tf(k1.z), f2tf(k1.w));
            const float* vp = &V[(size_t)(b * NQ + t0 + lrow) * 256 + h * 32 + lcg];
            float4 v0 = *reinterpret_cast<const float4*>(vp);
            float4 v1 = *reinterpret_cast<const float4*>(vp + 4);
            *reinterpret_cast<uint4*>(&Vs[lrow * LVP + lcg]) =
                make_uint4(f2tf(v0.x), f2tf(v0.y), f2tf(v0.z), f2tf(v0.w));
            *reinterpret_cast<uint4*>(&Vs[lrow * LVP + lcg + 4]) =
                make_uint4(f2tf(v1.x), f2tf(v1.y), f2tf(v1.z), f2tf(v1.w));
        }
        __syncthreads();

        float sc[8][4];
#pragma unroll
        for (int nt = 0; nt < 8; nt++) {
            sc[nt][0] = sc[nt][1] = sc[nt][2] = sc[nt][3] = 0.f;
            uint32_t bf[4][2];
#pragma unroll
            for (int ks = 0; ks < 4; ks++) {
                const uint32_t* base = &Ks[(nt * 8 + g) * LKP + ks * 8];
                bf[ks][0] = base[t];
                bf[ks][1] = base[t + 4];
            }
#pragma unroll
            for (int ks = 0; ks < 4; ks++) mma_tf32(sc[nt], af[ks], bf[ks]);
        }

        float mt0 = -1e30f, mt1 = -1e30f;
#pragma unroll
        for (int nt = 0; nt < 8; nt++) {
            mt0 = fmaxf(mt0, fmaxf(sc[nt][0], sc[nt][1]));
            mt1 = fmaxf(mt1, fmaxf(sc[nt][2], sc[nt][3]));
        }
        mt0 = fmaxf(mt0, __shfl_xor_sync(F, mt0, 1));
        mt0 = fmaxf(mt0, __shfl_xor_sync(F, mt0, 2));
        mt1 = fmaxf(mt1, __shfl_xor_sync(F, mt1, 1));
        mt1 = fmaxf(mt1, __shfl_xor_sync(F, mt1, 2));
        const float mn0 = fmaxf(m0r, mt0), mn1 = fmaxf(m1r, mt1);
        const float sc0 = __expf(m0r - mn0), sc1 = __expf(m1r - mn1);

        uint32_t pf[8][4];
        float s0 = 0.f, s1 = 0.f;
#pragma unroll
        for (int nt = 0; nt < 8; nt++) {
            float p0 = __expf(sc[nt][0] - mn0);
            float p1 = __expf(sc[nt][1] - mn0);
            float p2 = __expf(sc[nt][2] - mn1);
            float p3 = __expf(sc[nt][3] - mn1);
            s0 += p0 + p1; s1 += p2 + p3;
            pf[nt][0] = f2tf(p0); pf[nt][1] = f2tf(p1);
            pf[nt][2] = f2tf(p2); pf[nt][3] = f2tf(p3);
        }
        s0 += __shfl_xor_sync(F, s0, 1); s0 += __shfl_xor_sync(F, s0, 2);
        s1 += __shfl_xor_sync(F, s1, 1); s1 += __shfl_xor_sync(F, s1, 2);
        l0 = l0 * sc0 + s0;
        l1 = l1 * sc1 + s1;
        m0r = mn0; m1r = mn1;
#pragma unroll
        for (int nt = 0; nt < 4; nt++) {
            oc[nt][0] *= sc0; oc[nt][1] *= sc0;
            oc[nt][2] *= sc1; oc[nt][3] *= sc1;
        }

        const int src0 = (lane & ~3) | (t >> 1);
        const int src1 = src0 + 2;
        const bool odd = (t & 1);
#pragma unroll
        for (int kt = 0; kt < 8; kt++) {
            uint32_t a[4];
            uint32_t x0 = __shfl_sync(F, pf[kt][0], src0);
            uint32_t x1 = __shfl_sync(F, pf[kt][1], src0);
            a[0] = odd ? x1 : x0;
            uint32_t x2 = __shfl_sync(F, pf[kt][2], src0);
            uint32_t x3 = __shfl_sync(F, pf[kt][3], src0);
            a[1] = odd ? x3 : x2;
            x0 = __shfl_sync(F, pf[kt][0], src1);
            x1 = __shfl_sync(F, pf[kt][1], src1);
            a[2] = odd ? x1 : x0;
            x2 = __shfl_sync(F, pf[kt][2], src1);
            x3 = __shfl_sync(F, pf[kt][3], src1);
            a[3] = odd ? x3 : x2;
#pragma unroll
            for (int nt = 0; nt < 4; nt++) {
                uint32_t bf[2];
                bf[0] = Vs[(kt * 8 + t) * LVP + nt * 8 + g];
                bf[1] = Vs[(kt * 8 + t + 4) * LVP + nt * 8 + g];
                mma_tf32(oc[nt], a, bf);
            }
        }
    }

    const float inv0 = 1.f / l0, inv1 = 1.f / l1;
    const int r0 = b * NQ + q0 + w * 16 + g;
#pragma unroll
    for (int nt = 0; nt < 4; nt++) {
        const int col = h * 32 + nt * 8 + t * 2;
        *reinterpret_cast<float2*>(&O[(size_t)r0 * 256 + col]) =
            make_float2(oc[nt][0] * inv0, oc[nt][1] * inv0);
        *reinterpret_cast<float2*>(&O[(size_t)(r0 + 8) * 256 + col]) =
            make_float2(oc[nt][2] * inv1, oc[nt][3] * inv1);
    }
}

// ------------------------- MSDA sampling -------------------------
__global__ void msda_kernel(const float* __restrict__ val, const float* __restrict__ off,
                            const float* __restrict__ aw, const float* __restrict__ ref,
                            const int* __restrict__ lsi, float* __restrict__ out) {
    const int warp = (blockIdx.x * blockDim.x + threadIdx.x) >> 5;
    const int lane = threadIdx.x & 31;
    if (warp >= BS * NQ * NH) return;
    const int h  = warp % NH;
    const int bq = warp / NH;
    const int b  = bq / NQ;
    const int base = lsi[0];

    const float rx = ref[bq * 2 + 0] * (float)W_BEV - 0.5f;
    const float ry = ref[bq * 2 + 1] * (float)H_BEV - 0.5f;

    float a0 = aw[bq * (NH * NP) + h * NP + 0];
    float a1 = aw[bq * (NH * NP) + h * NP + 1];
    float a2 = aw[bq * (NH * NP) + h * NP + 2];
    float a3 = aw[bq * (NH * NP) + h * NP + 3];
    float mx = fmaxf(fmaxf(a0, a1), fmaxf(a2, a3));
    float e0 = __expf(a0 - mx), e1 = __expf(a1 - mx), e2 = __expf(a2 - mx), e3 = __expf(a3 - mx);
    float inv = 1.f / (e0 + e1 + e2 + e3);
    float ap[4] = {e0 * inv, e1 * inv, e2 * inv, e3 * inv};

    float accv = 0.f;
#pragma unroll
    for (int p = 0; p < NP; p++) {
        float ox = off[bq * (NH * NP * 2) + (h * NP + p) * 2 + 0];
        float oy = off[bq * (NH * NP * 2) + (h * NP + p) * 2 + 1];
        float x = rx + ox, y = ry + oy;
        float x0f = floorf(x), y0f = floorf(y);
        int x0 = (int)x0f, y0 = (int)y0f;
        float fx = x - x0f, fy = y - y0f;
        float wgt[4] = {(1.f - fx) * (1.f - fy), fx * (1.f - fy), (1.f - fx) * fy, fx * fy};
        int xs[4] = {x0, x0 + 1, x0, x0 + 1};
        int ys[4] = {y0, y0, y0 + 1, y0 + 1};
#pragma unroll
        for (int c = 0; c < 4; c++) {
            int xi = xs[c], yi = ys[c];
            if (xi >= 0 && xi < W_BEV && yi >= 0 && yi < H_BEV) {
                float vv = val[((size_t)(b * NV + base + yi * W_BEV + xi)) * D + h * DH + lane];
                accv += ap[p] * wgt[c] * vv;
            }
        }
    }
    out[(size_t)bq * D + h * DH + lane] = accv;
}

// ------------------------- refs tail -------------------------
__global__ void copy_refs_kernel(const float* __restrict__ ref, float* __restrict__ out) {
    int i = blockIdx.x * blockDim.x + threadIdx.x;
    const int n1 = BS * NQ * 2;
    if (i < LNUM * n1) out[i] = ref[i % n1];
}

// ------------------------- launch -------------------------
extern "C" void kernel_launch(void* const* d_in, const int* in_sizes, int n_in,
                              void* d_out, int out_size) {
    const float* query    = (const float*)d_in[0];
    const float* qpos     = (const float*)d_in[1];
    const float* ref      = (const float*)d_in[2];
    const float* src      = (const float*)d_in[3];
    const int*   lsi      = (const int*)d_in[5];
    const float* sa_in_w  = (const float*)d_in[6];
    const float* sa_in_b  = (const float*)d_in[7];
    const float* sa_out_w = (const float*)d_in[8];
    const float* sa_out_b = (const float*)d_in[9];
    const float* ca_off_w = (const float*)d_in[10];
    const float* ca_off_b = (const float*)d_in[11];
    const float* ca_aw_w  = (const float*)d_in[12];
    const float* ca_aw_b  = (const float*)d_in[13];
    const float* ca_val_w = (const float*)d_in[14];
    const float* ca_val_b = (const float*)d_in[15];
    const float* ca_out_w = (const float*)d_in[16];
    const float* ca_out_b = (const float*)d_in[17];
    const float* n1_w     = (const float*)d_in[18];
    const float* n1_b     = (const float*)d_in[19];
    const float* n2_w     = (const float*)d_in[20];
    const float* n2_b     = (const float*)d_in[21];
    const float* n3_w     = (const float*)d_in[22];
    const float* n3_b     = (const float*)d_in[23];
    const float* ff1_w    = (const float*)d_in[24];
    const float* ff1_b    = (const float*)d_in[25];
    const float* ff2_w    = (const float*)d_in[26];
    const float* ff2_b    = (const float*)d_in[27];

    float *xbuf, *qkb, *vb, *sab, *t1b, *t2b, *valb, *offb, *awb, *cab, *ffnb;
    cudaGetSymbolAddress((void**)&xbuf, g_xbuf);
    cudaGetSymbolAddress((void**)&qkb,  g_qk);
    cudaGetSymbolAddress((void**)&vb,   g_v);
    cudaGetSymbolAddress((void**)&sab,  g_sa);
    cudaGetSymbolAddress((void**)&t1b,  g_t1);
    cudaGetSymbolAddress((void**)&t2b,  g_t2);
    cudaGetSymbolAddress((void**)&valb, g_val);
    cudaGetSymbolAddress((void**)&offb, g_off);
    cudaGetSymbolAddress((void**)&awb,  g_aw);
    cudaGetSymbolAddress((void**)&cab,  g_ca);
    cudaGetSymbolAddress((void**)&ffnb, g_ffn);

    float* out_hs = (float*)d_out;
    const int NTOK = MROWS * D;
    const size_t VAL_STRIDE = (size_t)BS * NV * D;

    const bool use_sB = g_aux.ok;
    cudaStream_t sB = use_sB ? g_aux.sB : 0;

    // ---- fork: all 6 value projections on side stream ----
    if (use_sB) {
        cudaEventRecord(g_aux.fork, 0);
        cudaStreamWaitEvent(sB, g_aux.fork, 0);
    }
    for (int l = 0; l < LNUM; l++) {
        gemm_tc<128, 128, false><<<dim3(D / 128, (BS * NV + 127) / 128), 256, 0, sB>>>(
            src, ca_val_w + (size_t)l * D * D, ca_val_b + (size_t)l * D,
            valb + (size_t)l * VAL_STRIDE, BS * NV, D, D);
        if (use_sB) cudaEventRecord(g_aux.val_ev[l], sB);
    }

    // xbuf = query + qpos (first layer only; later layers get it from gemm_ln)
    add_kernel<<<(NTOK + 255) / 256, 256>>>(query, qpos, xbuf, NTOK);

    for (int l = 0; l < LNUM; l++) {
        const float* prev = (l == 0) ? query : out_hs + (size_t)(l - 1) * NTOK;
        float* cur = out_hs + (size_t)l * NTOK;

        // --- self attention ---
        gemm_tc<64, 128, false><<<dim3(512 / 128, MROWS / 64), 256>>>(
            xbuf, sa_in_w + (size_t)l * 3 * D * D, sa_in_b + (size_t)l * 3 * D,
            qkb, MROWS, 512, D);
        gemm_tc<64, 128, false><<<dim3(D / 128, MROWS / 64), 256>>>(
            prev, sa_in_w + (size_t)l * 3 * D * D + (size_t)2 * D * D,
            sa_in_b + (size_t)l * 3 * D + 2 * D, vb, MROWS, D, D);
        attn_tc_kernel<<<dim3(NQ / 128, NH, BS), 256>>>(qkb, vb, sab);
        // t1b = LN(prev + sa_out), xbuf = t1b + qpos
        gemm_ln<<<dim3(1, MROWS / 32), 256>>>(
            sab, sa_out_w + (size_t)l * D * D, sa_out_b + (size_t)l * D, prev,
            n2_w + (size_t)l * D, n2_b + (size_t)l * D, t1b, qpos, xbuf, MROWS, D);

        // --- deformable cross attention ---
        gemm_tc<64, 64, false><<<dim3(1, MROWS / 64), 256>>>(
            xbuf, ca_off_w + (size_t)l * NH * NP * 2 * D, ca_off_b + (size_t)l * NH * NP * 2,
            offb, MROWS, NH * NP * 2, D);
        gemm_tc<64, 32, false><<<dim3(1, MROWS / 64), 256>>>(
            xbuf, ca_aw_w + (size_t)l * NH * NP * D, ca_aw_b + (size_t)l * NH * NP,
            awb, MROWS, NH * NP, D);
        if (use_sB) cudaStreamWaitEvent(0, g_aux.val_ev[l], 0);
        msda_kernel<<<(BS * NQ * NH + 7) / 8, 256>>>(
            valb + (size_t)l * VAL_STRIDE, offb, awb, ref, lsi, cab);
        // t2b = LN(t1b + ca_out)
        gemm_ln<<<dim3(1, MROWS / 32), 256>>>(
            cab, ca_out_w + (size_t)l * D * D, ca_out_b + (size_t)l * D, t1b,
            n1_w + (size_t)l * D, n1_b + (size_t)l * D, t2b, nullptr, nullptr, MROWS, D);

        // --- FFN ---
        gemm_tc<128, 128, true><<<dim3(DFF / 128, MROWS / 128), 256>>>(
            t2b, ff1_w + (size_t)l * DFF * D, ff1_b + (size_t)l * DFF, ffnb, MROWS, DFF, D);
        // cur = LN(t2b + ffn2), xbuf = cur + qpos (for next layer QKV)
        gemm_ln<<<dim3(1, MROWS / 32), 256>>>(
            ffnb, ff2_w + (size_t)l * D * DFF, ff2_b + (size_t)l * D, t2b,
            n3_w + (size_t)l * D, n3_b + (size_t)l * D, cur, qpos, xbuf, MROWS, DFF);
    }

    const int hs_total = LNUM * MROWS * D;
    if (out_size > hs_total) {
        copy_refs_kernel<<<(LNUM * BS * NQ * 2 + 255) / 256, 256>>>(ref, out_hs + hs_total);
    }
}

// round 8
// speedup vs baseline: 4.5420x; 1.0525x over previous
#include <cuda_runtime.h>
#include <cuda_bf16.h>
#include <cstdint>

#define BS   4
#define NQ   1024
#define D    256
#define NH   8
#define NP   4
#define LNUM 6
#define DFF  1024
#define H_BEV 200
#define W_BEV 150
#define NV   (H_BEV * W_BEV)
#define DH   32
#define MROWS (BS * NQ)          // 4096

// ------------------------- scratch (static device globals) -------------------------
__device__ float g_xbuf[MROWS * D];
__device__ float g_qk[MROWS * 512];
__device__ float g_v[MROWS * D];
__device__ float g_sa[MROWS * D];
__device__ float g_t1[MROWS * D];
__device__ float g_t2[MROWS * D];
__device__ float g_val[(size_t)LNUM * BS * NV * D];
__device__ float g_ow[LNUM * 128 * D];     // packed off+aw weights
__device__ float g_ob[LNUM * 128];         // packed off+aw bias
__device__ float g_offaw[MROWS * 128];
__device__ float g_ca[MROWS * D];
__device__ float g_ffn[MROWS * DFF];

// ------------------------- stream/event aux -------------------------
struct Aux {
    cudaStream_t sB = 0, sC = 0;
    cudaEvent_t fork = 0;
    cudaEvent_t val_ev[LNUM] = {};
    cudaEvent_t ev_x[LNUM] = {};
    cudaEvent_t ev_v[LNUM] = {};
    bool ok = false;
    Aux() {
        if (cudaStreamCreateWithFlags(&sB, cudaStreamNonBlocking) != cudaSuccess) return;
        if (cudaStreamCreateWithFlags(&sC, cudaStreamNonBlocking) != cudaSuccess) return;
        if (cudaEventCreateWithFlags(&fork, cudaEventDisableTiming) != cudaSuccess) return;
        for (int i = 0; i < LNUM; i++) {
            if (cudaEventCreateWithFlags(&val_ev[i], cudaEventDisableTiming) != cudaSuccess) return;
            if (cudaEventCreateWithFlags(&ev_x[i], cudaEventDisableTiming) != cudaSuccess) return;
            if (cudaEventCreateWithFlags(&ev_v[i], cudaEventDisableTiming) != cudaSuccess) return;
        }
        ok = true;
    }
};
static Aux g_aux;

// ------------------------- helpers -------------------------
__device__ __forceinline__ uint32_t f2tf(float f) {
    uint32_t r;
    asm("cvt.rna.tf32.f32 %0, %1;" : "=r"(r) : "f"(f));
    return r;
}
__device__ __forceinline__ void mma_tf32(float* c, const uint32_t* a, const uint32_t* b) {
    asm volatile("mma.sync.aligned.m16n8k8.row.col.f32.tf32.tf32.f32 "
                 "{%0,%1,%2,%3},{%4,%5,%6,%7},{%8,%9},{%0,%1,%2,%3};"
                 : "+f"(c[0]), "+f"(c[1]), "+f"(c[2]), "+f"(c[3])
                 : "r"(a[0]), "r"(a[1]), "r"(a[2]), "r"(a[3]), "r"(b[0]), "r"(b[1]));
}
__device__ __forceinline__ void cp16(uint32_t smem_addr, const void* gptr, int src_bytes) {
    asm volatile("cp.async.ca.shared.global [%0], [%1], 16, %2;\n"
                 :: "r"(smem_addr), "l"(gptr), "r"(src_bytes));
}
__device__ __forceinline__ void cp_commit() { asm volatile("cp.async.commit_group;\n"); }
template <int N>
__device__ __forceinline__ void cp_wait() { asm volatile("cp.async.wait_group %0;\n" :: "n"(N)); }

// ------------------------- elementwise add -------------------------
__global__ void add_kernel(const float* __restrict__ a, const float* __restrict__ b,
                           float* __restrict__ o, int n) {
    int i = blockIdx.x * blockDim.x + threadIdx.x;
    if (i < n) o[i] = a[i] + b[i];
}

// ------------------------- pack off+aw weights -------------------------
__global__ void pack_offaw(const float* __restrict__ offw, const float* __restrict__ offb,
                           const float* __restrict__ aww, const float* __restrict__ awb,
                           float* __restrict__ W, float* __restrict__ B) {
    int i = blockIdx.x * blockDim.x + threadIdx.x;
    const int total = LNUM * 128 * D;
    if (i < total) {
        int l = i / (128 * D);
        int r = (i / D) % 128;
        int c = i % D;
        float v = 0.f;
        if (r < 64)      v = offw[((size_t)l * 64 + r) * D + c];
        else if (r < 96) v = aww[((size_t)l * 32 + (r - 64)) * D + c];
        W[i] = v;
    }
    if (i < LNUM * 128) {
        int l = i / 128, r = i % 128;
        float v = 0.f;
        if (r < 64)      v = offb[l * 64 + r];
        else if (r < 96) v = awb[l * 32 + (r - 64)];
        B[i] = v;
    }
}

// ------------------------- tf32 tensor-core GEMM (templated tile) -------------------------
template <int BM, int BN, bool RELU>
__global__ __launch_bounds__(256)
void gemm_tc(const float* __restrict__ A, const float* __restrict__ W,
             const float* __restrict__ bias, float* __restrict__ C,
             int M, int N, int K) {
    constexpr int ST  = 3;
    constexpr int WMC = BM / 32;
    constexpr int WNC = 8 / WMC;
    constexpr int WCOLS = BN / WNC;
    constexpr int NT  = WCOLS / 8;

    __shared__ uint32_t As[ST][BM * 16];
    __shared__ uint32_t Bs[ST][BN * 16];

    const int tid  = threadIdx.x;
    const int lane = tid & 31;
    const int wid  = tid >> 5;
    const int wm   = wid % WMC;
    const int wn   = wid / WMC;
    const int g    = lane >> 2;
    const int t    = lane & 3;
    const int m0   = blockIdx.y * BM;
    const int n0   = blockIdx.x * BN;

    auto load_stage = [&](int s, int kt) {
        const int k0 = kt * 16;
        uint32_t sa = (uint32_t)__cvta_generic_to_shared(&As[s][0]);
        uint32_t sb = (uint32_t)__cvta_generic_to_shared(&Bs[s][0]);
#pragma unroll
        for (int c = tid; c < (BM + BN) * 4; c += 256) {
            int row = c >> 2, cg = (c & 3) * 4;
            if (c < BM * 4) {
                int gm = m0 + row;
                cp16(sa + (row * 16 + cg) * 4, &A[(size_t)gm * K + k0 + cg], gm < M ? 16 : 0);
            } else {
                int r = row - BM;
                cp16(sb + (r * 16 + cg) * 4, &W[(size_t)(n0 + r) * K + k0 + cg], 16);
            }
        }
        cp_commit();
    };

    float acc[2][NT][4];
#pragma unroll
    for (int i = 0; i < 2; i++)
#pragma unroll
        for (int j = 0; j < NT; j++)
#pragma unroll
            for (int c = 0; c < 4; c++) acc[i][j][c] = 0.f;

    const int KT = K / 16;
    load_stage(0, 0);
    if (KT > 1) load_stage(1 % ST, 1);

    for (int kt = 0; kt < KT; kt++) {
        cp_wait<1>();
        __syncthreads();
        if (kt + 2 < KT) load_stage((kt + 2) % ST, kt + 2);
        const int s = kt % ST;

        uint32_t afA[2][4], afB[2][4];
#pragma unroll
        for (int mt = 0; mt < 2; mt++) {
            const int row = wm * 32 + mt * 16 + g;
            uint4 ar0 = *reinterpret_cast<const uint4*>(&As[s][row * 16 + t * 4]);
            uint4 ar1 = *reinterpret_cast<const uint4*>(&As[s][(row + 8) * 16 + t * 4]);
            afA[mt][0] = ar0.x; afA[mt][1] = ar1.x; afA[mt][2] = ar0.y; afA[mt][3] = ar1.y;
            afB[mt][0] = ar0.z; afB[mt][1] = ar1.z; afB[mt][2] = ar0.w; afB[mt][3] = ar1.w;
        }
#pragma unroll
        for (int nt = 0; nt < NT; nt++) {
            uint4 br = *reinterpret_cast<const uint4*>(&Bs[s][(wn * WCOLS + nt * 8 + g) * 16 + t * 4]);
            uint32_t bA[2] = {br.x, br.y};
            uint32_t bB[2] = {br.z, br.w};
#pragma unroll
            for (int mt = 0; mt < 2; mt++) {
                mma_tf32(acc[mt][nt], afA[mt], bA);
                mma_tf32(acc[mt][nt], afB[mt], bB);
            }
        }
    }

#pragma unroll
    for (int nt = 0; nt < NT; nt++) {
        const int cb = n0 + wn * WCOLS + nt * 8 + t * 2;
        const float bv0 = bias[cb], bv1 = bias[cb + 1];
#pragma unroll
        for (int mt = 0; mt < 2; mt++) {
            int r0 = m0 + wm * 32 + mt * 16 + g;
            float o0 = acc[mt][nt][0] + bv0, o1 = acc[mt][nt][1] + bv1;
            float o2 = acc[mt][nt][2] + bv0, o3 = acc[mt][nt][3] + bv1;
            if (RELU) {
                o0 = fmaxf(o0, 0.f); o1 = fmaxf(o1, 0.f);
                o2 = fmaxf(o2, 0.f); o3 = fmaxf(o3, 0.f);
            }
            if (r0 < M)
                *reinterpret_cast<float2*>(&C[(size_t)r0 * N + cb]) = make_float2(o0, o1);
            if (r0 + 8 < M)
                *reinterpret_cast<float2*>(&C[(size_t)(r0 + 8) * N + cb]) = make_float2(o2, o3);
        }
    }
}

// ------------------------- fused GEMM + bias + residual + LayerNorm -------------------------
__global__ __launch_bounds__(256)
void gemm_ln(const float* __restrict__ A, const float* __restrict__ W,
             const float* __restrict__ bias, const float* __restrict__ resid,
             const float* __restrict__ lnw, const float* __restrict__ lnb,
             float* __restrict__ C, const float* __restrict__ qpos,
             float* __restrict__ C2, int M, int K) {
    constexpr int ST = 3, BM = 32, BN = 256, NT = 4, WCOLS = 32;
    __shared__ uint32_t As[ST][BM * 16];
    __shared__ uint32_t Bs[ST][BN * 16];
    __shared__ float s_sum[BM][8];
    __shared__ float s_sq[BM][8];

    const int tid  = threadIdx.x;
    const int lane = tid & 31;
    const int wn   = tid >> 5;
    const int g    = lane >> 2;
    const int t    = lane & 3;
    const int m0   = blockIdx.y * BM;

    auto load_stage = [&](int s, int kt) {
        const int k0 = kt * 16;
        uint32_t sa = (uint32_t)__cvta_generic_to_shared(&As[s][0]);
        uint32_t sb = (uint32_t)__cvta_generic_to_shared(&Bs[s][0]);
#pragma unroll
        for (int c = tid; c < (BM + BN) * 4; c += 256) {
            int row = c >> 2, cg = (c & 3) * 4;
            if (c < BM * 4) {
                cp16(sa + (row * 16 + cg) * 4, &A[(size_t)(m0 + row) * K + k0 + cg], 16);
            } else {
                int r = row - BM;
                cp16(sb + (r * 16 + cg) * 4, &W[(size_t)r * K + k0 + cg], 16);
            }
        }
        cp_commit();
    };

    float acc[2][NT][4];
#pragma unroll
    for (int i = 0; i < 2; i++)
#pragma unroll
        for (int j = 0; j < NT; j++)
#pragma unroll
            for (int c = 0; c < 4; c++) acc[i][j][c] = 0.f;

    const int KT = K / 16;
    load_stage(0, 0);
    if (KT > 1) load_stage(1 % ST, 1);

    for (int kt = 0; kt < KT; kt++) {
        cp_wait<1>();
        __syncthreads();
        if (kt + 2 < KT) load_stage((kt + 2) % ST, kt + 2);
        const int s = kt % ST;

        uint32_t afA[2][4], afB[2][4];
#pragma unroll
        for (int mt = 0; mt < 2; mt++) {
            const int row = mt * 16 + g;
            uint4 ar0 = *reinterpret_cast<const uint4*>(&As[s][row * 16 + t * 4]);
            uint4 ar1 = *reinterpret_cast<const uint4*>(&As[s][(row + 8) * 16 + t * 4]);
            afA[mt][0] = ar0.x; afA[mt][1] = ar1.x; afA[mt][2] = ar0.y; afA[mt][3] = ar1.y;
            afB[mt][0] = ar0.z; afB[mt][1] = ar1.z; afB[mt][2] = ar0.w; afB[mt][3] = ar1.w;
        }
#pragma unroll
        for (int nt = 0; nt < NT; nt++) {
            uint4 br = *reinterpret_cast<const uint4*>(&Bs[s][(wn * WCOLS + nt * 8 + g) * 16 + t * 4]);
            uint32_t bA[2] = {br.x, br.y};
            uint32_t bB[2] = {br.z, br.w};
#pragma unroll
            for (int mt = 0; mt < 2; mt++) {
                mma_tf32(acc[mt][nt], afA[mt], bA);
                mma_tf32(acc[mt][nt], afB[mt], bB);
            }
        }
    }

    float vals[2][NT][4];
    float rsum[4] = {0.f, 0.f, 0.f, 0.f};
    float rsq[4]  = {0.f, 0.f, 0.f, 0.f};
#pragma unroll
    for (int mt = 0; mt < 2; mt++) {
        const int r0 = m0 + mt * 16 + g, r1 = r0 + 8;
#pragma unroll
        for (int nt = 0; nt < NT; nt++) {
            const int cb = wn * WCOLS + nt * 8 + t * 2;
            const float b0 = bias[cb], b1 = bias[cb + 1];
            float2 rr0 = *reinterpret_cast<const float2*>(&resid[(size_t)r0 * 256 + cb]);
            float2 rr1 = *reinterpret_cast<const float2*>(&resid[(size_t)r1 * 256 + cb]);
            float v0 = acc[mt][nt][0] + b0 + rr0.x;
            float v1 = acc[mt][nt][1] + b1 + rr0.y;
            float v2 = acc[mt][nt][2] + b0 + rr1.x;
            float v3 = acc[mt][nt][3] + b1 + rr1.y;
            vals[mt][nt][0] = v0; vals[mt][nt][1] = v1;
            vals[mt][nt][2] = v2; vals[mt][nt][3] = v3;
            rsum[mt * 2]     += v0 + v1;  rsq[mt * 2]     += v0 * v0 + v1 * v1;
            rsum[mt * 2 + 1] += v2 + v3;  rsq[mt * 2 + 1] += v2 * v2 + v3 * v3;
        }
    }
    const unsigned F = 0xffffffffu;
#pragma unroll
    for (int sl = 0; sl < 4; sl++) {
        rsum[sl] += __shfl_xor_sync(F, rsum[sl], 1);
        rsum[sl] += __shfl_xor_sync(F, rsum[sl], 2);
        rsq[sl]  += __shfl_xor_sync(F, rsq[sl], 1);
        rsq[sl]  += __shfl_xor_sync(F, rsq[sl], 2);
    }
    if (t == 0) {
#pragma unroll
        for (int sl = 0; sl < 4; sl++) {
            int rowl = (sl >> 1) * 16 + g + (sl & 1) * 8;
            s_sum[rowl][wn] = rsum[sl];
            s_sq[rowl][wn]  = rsq[sl];
        }
    }
    __syncthreads();

    float mean_[4], rstd_[4];
#pragma unroll
    for (int sl = 0; sl < 4; sl++) {
        int rowl = (sl >> 1) * 16 + g + (sl & 1) * 8;
        float s = 0.f, q = 0.f;
#pragma unroll
        for (int w8 = 0; w8 < 8; w8++) { s += s_sum[rowl][w8]; q += s_sq[rowl][w8]; }
        float mean = s * (1.f / 256.f);
        float var  = q * (1.f / 256.f) - mean * mean;
        mean_[sl] = mean;
        rstd_[sl] = rsqrtf(var + 1e-5f);
    }

#pragma unroll
    for (int mt = 0; mt < 2; mt++) {
        const int r0 = m0 + mt * 16 + g, r1 = r0 + 8;
        const float mA = mean_[mt * 2],     rA = rstd_[mt * 2];
        const float mB = mean_[mt * 2 + 1], rB = rstd_[mt * 2 + 1];
#pragma unroll
        for (int nt = 0; nt < NT; nt++) {
            const int cb = wn * WCOLS + nt * 8 + t * 2;
            const float w0 = lnw[cb], w1 = lnw[cb + 1];
            const float lb0 = lnb[cb], lb1 = lnb[cb + 1];
            float o0 = (vals[mt][nt][0] - mA) * rA * w0 + lb0;
            float o1 = (vals[mt][nt][1] - mA) * rA * w1 + lb1;
            float o2 = (vals[mt][nt][2] - mB) * rB * w0 + lb0;
            float o3 = (vals[mt][nt][3] - mB) * rB * w1 + lb1;
            *reinterpret_cast<float2*>(&C[(size_t)r0 * 256 + cb]) = make_float2(o0, o1);
            *reinterpret_cast<float2*>(&C[(size_t)r1 * 256 + cb]) = make_float2(o2, o3);
            if (C2) {
                float2 q0 = *reinterpret_cast<const float2*>(&qpos[(size_t)r0 * 256 + cb]);
                float2 q1 = *reinterpret_cast<const float2*>(&qpos[(size_t)r1 * 256 + cb]);
                *reinterpret_cast<float2*>(&C2[(size_t)r0 * 256 + cb]) =
                    make_float2(o0 + q0.x, o1 + q0.y);
                *reinterpret_cast<float2*>(&C2[(size_t)r1 * 256 + cb]) =
                    make_float2(o2 + q1.x, o3 + q1.y);
            }
        }
    }
}

// ------------------------- tensor-core flash attention (cp.async double-buffered) ----------
#define LKP 36
#define LVP 40
__global__ __launch_bounds__(256)
void attn_tc_kernel(const float* __restrict__ QK, const float* __restrict__ V,
                    float* __restrict__ O) {
    __shared__ uint32_t Ks[2][64 * LKP];
    __shared__ uint32_t Vs[2][64 * LVP];

    const int q0   = blockIdx.x * 128;
    const int h    = blockIdx.y;
    const int b    = blockIdx.z;
    const int tid  = threadIdx.x;
    const int lane = tid & 31;
    const int w    = tid >> 5;
    const int g    = lane >> 2;
    const int t    = lane & 3;

    auto load_tile = [&](int bufi, int t0) {
        uint32_t kb = (uint32_t)__cvta_generic_to_shared(&Ks[bufi][0]);
        uint32_t vbs = (uint32_t)__cvta_generic_to_shared(&Vs[bufi][0]);
#pragma unroll
        for (int j = 0; j < 2; j++) {
            int c = tid + j * 256;
            int row = c >> 3, cg = (c & 7) * 4;
            cp16(kb + (row * LKP + cg) * 4,
                 &QK[(size_t)(b * NQ + t0 + row) * 512 + 256 + h * 32 + cg], 16);
        }
#pragma unroll
        for (int j = 0; j < 2; j++) {
            int c = tid + j * 256;
            int row = c >> 3, cg = (c & 7) * 4;
            cp16(vbs + (row * LVP + cg) * 4,
                 &V[(size_t)(b * NQ + t0 + row) * 256 + h * 32 + cg], 16);
        }
        cp_commit();
    };

    uint32_t af[4][4];
    {
        const int r0 = b * NQ + q0 + w * 16 + g;
        const int r1 = r0 + 8;
        const float scq = 0.17677669529663687f;
        const float* Q0 = &QK[(size_t)r0 * 512 + h * 32];
        const float* Q1 = &QK[(size_t)r1 * 512 + h * 32];
#pragma unroll
        for (int ks = 0; ks < 4; ks++) {
            af[ks][0] = f2tf(Q0[ks * 8 + t] * scq);
            af[ks][1] = f2tf(Q1[ks * 8 + t] * scq);
            af[ks][2] = f2tf(Q0[ks * 8 + t + 4] * scq);
            af[ks][3] = f2tf(Q1[ks * 8 + t + 4] * scq);
        }
    }

    float oc[4][4];
#pragma unroll
    for (int i = 0; i < 4; i++)
#pragma unroll
        for (int j = 0; j < 4; j++) oc[i][j] = 0.f;
    float m0r = -1e30f, m1r = -1e30f, l0 = 0.f, l1 = 0.f;
    const unsigned F = 0xffffffffu;

    load_tile(0, 0);
    int buf = 0;
    const int NTILES = NQ / 64;

    for (int it = 0; it < NTILES; it++) {
        if (it + 1 < NTILES) {
            load_tile(buf ^ 1, (it + 1) * 64);
            cp_wait<1>();
        } else {
            cp_wait<0>();
        }
        __syncthreads();

        // ---- S = Q @ K^T ----
        float sc[8][4];
#pragma unroll
        for (int nt = 0; nt < 8; nt++) {
            sc[nt][0] = sc[nt][1] = sc[nt][2] = sc[nt][3] = 0.f;
            uint32_t bf[4][2];
#pragma unroll
            for (int ks = 0; ks < 4; ks++) {
                const uint32_t* base = &Ks[buf][(nt * 8 + g) * LKP + ks * 8];
                bf[ks][0] = base[t];
                bf[ks][1] = base[t + 4];
            }
#pragma unroll
            for (int ks = 0; ks < 4; ks++) mma_tf32(sc[nt], af[ks], bf[ks]);
        }

        // ---- online softmax ----
        float mt0 = -1e30f, mt1 = -1e30f;
#pragma unroll
        for (int nt = 0; nt < 8; nt++) {
            mt0 = fmaxf(mt0, fmaxf(sc[nt][0], sc[nt][1]));
            mt1 = fmaxf(mt1, fmaxf(sc[nt][2], sc[nt][3]));
        }
        mt0 = fmaxf(mt0, __shfl_xor_sync(F, mt0, 1));
        mt0 = fmaxf(mt0, __shfl_xor_sync(F, mt0, 2));
        mt1 = fmaxf(mt1, __shfl_xor_sync(F, mt1, 1));
        mt1 = fmaxf(mt1, __shfl_xor_sync(F, mt1, 2));
        const float mn0 = fmaxf(m0r, mt0), mn1 = fmaxf(m1r, mt1);
        const float sc0 = __expf(m0r - mn0), sc1 = __expf(m1r - mn1);

        uint32_t pf[8][4];
        float s0 = 0.f, s1 = 0.f;
#pragma unroll
        for (int nt = 0; nt < 8; nt++) {
            float p0 = __expf(sc[nt][0] - mn0);
            float p1 = __expf(sc[nt][1] - mn0);
            float p2 = __expf(sc[nt][2] - mn1);
            float p3 = __expf(sc[nt][3] - mn1);
            s0 += p0 + p1; s1 += p2 + p3;
            pf[nt][0] = f2tf(p0); pf[nt][1] = f2tf(p1);
            pf[nt][2] = f2tf(p2); pf[nt][3] = f2tf(p3);
        }
        s0 += __shfl_xor_sync(F, s0, 1); s0 += __shfl_xor_sync(F, s0, 2);
        s1 += __shfl_xor_sync(F, s1, 1); s1 += __shfl_xor_sync(F, s1, 2);
        l0 = l0 * sc0 + s0;
        l1 = l1 * sc1 + s1;
        m0r = mn0; m1r = mn1;
#pragma unroll
        for (int nt = 0; nt < 4; nt++) {
            oc[nt][0] *= sc0; oc[nt][1] *= sc0;
            oc[nt][2] *= sc1; oc[nt][3] *= sc1;
        }

        // ---- O += P @ V ----
        const int src0 = (lane & ~3) | (t >> 1);
        const int src1 = src0 + 2;
        const bool odd = (t & 1);
#pragma unroll
        for (int kt = 0; kt < 8; kt++) {
            uint32_t a[4];
            uint32_t x0 = __shfl_sync(F, pf[kt][0], src0);
            uint32_t x1 = __shfl_sync(F, pf[kt][1], src0);
            a[0] = odd ? x1 : x0;
            uint32_t x2 = __shfl_sync(F, pf[kt][2], src0);
            uint32_t x3 = __shfl_sync(F, pf[kt][3], src0);
            a[1] = odd ? x3 : x2;
            x0 = __shfl_sync(F, pf[kt][0], src1);
            x1 = __shfl_sync(F, pf[kt][1], src1);
            a[2] = odd ? x1 : x0;
            x2 = __shfl_sync(F, pf[kt][2], src1);
            x3 = __shfl_sync(F, pf[kt][3], src1);
            a[3] = odd ? x3 : x2;
#pragma unroll
            for (int nt = 0; nt < 4; nt++) {
                uint32_t bfv[2];
                bfv[0] = Vs[buf][(kt * 8 + t) * LVP + nt * 8 + g];
                bfv[1] = Vs[buf][(kt * 8 + t + 4) * LVP + nt * 8 + g];
                mma_tf32(oc[nt], a, bfv);
            }
        }
        __syncthreads();
        buf ^= 1;
    }

    const float inv0 = 1.f / l0, inv1 = 1.f / l1;
    const int r0 = b * NQ + q0 + w * 16 + g;
#pragma unroll
    for (int nt = 0; nt < 4; nt++) {
        const int col = h * 32 + nt * 8 + t * 2;
        *reinterpret_cast<float2*>(&O[(size_t)r0 * 256 + col]) =
            make_float2(oc[nt][0] * inv0, oc[nt][1] * inv0);
        *reinterpret_cast<float2*>(&O[(size_t)(r0 + 8) * 256 + col]) =
            make_float2(oc[nt][2] * inv1, oc[nt][3] * inv1);
    }
}

// ------------------------- MSDA sampling -------------------------
__global__ void msda_kernel(const float* __restrict__ val, const float* __restrict__ offaw,
                            const float* __restrict__ ref, const int* __restrict__ lsi,
                            float* __restrict__ out) {
    const int warp = (blockIdx.x * blockDim.x + threadIdx.x) >> 5;
    const int lane = threadIdx.x & 31;
    if (warp >= BS * NQ * NH) return;
    const int h  = warp % NH;
    const int bq = warp / NH;
    const int b  = bq / NQ;
    const int base = lsi[0];

    const float rx = ref[bq * 2 + 0] * (float)W_BEV - 0.5f;
    const float ry = ref[bq * 2 + 1] * (float)H_BEV - 0.5f;

    const float* row = &offaw[(size_t)bq * 128];
    float a0 = row[64 + h * NP + 0];
    float a1 = row[64 + h * NP + 1];
    float a2 = row[64 + h * NP + 2];
    float a3 = row[64 + h * NP + 3];
    float mx = fmaxf(fmaxf(a0, a1), fmaxf(a2, a3));
    float e0 = __expf(a0 - mx), e1 = __expf(a1 - mx), e2 = __expf(a2 - mx), e3 = __expf(a3 - mx);
    float inv = 1.f / (e0 + e1 + e2 + e3);
    float ap[4] = {e0 * inv, e1 * inv, e2 * inv, e3 * inv};

    float accv = 0.f;
#pragma unroll
    for (int p = 0; p < NP; p++) {
        float ox = row[(h * NP + p) * 2 + 0];
        float oy = row[(h * NP + p) * 2 + 1];
        float x = rx + ox, y = ry + oy;
        float x0f = floorf(x), y0f = floorf(y);
        int x0 = (int)x0f, y0 = (int)y0f;
        float fx = x - x0f, fy = y - y0f;
        float wgt[4] = {(1.f - fx) * (1.f - fy), fx * (1.f - fy), (1.f - fx) * fy, fx * fy};
        int xs[4] = {x0, x0 + 1, x0, x0 + 1};
        int ys[4] = {y0, y0, y0 + 1, y0 + 1};
#pragma unroll
        for (int c = 0; c < 4; c++) {
            int xi = xs[c], yi = ys[c];
            if (xi >= 0 && xi < W_BEV && yi >= 0 && yi < H_BEV) {
                float vv = val[((size_t)(b * NV + base + yi * W_BEV + xi)) * D + h * DH + lane];
                accv += ap[p] * wgt[c] * vv;
            }
        }
    }
    out[(size_t)bq * D + h * DH + lane] = accv;
}

// ------------------------- refs tail -------------------------
__global__ void copy_refs_kernel(const float* __restrict__ ref, float* __restrict__ out) {
    int i = blockIdx.x * blockDim.x + threadIdx.x;
    const int n1 = BS * NQ * 2;
    if (i < LNUM * n1) out[i] = ref[i % n1];
}

// ------------------------- launch -------------------------
extern "C" void kernel_launch(void* const* d_in, const int* in_sizes, int n_in,
                              void* d_out, int out_size) {
    const float* query    = (const float*)d_in[0];
    const float* qpos     = (const float*)d_in[1];
    const float* ref      = (const float*)d_in[2];
    const float* src      = (const float*)d_in[3];
    const int*   lsi      = (const int*)d_in[5];
    const float* sa_in_w  = (const float*)d_in[6];
    const float* sa_in_b  = (const float*)d_in[7];
    const float* sa_out_w = (const float*)d_in[8];
    const float* sa_out_b = (const float*)d_in[9];
    const float* ca_off_w = (const float*)d_in[10];
    const float* ca_off_b = (const float*)d_in[11];
    const float* ca_aw_w  = (const float*)d_in[12];
    const float* ca_aw_b  = (const float*)d_in[13];
    const float* ca_val_w = (const float*)d_in[14];
    const float* ca_val_b = (const float*)d_in[15];
    const float* ca_out_w = (const float*)d_in[16];
    const float* ca_out_b = (const float*)d_in[17];
    const float* n1_w     = (const float*)d_in[18];
    const float* n1_b     = (const float*)d_in[19];
    const float* n2_w     = (const float*)d_in[20];
    const float* n2_b     = (const float*)d_in[21];
    const float* n3_w     = (const float*)d_in[22];
    const float* n3_b     = (const float*)d_in[23];
    const float* ff1_w    = (const float*)d_in[24];
    const float* ff1_b    = (const float*)d_in[25];
    const float* ff2_w    = (const float*)d_in[26];
    const float* ff2_b    = (const float*)d_in[27];

    float *xbuf, *qkb, *vb, *sab, *t1b, *t2b, *valb, *owb, *obb, *offawb, *cab, *ffnb;
    cudaGetSymbolAddress((void**)&xbuf, g_xbuf);
    cudaGetSymbolAddress((void**)&qkb,  g_qk);
    cudaGetSymbolAddress((void**)&vb,   g_v);
    cudaGetSymbolAddress((void**)&sab,  g_sa);
    cudaGetSymbolAddress((void**)&t1b,  g_t1);
    cudaGetSymbolAddress((void**)&t2b,  g_t2);
    cudaGetSymbolAddress((void**)&valb, g_val);
    cudaGetSymbolAddress((void**)&owb,  g_ow);
    cudaGetSymbolAddress((void**)&obb,  g_ob);
    cudaGetSymbolAddress((void**)&offawb, g_offaw);
    cudaGetSymbolAddress((void**)&cab,  g_ca);
    cudaGetSymbolAddress((void**)&ffnb, g_ffn);

    float* out_hs = (float*)d_out;
    const int NTOK = MROWS * D;
    const size_t VAL_STRIDE = (size_t)BS * NV * D;

    const bool use_s = g_aux.ok;
    cudaStream_t sB = use_s ? g_aux.sB : 0;
    cudaStream_t sC = use_s ? g_aux.sC : 0;

    // pack off/aw weights (main stream; consumers are on main stream)
    pack_offaw<<<(LNUM * 128 * D + 255) / 256, 256>>>(ca_off_w, ca_off_b, ca_aw_w, ca_aw_b,
                                                      owb, obb);

    // ---- fork: all 6 value projections on side stream sB ----
    if (use_s) {
        cudaEventRecord(g_aux.fork, 0);
        cudaStreamWaitEvent(sB, g_aux.fork, 0);
        cudaStreamWaitEvent(sC, g_aux.fork, 0);
    }
    for (int l = 0; l < LNUM; l++) {
        gemm_tc<128, 128, false><<<dim3(D / 128, (BS * NV + 127) / 128), 256, 0, sB>>>(
            src, ca_val_w + (size_t)l * D * D, ca_val_b + (size_t)l * D,
            valb + (size_t)l * VAL_STRIDE, BS * NV, D, D);
        if (use_s) cudaEventRecord(g_aux.val_ev[l], sB);
    }

    // xbuf = query + qpos
    add_kernel<<<(NTOK + 255) / 256, 256>>>(query, qpos, xbuf, NTOK);
    if (use_s) cudaEventRecord(g_aux.ev_x[0], 0);

    for (int l = 0; l < LNUM; l++) {
        const float* prev = (l == 0) ? query : out_hs + (size_t)(l - 1) * NTOK;
        float* cur = out_hs + (size_t)l * NTOK;

        // --- V projection on sC (parallel with QKV) ---
        if (use_s) {
            cudaStreamWaitEvent(sC, g_aux.ev_x[l], 0);
            gemm_tc<64, 128, false><<<dim3(D / 128, MROWS / 64), 256, 0, sC>>>(
                prev, sa_in_w + (size_t)l * 3 * D * D + (size_t)2 * D * D,
                sa_in_b + (size_t)l * 3 * D + 2 * D, vb, MROWS, D, D);
            cudaEventRecord(g_aux.ev_v[l], sC);
        } else {
            gemm_tc<64, 128, false><<<dim3(D / 128, MROWS / 64), 256>>>(
                prev, sa_in_w + (size_t)l * 3 * D * D + (size_t)2 * D * D,
                sa_in_b + (size_t)l * 3 * D + 2 * D, vb, MROWS, D, D);
        }

        // --- QKV (fused q+k) on main ---
        gemm_tc<64, 128, false><<<dim3(512 / 128, MROWS / 64), 256>>>(
            xbuf, sa_in_w + (size_t)l * 3 * D * D, sa_in_b + (size_t)l * 3 * D,
            qkb, MROWS, 512, D);
        if (use_s) cudaStreamWaitEvent(0, g_aux.ev_v[l], 0);
        attn_tc_kernel<<<dim3(NQ / 128, NH, BS), 256>>>(qkb, vb, sab);
        gemm_ln<<<dim3(1, MROWS / 32), 256>>>(
            sab, sa_out_w + (size_t)l * D * D, sa_out_b + (size_t)l * D, prev,
            n2_w + (size_t)l * D, n2_b + (size_t)l * D, t1b, qpos, xbuf, MROWS, D);

        // --- deformable cross attention ---
        gemm_tc<64, 128, false><<<dim3(1, MROWS / 64), 256>>>(
            xbuf, owb + (size_t)l * 128 * D, obb + (size_t)l * 128, offawb, MROWS, 128, D);
        if (use_s) cudaStreamWaitEvent(0, g_aux.val_ev[l], 0);
        msda_kernel<<<(BS * NQ * NH + 7) / 8, 256>>>(
            valb + (size_t)l * VAL_STRIDE, offawb, ref, lsi, cab);
        gemm_ln<<<dim3(1, MROWS / 32), 256>>>(
            cab, ca_out_w + (size_t)l * D * D, ca_out_b + (size_t)l * D, t1b,
            n1_w + (size_t)l * D, n1_b + (size_t)l * D, t2b, nullptr, nullptr, MROWS, D);

        // --- FFN ---
        gemm_tc<128, 128, true><<<dim3(DFF / 128, MROWS / 128), 256>>>(
            t2b, ff1_w + (size_t)l * DFF * D, ff1_b + (size_t)l * DFF, ffnb, MROWS, DFF, D);
        gemm_ln<<<dim3(1, MROWS / 32), 256>>>(
            ffnb, ff2_w + (size_t)l * D * DFF, ff2_b + (size_t)l * D, t2b,
            n3_w + (size_t)l * D, n3_b + (size_t)l * D, cur, qpos, xbuf, MROWS, DFF);
        if (use_s && l + 1 < LNUM) cudaEventRecord(g_aux.ev_x[l + 1], 0);
    }

    const int hs_total = LNUM * MROWS * D;
    if (out_size > hs_total) {
        copy_refs_kernel<<<(LNUM * BS * NQ * 2 + 255) / 256, 256>>>(ref, out_hs + hs_total);
    }
}